// round 5
// baseline (speedup 1.0000x reference)
#include <cuda_runtime.h>
#include <cuda_bf16.h>
#include <cstddef>

// ---------------- problem constants ----------------
#define EPSB 1e-5f
constexpr int Bk   = 16;
constexpr int Pk   = 2048;
constexpr int KN   = 5;
constexpr int NPTS = Bk * Pk;       // 32768
constexpr int NEDG = NPTS * KN;     // 163840
constexpr int NBLK = 256;           // stat partial blocks (edge tensors)
constexpr int HRB  = NPTS / 64;     // 512 row-blocks for fused l1 stats

using u64 = unsigned long long;

// ---------------- scratch (device globals; no runtime allocation) ----------
__device__ float g_Z1[(size_t)NEDG * 64];
__device__ float g_Z2[(size_t)NEDG * 64];
__device__ float g_Z4[(size_t)NEDG * 128];
__device__ float g_X12[(size_t)NPTS * 192];   // cols 0..63 = x1, 64..191 = x2
__device__ float g_sq[NPTS];
__device__ int   g_idx1[NEDG];
__device__ int   g_idx2[NEDG];
__device__ float g_bd2[(size_t)NPTS * 10];    // split-kNN partial dists
__device__ int   g_bi2[(size_t)NPTS * 10];    // split-kNN partial indices
__device__ float g_part[(size_t)HRB * 2 * 1024];
__device__ float g_s1[64],  g_h1[64];
__device__ float g_s2[64],  g_h2[64];
__device__ float g_s3[64],  g_h3[64];
__device__ float g_s4[128], g_h4[128];
__device__ float g_s5[1024],g_h5[1024];
__device__ float g_s6[512], g_h6[512];
__device__ float g_s7[256], g_h7[256];
__device__ float g_eb2[64], g_eb3[64], g_ebm2[256], g_ebm3[2];
__device__ int   g_P1raw[16 * 1024];
__device__ float g_Zm1[16 * 512];
__device__ float g_Zm2[16 * 256];

// ---------------- f32x2 packed-FMA helpers ----------------
__device__ __forceinline__ u64 pack2(float lo, float hi) {
    u64 r; asm("mov.b64 %0, {%1, %2};" : "=l"(r) : "f"(lo), "f"(hi)); return r;
}
__device__ __forceinline__ float2 unpack2(u64 v) {
    float2 r; asm("mov.b64 {%0, %1}, %2;" : "=f"(r.x), "=f"(r.y) : "l"(v)); return r;
}
__device__ __forceinline__ void fma2(u64& d, u64 a, u64 b) {
    asm("fma.rn.f32x2 %0, %1, %2, %0;" : "+l"(d) : "l"(a), "l"(b));
}

// ---------------- helpers ----------------
__device__ __forceinline__ void knn_insert(float d, int j, float bd[KN], int bi[KN]) {
#pragma unroll
    for (int k = 0; k < KN; k++) {
        if (d < bd[k]) {
            float td = bd[k]; int ti = bi[k];
            bd[k] = d; bi[k] = j;
            d = td; j = ti;
        }
    }
}

// ---------------- kNN on positions (D=3) ----------------
__global__ void knn3_k(const float* __restrict__ pos, int* __restrict__ idx) {
    __shared__ float sx[Pk], sy[Pk], sz[Pk], sn[Pk];
    int b  = blockIdx.x >> 3;
    int p0 = (blockIdx.x & 7) << 8;
    const float* base = pos + (size_t)b * Pk * 3;
    for (int j = threadIdx.x; j < Pk; j += 256) {
        float x = base[3 * j], y = base[3 * j + 1], z = base[3 * j + 2];
        sx[j] = x; sy[j] = y; sz[j] = z;
        sn[j] = x * x + y * y + z * z;
    }
    __syncthreads();
    int p = p0 + threadIdx.x;
    float x = sx[p], y = sy[p], z = sz[p], sq = sn[p];
    float bd[KN]; int bi[KN];
#pragma unroll
    for (int k = 0; k < KN; k++) { bd[k] = 1e30f; bi[k] = 0; }
    for (int j = 0; j < Pk; j++) {
        float dot = x * sx[j] + y * sy[j] + z * sz[j];
        float d = sq + sn[j] - 2.f * dot;
        if (d < bd[KN - 1]) knn_insert(d, j, bd, bi);
    }
    int o = (b * Pk + p) * KN;
#pragma unroll
    for (int k = 0; k < KN; k++) idx[o + k] = bi[k];
}

// ---------------- EdgeConv1 layer0: edges(6) -> 64, ReLU ----------------
__global__ void ec1_l0_k(const float* __restrict__ pos, const int* __restrict__ idx,
                         const float* __restrict__ w, const float* __restrict__ bias,
                         float* __restrict__ Z) {
    __shared__ float sw[6 * 64];
    __shared__ float sb[64];
    if (threadIdx.x < 64) sb[threadIdx.x] = bias[threadIdx.x];
    for (int i = threadIdx.x; i < 384; i += 256) sw[i] = w[i];
    __syncthreads();
    int g = blockIdx.x * 256 + threadIdx.x;
    int e = g >> 2, q = g & 3;
    int pt = e / KN;
    int b  = pt >> 11;
    int j  = idx[e];
    const float* pi = pos + (size_t)pt * 3;
    const float* pj = pos + ((size_t)(b << 11) + j) * 3;
    float e0 = pi[0], e1 = pi[1], e2 = pi[2];
    float e3 = pj[0] - e0, e4 = pj[1] - e1, e5 = pj[2] - e2;
    int c0 = q * 16;
    float out[16];
#pragma unroll
    for (int c = 0; c < 16; c++) {
        int cc = c0 + c;
        float a = sb[cc];
        a = fmaf(e0, sw[0 * 64 + cc], a);
        a = fmaf(e1, sw[1 * 64 + cc], a);
        a = fmaf(e2, sw[2 * 64 + cc], a);
        a = fmaf(e3, sw[3 * 64 + cc], a);
        a = fmaf(e4, sw[4 * 64 + cc], a);
        a = fmaf(e5, sw[5 * 64 + cc], a);
        out[c] = fmaxf(a, 0.f);
    }
    float4* dst = reinterpret_cast<float4*>(Z + (size_t)e * 64 + c0);
#pragma unroll
    for (int v = 0; v < 4; v++)
        dst[v] = make_float4(out[v * 4], out[v * 4 + 1], out[v * 4 + 2], out[v * 4 + 3]);
}

// ---------------- per-channel stats partials (deterministic) ----------------
template <int C>
__global__ void stats_k(const float* __restrict__ Z, int rpb) {
    __shared__ float ssum[256], ssq[256];
    int row0 = blockIdx.x * rpb;
    if (C >= 256) {
#pragma unroll
        for (int m = 0; m < C / 256; m++) {
            int c = threadIdx.x + m * 256;
            float s = 0.f, q = 0.f;
            for (int r = 0; r < rpb; r++) {
                float v = Z[(size_t)(row0 + r) * C + c];
                s += v; q += v * v;
            }
            g_part[((size_t)blockIdx.x * 2 + 0) * C + c] = s;
            g_part[((size_t)blockIdx.x * 2 + 1) * C + c] = q;
        }
    } else {
        const int ns = 256 / C;
        int c  = threadIdx.x % C;
        int sl = threadIdx.x / C;
        int rs = rpb / ns;
        float s = 0.f, q = 0.f;
        for (int r = sl * rs; r < (sl + 1) * rs; r++) {
            float v = Z[(size_t)(row0 + r) * C + c];
            s += v; q += v * v;
        }
        ssum[threadIdx.x] = s; ssq[threadIdx.x] = q;
        __syncthreads();
        if (sl == 0) {
            for (int m = 1; m < ns; m++) { s += ssum[m * C + c]; q += ssq[m * C + c]; }
            g_part[((size_t)blockIdx.x * 2 + 0) * C + c] = s;
            g_part[((size_t)blockIdx.x * 2 + 1) * C + c] = q;
        }
    }
}

// one warp per channel, parallel over partial blocks
__global__ void finalize_k(int C, float n, int nblk, const float* __restrict__ g,
                           const float* __restrict__ be,
                           float* __restrict__ scale, float* __restrict__ shift) {
    int warp = (blockIdx.x * blockDim.x + threadIdx.x) >> 5;
    int lane = threadIdx.x & 31;
    if (warp >= C) return;
    float s = 0.f, q = 0.f;
    for (int b = lane; b < nblk; b += 32) {
        s += g_part[((size_t)b * 2 + 0) * C + warp];
        q += g_part[((size_t)b * 2 + 1) * C + warp];
    }
#pragma unroll
    for (int o = 16; o; o >>= 1) {
        s += __shfl_xor_sync(0xffffffffu, s, o);
        q += __shfl_xor_sync(0xffffffffu, q, o);
    }
    if (lane == 0) {
        float mean = s / n;
        float var  = q / n - mean * mean;
        float sc = g[warp] * rsqrtf(var + EPSB);
        scale[warp] = sc;
        shift[warp] = be[warp] - mean * sc;
    }
}

__global__ void foldbias_k(int Cin, int Cout, const float* __restrict__ w,
                           const float* __restrict__ bias, const float* __restrict__ shift,
                           float* __restrict__ eb) {
    int c = blockIdx.x * blockDim.x + threadIdx.x;
    if (c >= Cout) return;
    float a = bias[c];
    for (int r = 0; r < Cin; r++) a = fmaf(shift[r], w[(size_t)r * Cout + c], a);
    eb[c] = a;
}

// ---------------- 64->64 GEMM (BN-folded input), ReLU, f32x2 ----------------
// warp tile: 16 rows x 32 cols; lane tile 4x4 (rh = lane>>3, ch = lane&7)
__global__ void __launch_bounds__(256) ec_mid_k(const float* __restrict__ Zin,
                                                const float* __restrict__ w,
                                                const float* __restrict__ scaleIn,
                                                const float* __restrict__ eb,
                                                float* __restrict__ Zout) {
    __shared__ __align__(16) float At[64 * 68];
    __shared__ __align__(16) float Bs[64 * 68];
    int row0 = blockIdx.x * 64;
    for (int i = threadIdx.x; i < 64 * 64; i += 256) {
        int r = i >> 6, k = i & 63;
        At[k * 68 + r] = Zin[(size_t)(row0 + r) * 64 + k];
    }
    for (int i = threadIdx.x; i < 64 * 64; i += 256) {
        int k = i >> 6, c = i & 63;
        Bs[k * 68 + c] = scaleIn[k] * w[i];
    }
    __syncthreads();
    int wrp = threadIdx.x >> 5, lane = threadIdx.x & 31;
    int r0 = (wrp >> 1) * 16 + (lane >> 3) * 4;
    int c0 = (wrp & 1) * 32 + (lane & 7) * 4;
    u64 acc2[4][2] = {};
#pragma unroll 4
    for (int k = 0; k < 64; k++) {
        float4 a = *reinterpret_cast<const float4*>(&At[k * 68 + r0]);
        ulonglong2 bv = *reinterpret_cast<const ulonglong2*>(&Bs[k * 68 + c0]);
        float aa[4] = {a.x, a.y, a.z, a.w};
#pragma unroll
        for (int ii = 0; ii < 4; ii++) {
            u64 ad = pack2(aa[ii], aa[ii]);
            fma2(acc2[ii][0], ad, bv.x);
            fma2(acc2[ii][1], ad, bv.y);
        }
    }
    float e0 = eb[c0], e1 = eb[c0 + 1], e2 = eb[c0 + 2], e3 = eb[c0 + 3];
#pragma unroll
    for (int ii = 0; ii < 4; ii++) {
        float2 p0 = unpack2(acc2[ii][0]);
        float2 p1 = unpack2(acc2[ii][1]);
        float4 o;
        o.x = fmaxf(p0.x + e0, 0.f);
        o.y = fmaxf(p0.y + e1, 0.f);
        o.z = fmaxf(p1.x + e2, 0.f);
        o.w = fmaxf(p1.y + e3, 0.f);
        *reinterpret_cast<float4*>(&Zout[(size_t)(row0 + r0 + ii) * 64 + c0]) = o;
    }
}

// -------- k-max over edges + BN affine (+ optional fused sqnorm) --------
__global__ void maxE_k(const float* __restrict__ Z, int C,
                       const float* __restrict__ scale, const float* __restrict__ shift,
                       float* __restrict__ X, int colOff, int doSq) {
    int g = blockIdx.x * 256 + threadIdx.x;
    int per = C >> 2;
    int pt = g / per;
    int c4 = (g % per) * 4;
    float4 m = make_float4(-1e30f, -1e30f, -1e30f, -1e30f);
#pragma unroll
    for (int k = 0; k < KN; k++) {
        float4 v = *reinterpret_cast<const float4*>(&Z[(size_t)(pt * KN + k) * C + c4]);
        m.x = fmaxf(m.x, v.x); m.y = fmaxf(m.y, v.y);
        m.z = fmaxf(m.z, v.z); m.w = fmaxf(m.w, v.w);
    }
    float4 o;
    o.x = fmaf(scale[c4 + 0], m.x, shift[c4 + 0]);
    o.y = fmaf(scale[c4 + 1], m.y, shift[c4 + 1]);
    o.z = fmaf(scale[c4 + 2], m.z, shift[c4 + 2]);
    o.w = fmaf(scale[c4 + 3], m.w, shift[c4 + 3]);
    *reinterpret_cast<float4*>(&X[(size_t)pt * 192 + colOff + c4]) = o;
    if (doSq) {   // C==64 path: 16 consecutive lanes hold one point
        float s = o.x * o.x + o.y * o.y + o.z * o.z + o.w * o.w;
#pragma unroll
        for (int off = 8; off; off >>= 1)
            s += __shfl_down_sync(0xffffffffu, s, off, 16);
        if ((threadIdx.x & 15) == 0) g_sq[pt] = s;
    }
}

// ------- kNN on 64-dim x1, candidate-split (half per block), f32x2 ---------
__global__ void __launch_bounds__(256) knn64_k(float* __restrict__ bd2,
                                               int* __restrict__ bi2) {
    __shared__ __align__(16) float4 sq4[128 * 16];
    __shared__ float  ssn[128];
    int half = blockIdx.x & 1;
    int grp  = blockIdx.x >> 1;
    int b = grp >> 3;
    int p = ((grp & 7) << 8) + threadIdx.x;
    int pt = (b << 11) + p;
    ulonglong2 xpv[16];
#pragma unroll
    for (int i = 0; i < 16; i++)
        xpv[i] = *reinterpret_cast<const ulonglong2*>(&g_X12[(size_t)pt * 192 + i * 4]);
    float sqp = g_sq[pt];
    float bd[KN]; int bi[KN];
#pragma unroll
    for (int k = 0; k < KN; k++) { bd[k] = 1e30f; bi[k] = 0; }
    int qbase = half << 10;
    for (int q0 = qbase; q0 < qbase + 1024; q0 += 128) {
        __syncthreads();
        for (int t = threadIdx.x; t < 128 * 16; t += 256) {
            int qr = t >> 4, d4 = t & 15;
            sq4[qr * 16 + d4] = *reinterpret_cast<const float4*>(
                &g_X12[(size_t)((b << 11) + q0 + qr) * 192 + d4 * 4]);
        }
        if (threadIdx.x < 128) ssn[threadIdx.x] = g_sq[(b << 11) + q0 + threadIdx.x];
        __syncthreads();
        for (int qr = 0; qr < 128; qr++) {
            const ulonglong2* qv = reinterpret_cast<const ulonglong2*>(&sq4[qr * 16]);
            u64 dc[4] = {};
#pragma unroll
            for (int i = 0; i < 16; i += 2) {
                ulonglong2 qa = qv[i], qb = qv[i + 1];
                fma2(dc[0], xpv[i].x, qa.x);
                fma2(dc[1], xpv[i].y, qa.y);
                fma2(dc[2], xpv[i + 1].x, qb.x);
                fma2(dc[3], xpv[i + 1].y, qb.y);
            }
            float2 f0 = unpack2(dc[0]), f1 = unpack2(dc[1]);
            float2 f2 = unpack2(dc[2]), f3 = unpack2(dc[3]);
            float dot = ((f0.x + f0.y) + (f1.x + f1.y)) + ((f2.x + f2.y) + (f3.x + f3.y));
            float d = sqp + ssn[qr] - 2.f * dot;
            if (d < bd[KN - 1]) knn_insert(d, q0 + qr, bd, bi);
        }
    }
    size_t o = (size_t)pt * 10 + half * 5;
#pragma unroll
    for (int k = 0; k < KN; k++) { bd2[o + k] = bd[k]; bi2[o + k] = bi[k]; }
}

// merge two sorted 5-lists per point (list0 has lower indices -> wins ties)
__global__ void knnmerge_k(const float* __restrict__ bd2, const int* __restrict__ bi2,
                           int* __restrict__ idx) {
    int pt = blockIdx.x * 256 + threadIdx.x;
    const float* d0 = bd2 + (size_t)pt * 10;
    const float* d1 = d0 + 5;
    const int*   i0 = bi2 + (size_t)pt * 10;
    const int*   i1 = i0 + 5;
    int a = 0, c = 0;
#pragma unroll
    for (int k = 0; k < KN; k++) {
        bool take0 = (c >= KN) || (a < KN && d0[a] <= d1[c]);
        idx[pt * KN + k] = take0 ? i0[a] : i1[c];
        if (take0) a++; else c++;
    }
}

// ---------------- EdgeConv2: gather(128) + GEMM 128->128, ReLU, f32x2 --------
// warp tile: 16 rows x 64 cols; lane tile 4x8
__global__ void __launch_bounds__(256) ec2_k(const float* __restrict__ X,
                                             const int* __restrict__ idx,
                                             const float* __restrict__ w,
                                             const float* __restrict__ bias,
                                             float* __restrict__ Z) {
    __shared__ __align__(16) float At[128 * 68];
    __shared__ __align__(16) float Bs[16 * 132];
    int e0 = blockIdx.x * 64;
    for (int i = threadIdx.x; i < 64 * 128; i += 256) {
        int r = i >> 7, col = i & 127;
        int e = e0 + r;
        int pt = e / KN;
        int bb = pt >> 11;
        int j  = idx[e];
        const float* xi = X + (size_t)pt * 192;
        const float* xj = X + ((size_t)(bb << 11) + j) * 192;
        float v = (col < 64) ? xi[col] : (xj[col - 64] - xi[col - 64]);
        At[col * 68 + r] = v;
    }
    int wrp = threadIdx.x >> 5, lane = threadIdx.x & 31;
    int r0 = (wrp >> 1) * 16 + (lane >> 3) * 4;
    int c0 = (wrp & 1) * 64 + (lane & 7) * 8;
    u64 acc2[4][4] = {};
    for (int kc = 0; kc < 8; kc++) {
        __syncthreads();
        for (int i = threadIdx.x; i < 16 * 128; i += 256) {
            int kk = i >> 7, c = i & 127;
            Bs[kk * 132 + c] = w[(size_t)(kc * 16 + kk) * 128 + c];
        }
        __syncthreads();
#pragma unroll
        for (int kk = 0; kk < 16; kk++) {
            float4 a = *reinterpret_cast<const float4*>(&At[(kc * 16 + kk) * 68 + r0]);
            ulonglong2 b01 = *reinterpret_cast<const ulonglong2*>(&Bs[kk * 132 + c0]);
            ulonglong2 b23 = *reinterpret_cast<const ulonglong2*>(&Bs[kk * 132 + c0 + 4]);
            float aa[4] = {a.x, a.y, a.z, a.w};
#pragma unroll
            for (int ii = 0; ii < 4; ii++) {
                u64 ad = pack2(aa[ii], aa[ii]);
                fma2(acc2[ii][0], ad, b01.x);
                fma2(acc2[ii][1], ad, b01.y);
                fma2(acc2[ii][2], ad, b23.x);
                fma2(acc2[ii][3], ad, b23.y);
            }
        }
    }
    float bv[8];
#pragma unroll
    for (int jj = 0; jj < 8; jj++) bv[jj] = bias[c0 + jj];
#pragma unroll
    for (int ii = 0; ii < 4; ii++) {
        float2 p0 = unpack2(acc2[ii][0]);
        float2 p1 = unpack2(acc2[ii][1]);
        float2 p2 = unpack2(acc2[ii][2]);
        float2 p3 = unpack2(acc2[ii][3]);
        float4 o0, o1;
        o0.x = fmaxf(p0.x + bv[0], 0.f);
        o0.y = fmaxf(p0.y + bv[1], 0.f);
        o0.z = fmaxf(p1.x + bv[2], 0.f);
        o0.w = fmaxf(p1.y + bv[3], 0.f);
        o1.x = fmaxf(p2.x + bv[4], 0.f);
        o1.y = fmaxf(p2.y + bv[5], 0.f);
        o1.z = fmaxf(p3.x + bv[6], 0.f);
        o1.w = fmaxf(p3.y + bv[7], 0.f);
        size_t off = (size_t)(e0 + r0 + ii) * 128 + c0;
        *reinterpret_cast<float4*>(&Z[off])     = o0;
        *reinterpret_cast<float4*>(&Z[off + 4]) = o1;
    }
}

// ---------------- init pool accumulator ----------------
__global__ void initP1_k() {
    int g = blockIdx.x * 256 + threadIdx.x;
    if (g < 16 * 1024) g_P1raw[g] = 0;
}

// ------- fused l1: GEMM 192->1024 + ReLU + stats partials + max pool --------
__global__ void __launch_bounds__(256) l1_k(const float* __restrict__ X,
                                            const float* __restrict__ w,
                                            const float* __restrict__ bias) {
    __shared__ __align__(16) float At[32 * 68];
    __shared__ __align__(16) float Bs[32 * 132];
    __shared__ float red[16 * 128];
    int rb   = blockIdx.x >> 3;
    int row0 = rb * 64;
    int col0 = (blockIdx.x & 7) * 128;
    int bidx = row0 >> 11;
    int wrp = threadIdx.x >> 5, lane = threadIdx.x & 31;
    int r0 = (wrp >> 1) * 16 + (lane >> 3) * 4;
    int c0 = (wrp & 1) * 64 + (lane & 7) * 8;
    u64 acc2[4][4] = {};
    for (int kc = 0; kc < 6; kc++) {
        __syncthreads();
        for (int i = threadIdx.x; i < 64 * 32; i += 256) {
            int r = i >> 5, k = i & 31;
            At[k * 68 + r] = X[(size_t)(row0 + r) * 192 + kc * 32 + k];
        }
        for (int i = threadIdx.x; i < 32 * 128; i += 256) {
            int kk = i >> 7, c = i & 127;
            Bs[kk * 132 + c] = w[(size_t)(kc * 32 + kk) * 1024 + col0 + c];
        }
        __syncthreads();
#pragma unroll
        for (int kk = 0; kk < 32; kk++) {
            float4 a = *reinterpret_cast<const float4*>(&At[kk * 68 + r0]);
            ulonglong2 b01 = *reinterpret_cast<const ulonglong2*>(&Bs[kk * 132 + c0]);
            ulonglong2 b23 = *reinterpret_cast<const ulonglong2*>(&Bs[kk * 132 + c0 + 4]);
            float aa[4] = {a.x, a.y, a.z, a.w};
#pragma unroll
            for (int ii = 0; ii < 4; ii++) {
                u64 ad = pack2(aa[ii], aa[ii]);
                fma2(acc2[ii][0], ad, b01.x);
                fma2(acc2[ii][1], ad, b01.y);
                fma2(acc2[ii][2], ad, b23.x);
                fma2(acc2[ii][3], ad, b23.y);
            }
        }
    }
    float out[4][8];
    float bv[8];
#pragma unroll
    for (int jj = 0; jj < 8; jj++) bv[jj] = bias[col0 + c0 + jj];
#pragma unroll
    for (int ii = 0; ii < 4; ii++) {
        float2 p0 = unpack2(acc2[ii][0]);
        float2 p1 = unpack2(acc2[ii][1]);
        float2 p2 = unpack2(acc2[ii][2]);
        float2 p3 = unpack2(acc2[ii][3]);
        out[ii][0] = fmaxf(p0.x + bv[0], 0.f);
        out[ii][1] = fmaxf(p0.y + bv[1], 0.f);
        out[ii][2] = fmaxf(p1.x + bv[2], 0.f);
        out[ii][3] = fmaxf(p1.y + bv[3], 0.f);
        out[ii][4] = fmaxf(p2.x + bv[4], 0.f);
        out[ii][5] = fmaxf(p2.y + bv[5], 0.f);
        out[ii][6] = fmaxf(p3.x + bv[6], 0.f);
        out[ii][7] = fmaxf(p3.y + bv[7], 0.f);
    }
    int rg = (wrp >> 1) * 4 + (lane >> 3);   // row group 0..15
    // pass 1: sums
    __syncthreads();
#pragma unroll
    for (int jj = 0; jj < 8; jj++) {
        float s = out[0][jj] + out[1][jj] + out[2][jj] + out[3][jj];
        red[rg * 128 + c0 + jj] = s;
    }
    __syncthreads();
    if (threadIdx.x < 128) {
        float s = 0.f;
#pragma unroll
        for (int m = 0; m < 16; m++) s += red[m * 128 + threadIdx.x];
        g_part[((size_t)rb * 2 + 0) * 1024 + col0 + threadIdx.x] = s;
    }
    // pass 2: sumsq
    __syncthreads();
#pragma unroll
    for (int jj = 0; jj < 8; jj++) {
        float s = out[0][jj] * out[0][jj] + out[1][jj] * out[1][jj]
                + out[2][jj] * out[2][jj] + out[3][jj] * out[3][jj];
        red[rg * 128 + c0 + jj] = s;
    }
    __syncthreads();
    if (threadIdx.x < 128) {
        float s = 0.f;
#pragma unroll
        for (int m = 0; m < 16; m++) s += red[m * 128 + threadIdx.x];
        g_part[((size_t)rb * 2 + 1) * 1024 + col0 + threadIdx.x] = s;
    }
    // pass 3: max -> atomicMax (values >= 0, int-bit compare == float compare)
    __syncthreads();
#pragma unroll
    for (int jj = 0; jj < 8; jj++) {
        float m = fmaxf(fmaxf(out[0][jj], out[1][jj]), fmaxf(out[2][jj], out[3][jj]));
        red[rg * 128 + c0 + jj] = m;
    }
    __syncthreads();
    if (threadIdx.x < 128) {
        float m = red[threadIdx.x];
#pragma unroll
        for (int mm = 1; mm < 16; mm++) m = fmaxf(m, red[mm * 128 + threadIdx.x]);
        atomicMax(&g_P1raw[bidx * 1024 + col0 + threadIdx.x], __float_as_int(m));
    }
}

// ---------------- head (pool affine fused into head1) ----------------
__global__ void head1_k(const float* __restrict__ w, const float* __restrict__ bias) {
    __shared__ float sp[1024];
    int g = blockIdx.x * 256 + threadIdx.x;  // 16*512
    int b = g >> 9, c = g & 511;
    for (int i = threadIdx.x; i < 1024; i += 256)
        sp[i] = fmaf(g_s5[i], __int_as_float(g_P1raw[(b << 10) + i]), g_h5[i]);
    __syncthreads();
    float a = bias[c];
#pragma unroll 8
    for (int r = 0; r < 1024; r++) a = fmaf(sp[r], w[(size_t)r * 512 + c], a);
    g_Zm1[g] = fmaxf(a, 0.f);
}

__global__ void stats16_k(const float* __restrict__ Z, int C,
                          const float* __restrict__ g, const float* __restrict__ be,
                          float* __restrict__ scale, float* __restrict__ shift) {
    int c = blockIdx.x * blockDim.x + threadIdx.x;
    if (c >= C) return;
    float s = 0.f, q = 0.f;
    for (int b = 0; b < 16; b++) { float v = Z[b * C + c]; s += v; q += v * v; }
    float mean = s * (1.f / 16.f);
    float var  = q * (1.f / 16.f) - mean * mean;
    float sc = g[c] * rsqrtf(var + EPSB);
    scale[c] = sc;
    shift[c] = be[c] - mean * sc;
}

__global__ void head2_k(const float* __restrict__ w) {
    int g = blockIdx.x * 256 + threadIdx.x;  // 16*256
    int b = g >> 8, c = g & 255;
    float a = g_ebm2[c];
    const float* z = g_Zm1 + b * 512;
#pragma unroll 8
    for (int r = 0; r < 512; r++) a = fmaf(z[r] * g_s6[r], w[(size_t)r * 256 + c], a);
    g_Zm2[g] = fmaxf(a, 0.f);
}

__global__ void head3_k(const float* __restrict__ w, float* __restrict__ out) {
    int t = threadIdx.x;
    if (t >= 32) return;
    int b = t >> 1, n = t & 1;
    float a = g_ebm3[n];
    const float* z = g_Zm2 + b * 256;
#pragma unroll 8
    for (int r = 0; r < 256; r++) a = fmaf(z[r] * g_s7[r], w[r * 2 + n], a);
    out[b * 2 + n] = a;
}

// ---------------- launch ----------------
extern "C" void kernel_launch(void* const* d_in, const int* in_sizes, int n_in,
                              void* d_out, int out_size) {
    const float* pos  = (const float*)d_in[0];
    const float* c1w0 = (const float*)d_in[1];
    const float* c1b0 = (const float*)d_in[2];
    const float* c1g0 = (const float*)d_in[3];
    const float* c1e0 = (const float*)d_in[4];
    const float* c1w1 = (const float*)d_in[5];
    const float* c1b1 = (const float*)d_in[6];
    const float* c1g1 = (const float*)d_in[7];
    const float* c1e1 = (const float*)d_in[8];
    const float* c1w2 = (const float*)d_in[9];
    const float* c1b2 = (const float*)d_in[10];
    const float* c1g2 = (const float*)d_in[11];
    const float* c1e2 = (const float*)d_in[12];
    const float* c2w  = (const float*)d_in[13];
    const float* c2b  = (const float*)d_in[14];
    const float* c2g  = (const float*)d_in[15];
    const float* c2e  = (const float*)d_in[16];
    const float* l1w  = (const float*)d_in[17];
    const float* l1b  = (const float*)d_in[18];
    const float* l1g  = (const float*)d_in[19];
    const float* l1e  = (const float*)d_in[20];
    const float* m1w  = (const float*)d_in[21];
    const float* m1b  = (const float*)d_in[22];
    const float* m1g  = (const float*)d_in[23];
    const float* m1e  = (const float*)d_in[24];
    const float* m2w  = (const float*)d_in[25];
    const float* m2b  = (const float*)d_in[26];
    const float* m2g  = (const float*)d_in[27];
    const float* m2e  = (const float*)d_in[28];
    const float* m3w  = (const float*)d_in[29];
    const float* m3b  = (const float*)d_in[30];

    void *pZ1, *pZ2, *pZ4, *pX, *pI1, *pI2, *pBD, *pBI;
    void *ps1, *ph1, *ps2, *ph2, *ps3, *ph3, *ps4, *ph4, *ps5, *ph5, *ps6, *ph6, *ps7, *ph7;
    void *peb2, *peb3, *pebm2, *pebm3, *pZm1, *pZm2;
    cudaGetSymbolAddress(&pZ1, g_Z1);
    cudaGetSymbolAddress(&pZ2, g_Z2);
    cudaGetSymbolAddress(&pZ4, g_Z4);
    cudaGetSymbolAddress(&pX,  g_X12);
    cudaGetSymbolAddress(&pI1, g_idx1);
    cudaGetSymbolAddress(&pI2, g_idx2);
    cudaGetSymbolAddress(&pBD, g_bd2);
    cudaGetSymbolAddress(&pBI, g_bi2);
    cudaGetSymbolAddress(&ps1, g_s1); cudaGetSymbolAddress(&ph1, g_h1);
    cudaGetSymbolAddress(&ps2, g_s2); cudaGetSymbolAddress(&ph2, g_h2);
    cudaGetSymbolAddress(&ps3, g_s3); cudaGetSymbolAddress(&ph3, g_h3);
    cudaGetSymbolAddress(&ps4, g_s4); cudaGetSymbolAddress(&ph4, g_h4);
    cudaGetSymbolAddress(&ps5, g_s5); cudaGetSymbolAddress(&ph5, g_h5);
    cudaGetSymbolAddress(&ps6, g_s6); cudaGetSymbolAddress(&ph6, g_h6);
    cudaGetSymbolAddress(&ps7, g_s7); cudaGetSymbolAddress(&ph7, g_h7);
    cudaGetSymbolAddress(&peb2, g_eb2); cudaGetSymbolAddress(&peb3, g_eb3);
    cudaGetSymbolAddress(&pebm2, g_ebm2); cudaGetSymbolAddress(&pebm3, g_ebm3);
    cudaGetSymbolAddress(&pZm1, g_Zm1); cudaGetSymbolAddress(&pZm2, g_Zm2);

    float* Z1 = (float*)pZ1;  float* Z2 = (float*)pZ2;  float* Z4 = (float*)pZ4;
    float* X  = (float*)pX;
    int* I1 = (int*)pI1;      int* I2 = (int*)pI2;

    // --- EdgeConv1 ---
    knn3_k<<<128, 256>>>(pos, I1);
    ec1_l0_k<<<NEDG * 4 / 256, 256>>>(pos, I1, c1w0, c1b0, Z1);
    stats_k<64><<<NBLK, 256>>>(Z1, NEDG / NBLK);
    finalize_k<<<8, 256>>>(64, (float)NEDG, NBLK, c1g0, c1e0, (float*)ps1, (float*)ph1);
    foldbias_k<<<1, 64>>>(64, 64, c1w1, c1b1, (float*)ph1, (float*)peb2);
    ec_mid_k<<<NEDG / 64, 256>>>(Z1, c1w1, (float*)ps1, (float*)peb2, Z2);
    stats_k<64><<<NBLK, 256>>>(Z2, NEDG / NBLK);
    finalize_k<<<8, 256>>>(64, (float)NEDG, NBLK, c1g1, c1e1, (float*)ps2, (float*)ph2);
    foldbias_k<<<1, 64>>>(64, 64, c1w2, c1b2, (float*)ph2, (float*)peb3);
    ec_mid_k<<<NEDG / 64, 256>>>(Z2, c1w2, (float*)ps2, (float*)peb3, Z1);
    stats_k<64><<<NBLK, 256>>>(Z1, NEDG / NBLK);
    finalize_k<<<8, 256>>>(64, (float)NEDG, NBLK, c1g2, c1e2, (float*)ps3, (float*)ph3);
    maxE_k<<<NPTS * 16 / 256, 256>>>(Z1, 64, (float*)ps3, (float*)ph3, X, 0, 1);

    // --- EdgeConv2 ---
    knn64_k<<<256, 256>>>((float*)pBD, (int*)pBI);
    knnmerge_k<<<NPTS / 256, 256>>>((float*)pBD, (int*)pBI, I2);
    ec2_k<<<NEDG / 64, 256>>>(X, I2, c2w, c2b, Z4);
    stats_k<128><<<NBLK, 256>>>(Z4, NEDG / NBLK);
    finalize_k<<<16, 256>>>(128, (float)NEDG, NBLK, c2g, c2e, (float*)ps4, (float*)ph4);
    maxE_k<<<NPTS * 32 / 256, 256>>>(Z4, 128, (float*)ps4, (float*)ph4, X, 64, 0);

    // --- fused l1 (GEMM + stats partials + max pool) ---
    initP1_k<<<64, 256>>>();
    l1_k<<<HRB * 8, 256>>>(X, l1w, l1b);
    finalize_k<<<128, 256>>>(1024, (float)NPTS, HRB, l1g, l1e, (float*)ps5, (float*)ph5);

    // --- head ---
    head1_k<<<32, 256>>>(m1w, m1b);
    stats16_k<<<2, 256>>>((float*)pZm1, 512, m1g, m1e, (float*)ps6, (float*)ph6);
    foldbias_k<<<1, 256>>>(512, 256, m2w, m2b, (float*)ph6, (float*)pebm2);
    head2_k<<<16, 256>>>(m2w);
    stats16_k<<<1, 256>>>((float*)pZm2, 256, m2g, m2e, (float*)ps7, (float*)ph7);
    foldbias_k<<<1, 32>>>(256, 2, m3w, m3b, (float*)ph7, (float*)pebm3);
    head3_k<<<1, 32>>>(m3w, (float*)d_out);
}

// round 10
// speedup vs baseline: 1.1947x; 1.1947x over previous
#include <cuda_runtime.h>
#include <cuda_bf16.h>
#include <mma.h>
#include <cstddef>

using namespace nvcuda;

#define EPSB 1e-5f
constexpr int Pk = 2048;
constexpr int KN = 5;
constexpr int NPTS = 16 * Pk;
constexpr int NEDG = NPTS * KN;
constexpr int NBLK = 256;
using u64 = unsigned long long;

__device__ float g_Z1[(size_t)NEDG * 64];
__device__ float g_Z2[(size_t)NEDG * 64];
__device__ float g_Z4[(size_t)NEDG * 128];
__device__ float g_X12[(size_t)NPTS * 192];
__device__ float g_sq[NPTS];
__device__ int   g_idx1[NEDG];
__device__ int   g_idx2[NEDG];
__device__ float g_part[(size_t)512 * 2 * 1024];
__device__ float g_s1[64], g_h1[64], g_s2[64], g_h2[64], g_s3[64], g_h3[64];
__device__ float g_s4[128], g_h4[128], g_s5[1024], g_h5[1024];
__device__ float g_s6[512], g_h6[512], g_s7[256], g_h7[256];
__device__ float g_eb2[64], g_eb3[64], g_ebm2[256], g_ebm3[2];
__device__ int   g_P1raw[16 * 1024];
__device__ float g_Zm1[16 * 512];
__device__ float g_Zm2[16 * 256];
__device__ __align__(256) __nv_bfloat16 g_Xhi[(size_t)NPTS * 192];
__device__ __align__(256) __nv_bfloat16 g_Xlo[(size_t)NPTS * 192];
__device__ __align__(256) __nv_bfloat16 g_Whi[1024 * 192];
__device__ __align__(256) __nv_bfloat16 g_Wlo[1024 * 192];

__device__ __forceinline__ u64 pack2(float lo, float hi) {
    u64 r;
    asm("mov.b64 %0, {%1, %2};" : "=l"(r) : "f"(lo), "f"(hi));
    return r;
}
__device__ __forceinline__ float2 unpack2(u64 v) {
    float2 r;
    asm("mov.b64 {%0, %1}, %2;" : "=f"(r.x), "=f"(r.y) : "l"(v));
    return r;
}
__device__ __forceinline__ void fma2(u64& d, u64 a, u64 b) {
    asm("fma.rn.f32x2 %0, %1, %2, %0;" : "+l"(d) : "l"(a), "l"(b));
}

__device__ __forceinline__ void knn_insert(float d, int j, float bd[KN], int bi[KN]) {
#pragma unroll
    for (int k = 0; k < KN; k++) {
        if (d < bd[k]) {
            float td = bd[k]; int ti = bi[k];
            bd[k] = d; bi[k] = j;
            d = td; j = ti;
        }
    }
}

__global__ void knn3_k(const float* __restrict__ pos, int* __restrict__ idx) {
    __shared__ float sx[Pk], sy[Pk], sz[Pk], sn[Pk];
    int b = blockIdx.x >> 3;
    int p0 = (blockIdx.x & 7) << 8;
    const float* base = pos + (size_t)b * Pk * 3;
    for (int j = threadIdx.x; j < Pk; j += 256) {
        float x = base[3 * j], y = base[3 * j + 1], z = base[3 * j + 2];
        sx[j] = x; sy[j] = y; sz[j] = z;
        sn[j] = x * x + y * y + z * z;
    }
    __syncthreads();
    int p = p0 + threadIdx.x;
    float x = sx[p], y = sy[p], z = sz[p], sq = sn[p];
    float bd[KN]; int bi[KN];
#pragma unroll
    for (int k = 0; k < KN; k++) { bd[k] = 1e30f; bi[k] = 0; }
    for (int j = 0; j < Pk; j++) {
        float d = sq + sn[j] - 2.f * (x * sx[j] + y * sy[j] + z * sz[j]);
        if (d < bd[KN - 1]) knn_insert(d, j, bd, bi);
    }
    int o = (b * Pk + p) * KN;
#pragma unroll
    for (int k = 0; k < KN; k++) idx[o + k] = bi[k];
}

__global__ void ec1_l0_k(const float* __restrict__ pos, const int* __restrict__ idx,
                         const float* __restrict__ w, const float* __restrict__ bias,
                         float* __restrict__ Z) {
    __shared__ float sw[384], sb[64];
    if (threadIdx.x < 64) sb[threadIdx.x] = bias[threadIdx.x];
    for (int i = threadIdx.x; i < 384; i += 256) sw[i] = w[i];
    __syncthreads();
    int g = blockIdx.x * 256 + threadIdx.x;
    int e = g >> 2, q = g & 3;
    int pt = e / KN, b = pt >> 11, j = idx[e];
    const float* pi = pos + (size_t)pt * 3;
    const float* pj = pos + ((size_t)(b << 11) + j) * 3;
    float e0 = pi[0], e1 = pi[1], e2 = pi[2];
    float e3 = pj[0] - e0, e4 = pj[1] - e1, e5 = pj[2] - e2;
    int c0 = q * 16;
    float out[16];
#pragma unroll
    for (int c = 0; c < 16; c++) {
        int cc = c0 + c;
        float a = sb[cc];
        a = fmaf(e0, sw[cc], a);
        a = fmaf(e1, sw[64 + cc], a);
        a = fmaf(e2, sw[128 + cc], a);
        a = fmaf(e3, sw[192 + cc], a);
        a = fmaf(e4, sw[256 + cc], a);
        a = fmaf(e5, sw[320 + cc], a);
        out[c] = fmaxf(a, 0.f);
    }
    float4* dst = reinterpret_cast<float4*>(Z + (size_t)e * 64 + c0);
#pragma unroll
    for (int v = 0; v < 4; v++)
        dst[v] = make_float4(out[v * 4], out[v * 4 + 1], out[v * 4 + 2], out[v * 4 + 3]);
}

template <int C>
__global__ void stats_k(const float* __restrict__ Z, int rpb) {
    __shared__ float ssum[256], ssq[256];
    int row0 = blockIdx.x * rpb;
    const int ns = 256 / C;
    int c = threadIdx.x % C;
    int sl = threadIdx.x / C;
    int rs = rpb / ns;
    float s = 0.f, q = 0.f;
    for (int r = sl * rs; r < (sl + 1) * rs; r++) {
        float v = Z[(size_t)(row0 + r) * C + c];
        s += v; q += v * v;
    }
    ssum[threadIdx.x] = s; ssq[threadIdx.x] = q;
    __syncthreads();
    if (sl == 0) {
        for (int m = 1; m < ns; m++) { s += ssum[m * C + c]; q += ssq[m * C + c]; }
        g_part[((size_t)blockIdx.x * 2 + 0) * C + c] = s;
        g_part[((size_t)blockIdx.x * 2 + 1) * C + c] = q;
    }
}

__global__ void finalize_k(int C, float n, int nblk, const float* __restrict__ g,
                           const float* __restrict__ be,
                           float* __restrict__ scale, float* __restrict__ shift) {
    int warp = (blockIdx.x * blockDim.x + threadIdx.x) >> 5;
    int lane = threadIdx.x & 31;
    if (warp >= C) return;
    float s = 0.f, q = 0.f;
    for (int b = lane; b < nblk; b += 32) {
        s += g_part[((size_t)b * 2 + 0) * C + warp];
        q += g_part[((size_t)b * 2 + 1) * C + warp];
    }
#pragma unroll
    for (int o = 16; o; o >>= 1) {
        s += __shfl_xor_sync(0xffffffffu, s, o);
        q += __shfl_xor_sync(0xffffffffu, q, o);
    }
    if (lane == 0) {
        float mean = s / n;
        float var = q / n - mean * mean;
        float sc = g[warp] * rsqrtf(var + EPSB);
        scale[warp] = sc;
        shift[warp] = be[warp] - mean * sc;
    }
}

__global__ void foldbias_k(int Cin, int Cout, const float* __restrict__ w,
                           const float* __restrict__ bias, const float* __restrict__ shift,
                           float* __restrict__ eb) {
    int c = blockIdx.x * blockDim.x + threadIdx.x;
    if (c >= Cout) return;
    float a = bias[c];
    for (int r = 0; r < Cin; r++) a = fmaf(shift[r], w[(size_t)r * Cout + c], a);
    eb[c] = a;
}

__global__ void __launch_bounds__(256) ec_mid_k(const float* __restrict__ Zin,
                                                const float* __restrict__ w,
                                                const float* __restrict__ scaleIn,
                                                const float* __restrict__ eb,
                                                float* __restrict__ Zout) {
    __shared__ __align__(16) float At[64 * 68];
    __shared__ __align__(16) float Bs[64 * 68];
    int row0 = blockIdx.x * 64;
    for (int i = threadIdx.x; i < 4096; i += 256) {
        int r = i >> 6, k = i & 63;
        At[k * 68 + r] = Zin[(size_t)(row0 + r) * 64 + k];
    }
    for (int i = threadIdx.x; i < 4096; i += 256) {
        int k = i >> 6, c = i & 63;
        Bs[k * 68 + c] = scaleIn[k] * w[i];
    }
    __syncthreads();
    int wrp = threadIdx.x >> 5, lane = threadIdx.x & 31;
    int r0 = (wrp >> 1) * 16 + (lane >> 3) * 4;
    int c0 = (wrp & 1) * 32 + (lane & 7) * 4;
    u64 acc2[4][2] = {};
#pragma unroll 4
    for (int k = 0; k < 64; k++) {
        float4 a = *reinterpret_cast<const float4*>(&At[k * 68 + r0]);
        ulonglong2 bv = *reinterpret_cast<const ulonglong2*>(&Bs[k * 68 + c0]);
        float aa[4] = {a.x, a.y, a.z, a.w};
#pragma unroll
        for (int ii = 0; ii < 4; ii++) {
            u64 ad = pack2(aa[ii], aa[ii]);
            fma2(acc2[ii][0], ad, bv.x);
            fma2(acc2[ii][1], ad, bv.y);
        }
    }
    float e0 = eb[c0], e1 = eb[c0 + 1], e2 = eb[c0 + 2], e3 = eb[c0 + 3];
#pragma unroll
    for (int ii = 0; ii < 4; ii++) {
        float2 p0 = unpack2(acc2[ii][0]);
        float2 p1 = unpack2(acc2[ii][1]);
        float4 o;
        o.x = fmaxf(p0.x + e0, 0.f);
        o.y = fmaxf(p0.y + e1, 0.f);
        o.z = fmaxf(p1.x + e2, 0.f);
        o.w = fmaxf(p1.y + e3, 0.f);
        *reinterpret_cast<float4*>(&Zout[(size_t)(row0 + r0 + ii) * 64 + c0]) = o;
    }
}

__global__ void maxE_k(const float* __restrict__ Z, int C,
                       const float* __restrict__ scale, const float* __restrict__ shift,
                       float* __restrict__ X, int colOff, int doSq) {
    int g = blockIdx.x * 256 + threadIdx.x;
    int per = C >> 2;
    int pt = g / per;
    int c4 = (g % per) * 4;
    float4 m = make_float4(-1e30f, -1e30f, -1e30f, -1e30f);
#pragma unroll
    for (int k = 0; k < KN; k++) {
        float4 v = *reinterpret_cast<const float4*>(&Z[(size_t)(pt * KN + k) * C + c4]);
        m.x = fmaxf(m.x, v.x); m.y = fmaxf(m.y, v.y);
        m.z = fmaxf(m.z, v.z); m.w = fmaxf(m.w, v.w);
    }
    float4 o;
    o.x = fmaf(scale[c4 + 0], m.x, shift[c4 + 0]);
    o.y = fmaf(scale[c4 + 1], m.y, shift[c4 + 1]);
    o.z = fmaf(scale[c4 + 2], m.z, shift[c4 + 2]);
    o.w = fmaf(scale[c4 + 3], m.w, shift[c4 + 3]);
    *reinterpret_cast<float4*>(&X[(size_t)pt * 192 + colOff + c4]) = o;
    __nv_bfloat16 h0 = __float2bfloat16(o.x), h1 = __float2bfloat16(o.y);
    __nv_bfloat16 h2 = __float2bfloat16(o.z), h3 = __float2bfloat16(o.w);
    size_t bo = (size_t)pt * 192 + colOff + c4;
    __nv_bfloat162* dh = reinterpret_cast<__nv_bfloat162*>(&g_Xhi[bo]);
    __nv_bfloat162* dl = reinterpret_cast<__nv_bfloat162*>(&g_Xlo[bo]);
    dh[0] = __halves2bfloat162(h0, h1);
    dh[1] = __halves2bfloat162(h2, h3);
    dl[0] = __halves2bfloat162(__float2bfloat16(o.x - __bfloat162float(h0)),
                               __float2bfloat16(o.y - __bfloat162float(h1)));
    dl[1] = __halves2bfloat162(__float2bfloat16(o.z - __bfloat162float(h2)),
                               __float2bfloat16(o.w - __bfloat162float(h3)));
    if (doSq) {
        float s = o.x * o.x + o.y * o.y + o.z * o.z + o.w * o.w;
#pragma unroll
        for (int off = 8; off; off >>= 1)
            s += __shfl_down_sync(0xffffffffu, s, off, 16);
        if ((threadIdx.x & 15) == 0) g_sq[pt] = s;
    }
}

__global__ void __launch_bounds__(256) knn64_k(int* __restrict__ idx) {
    __shared__ __align__(16) float4 sq4[128 * 16];
    __shared__ float ssn[128];
    int b = blockIdx.x >> 3;
    int p = ((blockIdx.x & 7) << 8) + threadIdx.x;
    int pt = (b << 11) + p;
    ulonglong2 xpv[16];
#pragma unroll
    for (int i = 0; i < 16; i++)
        xpv[i] = *reinterpret_cast<const ulonglong2*>(&g_X12[(size_t)pt * 192 + i * 4]);
    float sqp = g_sq[pt];
    float bd[KN]; int bi[KN];
#pragma unroll
    for (int k = 0; k < KN; k++) { bd[k] = 1e30f; bi[k] = 0; }
    for (int q0 = 0; q0 < Pk; q0 += 128) {
        __syncthreads();
        for (int t = threadIdx.x; t < 2048; t += 256) {
            int qr = t >> 4, d4 = t & 15;
            sq4[qr * 16 + d4] = *reinterpret_cast<const float4*>(
                &g_X12[(size_t)((b << 11) + q0 + qr) * 192 + d4 * 4]);
        }
        if (threadIdx.x < 128) ssn[threadIdx.x] = g_sq[(b << 11) + q0 + threadIdx.x];
        __syncthreads();
        for (int qr = 0; qr < 128; qr++) {
            const ulonglong2* qv = reinterpret_cast<const ulonglong2*>(&sq4[qr * 16]);
            u64 dc[4] = {};
#pragma unroll
            for (int i = 0; i < 16; i += 2) {
                ulonglong2 qa = qv[i], qb = qv[i + 1];
                fma2(dc[0], xpv[i].x, qa.x);
                fma2(dc[1], xpv[i].y, qa.y);
                fma2(dc[2], xpv[i + 1].x, qb.x);
                fma2(dc[3], xpv[i + 1].y, qb.y);
            }
            float2 f0 = unpack2(dc[0]), f1 = unpack2(dc[1]);
            float2 f2 = unpack2(dc[2]), f3 = unpack2(dc[3]);
            float dot = ((f0.x + f0.y) + (f1.x + f1.y)) + ((f2.x + f2.y) + (f3.x + f3.y));
            float d = sqp + ssn[qr] - 2.f * dot;
            if (d < bd[KN - 1]) knn_insert(d, q0 + qr, bd, bi);
        }
    }
    int o = pt * KN;
#pragma unroll
    for (int k = 0; k < KN; k++) idx[o + k] = bi[k];
}

__global__ void __launch_bounds__(256) ec2_k(const float* __restrict__ X,
                                             const int* __restrict__ idx,
                                             const float* __restrict__ w,
                                             const float* __restrict__ bias,
                                             float* __restrict__ Z) {
    __shared__ __align__(16) float At[128 * 68];
    __shared__ __align__(16) float Bs[16 * 132];
    int e0 = blockIdx.x * 64;
    for (int i = threadIdx.x; i < 8192; i += 256) {
        int r = i >> 7, col = i & 127;
        int e = e0 + r;
        int pt = e / KN, bb = pt >> 11, j = idx[e];
        const float* xi = X + (size_t)pt * 192;
        const float* xj = X + ((size_t)(bb << 11) + j) * 192;
        At[col * 68 + r] = (col < 64) ? xi[col] : (xj[col - 64] - xi[col - 64]);
    }
    int wrp = threadIdx.x >> 5, lane = threadIdx.x & 31;
    int r0 = (wrp >> 1) * 16 + (lane >> 3) * 4;
    int c0 = (wrp & 1) * 64 + (lane & 7) * 8;
    u64 acc2[4][4] = {};
    for (int kc = 0; kc < 8; kc++) {
        __syncthreads();
        for (int i = threadIdx.x; i < 2048; i += 256) {
            int kk = i >> 7, c = i & 127;
            Bs[kk * 132 + c] = w[(size_t)(kc * 16 + kk) * 128 + c];
        }
        __syncthreads();
#pragma unroll
        for (int kk = 0; kk < 16; kk++) {
            float4 a = *reinterpret_cast<const float4*>(&At[(kc * 16 + kk) * 68 + r0]);
            ulonglong2 b01 = *reinterpret_cast<const ulonglong2*>(&Bs[kk * 132 + c0]);
            ulonglong2 b23 = *reinterpret_cast<const ulonglong2*>(&Bs[kk * 132 + c0 + 4]);
            float aa[4] = {a.x, a.y, a.z, a.w};
#pragma unroll
            for (int ii = 0; ii < 4; ii++) {
                u64 ad = pack2(aa[ii], aa[ii]);
                fma2(acc2[ii][0], ad, b01.x);
                fma2(acc2[ii][1], ad, b01.y);
                fma2(acc2[ii][2], ad, b23.x);
                fma2(acc2[ii][3], ad, b23.y);
            }
        }
    }
    float bv[8];
#pragma unroll
    for (int jj = 0; jj < 8; jj++) bv[jj] = bias[c0 + jj];
#pragma unroll
    for (int ii = 0; ii < 4; ii++) {
        float2 p0 = unpack2(acc2[ii][0]), p1 = unpack2(acc2[ii][1]);
        float2 p2 = unpack2(acc2[ii][2]), p3 = unpack2(acc2[ii][3]);
        float4 o0, o1;
        o0.x = fmaxf(p0.x + bv[0], 0.f);
        o0.y = fmaxf(p0.y + bv[1], 0.f);
        o0.z = fmaxf(p1.x + bv[2], 0.f);
        o0.w = fmaxf(p1.y + bv[3], 0.f);
        o1.x = fmaxf(p2.x + bv[4], 0.f);
        o1.y = fmaxf(p2.y + bv[5], 0.f);
        o1.z = fmaxf(p3.x + bv[6], 0.f);
        o1.w = fmaxf(p3.y + bv[7], 0.f);
        size_t off = (size_t)(e0 + r0 + ii) * 128 + c0;
        *reinterpret_cast<float4*>(&Z[off]) = o0;
        *reinterpret_cast<float4*>(&Z[off + 4]) = o1;
    }
}

__global__ void initP1_k() {
    int g = blockIdx.x * 256 + threadIdx.x;
    if (g < 16 * 1024) g_P1raw[g] = 0;
}

__global__ void wsplit_k(const float* __restrict__ w) {
    int i = blockIdx.x * 256 + threadIdx.x;
    int r = i >> 10, c = i & 1023;
    float v = w[i];
    __nv_bfloat16 h = __float2bfloat16(v);
    g_Whi[c * 192 + r] = h;
    g_Wlo[c * 192 + r] = __float2bfloat16(v - __bfloat162float(h));
}

constexpr int LSTR = 40;
__global__ void __launch_bounds__(256) mma_l1_k(const float* __restrict__ bias) {
    __shared__ __align__(16) char smbuf[128 * 68 * 4];
    __nv_bfloat16* Ah = reinterpret_cast<__nv_bfloat16*>(smbuf);
    __nv_bfloat16* Al = Ah + 128 * LSTR;
    __nv_bfloat16* Wh = Al + 128 * LSTR;
    __nv_bfloat16* Wl = Wh + 64 * LSTR;
    float* out = reinterpret_cast<float*>(smbuf);
    int tid = threadIdx.x, wrp = tid >> 5;
    int mt = blockIdx.x >> 4, nt = blockIdx.x & 15;
    int row0 = mt << 7, col0 = nt << 6;
    int wm = wrp >> 1, wn = wrp & 1;

    wmma::fragment<wmma::accumulator, 16, 16, 16, float> acc[2][2];
#pragma unroll
    for (int mm = 0; mm < 2; mm++)
#pragma unroll
        for (int nn = 0; nn < 2; nn++)
            wmma::fill_fragment(acc[mm][nn], 0.f);

    for (int kc = 0; kc < 6; kc++) {
        __syncthreads();
        for (int i = tid; i < 512; i += 256) {
            int r = i >> 2, cq = (i & 3) * 8;
            size_t g = (size_t)(row0 + r) * 192 + kc * 32 + cq;
            *reinterpret_cast<uint4*>(&Ah[r * LSTR + cq]) =
                *reinterpret_cast<const uint4*>(&g_Xhi[g]);
            *reinterpret_cast<uint4*>(&Al[r * LSTR + cq]) =
                *reinterpret_cast<const uint4*>(&g_Xlo[g]);
        }
        if (tid < 256) {
            int r = tid >> 2, cq = (tid & 3) * 8;
            size_t g = (size_t)(col0 + r) * 192 + kc * 32 + cq;
            *reinterpret_cast<uint4*>(&Wh[r * LSTR + cq]) =
                *reinterpret_cast<const uint4*>(&g_Whi[g]);
            *reinterpret_cast<uint4*>(&Wl[r * LSTR + cq]) =
                *reinterpret_cast<const uint4*>(&g_Wlo[g]);
        }
        __syncthreads();
#pragma unroll
        for (int kk = 0; kk < 32; kk += 16) {
            wmma::fragment<wmma::matrix_a, 16, 16, 16, __nv_bfloat16, wmma::row_major> ah[2], al[2];
            wmma::fragment<wmma::matrix_b, 16, 16, 16, __nv_bfloat16, wmma::col_major> bh[2], bl[2];
#pragma unroll
            for (int mm = 0; mm < 2; mm++) {
                int rb = wm * 32 + mm * 16;
                wmma::load_matrix_sync(ah[mm], &Ah[rb * LSTR + kk], LSTR);
                wmma::load_matrix_sync(al[mm], &Al[rb * LSTR + kk], LSTR);
            }
#pragma unroll
            for (int nn = 0; nn < 2; nn++) {
                int nb = wn * 32 + nn * 16;
                wmma::load_matrix_sync(bh[nn], &Wh[nb * LSTR + kk], LSTR);
                wmma::load_matrix_sync(bl[nn], &Wl[nb * LSTR + kk], LSTR);
            }
#pragma unroll
            for (int mm = 0; mm < 2; mm++)
#pragma unroll
                for (int nn = 0; nn < 2; nn++) {
                    wmma::mma_sync(acc[mm][nn], ah[mm], bh[nn], acc[mm][nn]);
                    wmma::mma_sync(acc[mm][nn], ah[mm], bl[nn], acc[mm][nn]);
                    wmma::mma_sync(acc[mm][nn], al[mm], bh[nn], acc[mm][nn]);
                }
        }
    }
    __syncthreads();
#pragma unroll
    for (int mm = 0; mm < 2; mm++)
#pragma unroll
        for (int nn = 0; nn < 2; nn++) {
            int r = wm * 32 + mm * 16;
            int c = wn * 32 + nn * 16;
            wmma::store_matrix_sync(&out[r * 68 + c], acc[mm][nn], 68, wmma::mem_row_major);
        }
    __syncthreads();
    for (int i = tid; i < 8192; i += 256) {
        int r = i >> 6, c = i & 63;
        out[r * 68 + c] = fmaxf(out[r * 68 + c] + bias[col0 + c], 0.f);
    }
    __syncthreads();
    if (tid < 64) {
        float s = 0.f, q = 0.f, m = 0.f;
        for (int r = 0; r < 128; r++) {
            float v = out[r * 68 + tid];
            s += v; q += v * v; m = fmaxf(m, v);
        }
        g_part[((size_t)mt * 2 + 0) * 1024 + col0 + tid] = s;
        g_part[((size_t)mt * 2 + 1) * 1024 + col0 + tid] = q;
        atomicMax(&g_P1raw[(row0 >> 11) * 1024 + col0 + tid], __float_as_int(m));
    }
}

__global__ void head1_k(const float* __restrict__ w, const float* __restrict__ bias) {
    __shared__ float sp[1024];
    int g = blockIdx.x * 256 + threadIdx.x;
    int b = g >> 9, c = g & 511;
    for (int i = threadIdx.x; i < 1024; i += 256)
        sp[i] = fmaf(g_s5[i], __int_as_float(g_P1raw[(b << 10) + i]), g_h5[i]);
    __syncthreads();
    float a = bias[c];
#pragma unroll 8
    for (int r = 0; r < 1024; r++) a = fmaf(sp[r], w[(size_t)r * 512 + c], a);
    g_Zm1[g] = fmaxf(a, 0.f);
}

__global__ void stats16_k(const float* __restrict__ Z, int C,
                          const float* __restrict__ g, const float* __restrict__ be,
                          float* __restrict__ scale, float* __restrict__ shift) {
    int c = blockIdx.x * blockDim.x + threadIdx.x;
    if (c >= C) return;
    float s = 0.f, q = 0.f;
    for (int b = 0; b < 16; b++) { float v = Z[b * C + c]; s += v; q += v * v; }
    float mean = s * 0.0625f;
    float var = q * 0.0625f - mean * mean;
    float sc = g[c] * rsqrtf(var + EPSB);
    scale[c] = sc;
    shift[c] = be[c] - mean * sc;
}

__global__ void head2_k(const float* __restrict__ w) {
    int g = blockIdx.x * 256 + threadIdx.x;
    int b = g >> 8, c = g & 255;
    float a = g_ebm2[c];
    const float* z = g_Zm1 + b * 512;
#pragma unroll 8
    for (int r = 0; r < 512; r++) a = fmaf(z[r] * g_s6[r], w[(size_t)r * 256 + c], a);
    g_Zm2[g] = fmaxf(a, 0.f);
}

__global__ void head3_k(const float* __restrict__ w, float* __restrict__ out) {
    int t = threadIdx.x;
    if (t >= 32) return;
    int b = t >> 1, n = t & 1;
    float a = g_ebm3[n];
    const float* z = g_Zm2 + b * 256;
#pragma unroll 8
    for (int r = 0; r < 256; r++) a = fmaf(z[r] * g_s7[r], w[r * 2 + n], a);
    out[b * 2 + n] = a;
}

static void* symaddr(const void* s) {
    void* p = nullptr;
    cudaGetSymbolAddress(&p, s);
    return p;
}

extern "C" void kernel_launch(void* const* d_in, const int* in_sizes, int n_in,
                              void* d_out, int out_size) {
    const float* pos = (const float*)d_in[0];
    const float* c1w0 = (const float*)d_in[1];
    const float* c1b0 = (const float*)d_in[2];
    const float* c1g0 = (const float*)d_in[3];
    const float* c1e0 = (const float*)d_in[4];
    const float* c1w1 = (const float*)d_in[5];
    const float* c1b1 = (const float*)d_in[6];
    const float* c1g1 = (const float*)d_in[7];
    const float* c1e1 = (const float*)d_in[8];
    const float* c1w2 = (const float*)d_in[9];
    const float* c1b2 = (const float*)d_in[10];
    const float* c1g2 = (const float*)d_in[11];
    const float* c1e2 = (const float*)d_in[12];
    const float* c2w = (const float*)d_in[13];
    const float* c2b = (const float*)d_in[14];
    const float* c2g = (const float*)d_in[15];
    const float* c2e = (const float*)d_in[16];
    const float* l1w = (const float*)d_in[17];
    const float* l1b = (const float*)d_in[18];
    const float* l1g = (const float*)d_in[19];
    const float* l1e = (const float*)d_in[20];
    const float* m1w = (const float*)d_in[21];
    const float* m1b = (const float*)d_in[22];
    const float* m1g = (const float*)d_in[23];
    const float* m1e = (const float*)d_in[24];
    const float* m2w = (const float*)d_in[25];
    const float* m2b = (const float*)d_in[26];
    const float* m2g = (const float*)d_in[27];
    const float* m2e = (const float*)d_in[28];
    const float* m3w = (const float*)d_in[29];
    const float* m3b = (const float*)d_in[30];

    float* Z1 = (float*)symaddr(g_Z1);
    float* Z2 = (float*)symaddr(g_Z2);
    float* Z4 = (float*)symaddr(g_Z4);
    float* X = (float*)symaddr(g_X12);
    int* I1 = (int*)symaddr(g_idx1);
    int* I2 = (int*)symaddr(g_idx2);
    float* s1 = (float*)symaddr(g_s1);
    float* h1 = (float*)symaddr(g_h1);
    float* s2 = (float*)symaddr(g_s2);
    float* h2 = (float*)symaddr(g_h2);
    float* s3 = (float*)symaddr(g_s3);
    float* h3 = (float*)symaddr(g_h3);
    float* s4 = (float*)symaddr(g_s4);
    float* h4 = (float*)symaddr(g_h4);
    float* s5 = (float*)symaddr(g_s5);
    float* h5 = (float*)symaddr(g_h5);
    float* s6 = (float*)symaddr(g_s6);
    float* h6 = (float*)symaddr(g_h6);
    float* s7 = (float*)symaddr(g_s7);
    float* h7 = (float*)symaddr(g_h7);
    float* eb2 = (float*)symaddr(g_eb2);
    float* eb3 = (float*)symaddr(g_eb3);
    float* ebm2 = (float*)symaddr(g_ebm2);
    float* ebm3 = (float*)symaddr(g_ebm3);
    float* Zm1 = (float*)symaddr(g_Zm1);
    float* Zm2 = (float*)symaddr(g_Zm2);

    wsplit_k<<<768, 256>>>(l1w);
    knn3_k<<<128, 256>>>(pos, I1);
    ec1_l0_k<<<NEDG * 4 / 256, 256>>>(pos, I1, c1w0, c1b0, Z1);
    stats_k<64><<<NBLK, 256>>>(Z1, NEDG / NBLK);
    finalize_k<<<8, 256>>>(64, (float)NEDG, NBLK, c1g0, c1e0, s1, h1);
    foldbias_k<<<1, 64>>>(64, 64, c1w1, c1b1, h1, eb2);
    ec_mid_k<<<NEDG / 64, 256>>>(Z1, c1w1, s1, eb2, Z2);
    stats_k<64><<<NBLK, 256>>>(Z2, NEDG / NBLK);
    finalize_k<<<8, 256>>>(64, (float)NEDG, NBLK, c1g1, c1e1, s2, h2);
    foldbias_k<<<1, 64>>>(64, 64, c1w2, c1b2, h2, eb3);
    ec_mid_k<<<NEDG / 64, 256>>>(Z2, c1w2, s2, eb3, Z1);
    stats_k<64><<<NBLK, 256>>>(Z1, NEDG / NBLK);
    finalize_k<<<8, 256>>>(64, (float)NEDG, NBLK, c1g2, c1e2, s3, h3);
    maxE_k<<<NPTS * 16 / 256, 256>>>(Z1, 64, s3, h3, X, 0, 1);

    knn64_k<<<128, 256>>>(I2);
    ec2_k<<<NEDG / 64, 256>>>(X, I2, c2w, c2b, Z4);
    stats_k<128><<<NBLK, 256>>>(Z4, NEDG / NBLK);
    finalize_k<<<16, 256>>>(128, (float)NEDG, NBLK, c2g, c2e, s4, h4);
    maxE_k<<<NPTS * 32 / 256, 256>>>(Z4, 128, s4, h4, X, 64, 0);

    initP1_k<<<64, 256>>>();
    mma_l1_k<<<4096, 256>>>(l1b);
    finalize_k<<<128, 256>>>(1024, (float)NPTS, 256, l1g, l1e, s5, h5);

    head1_k<<<32, 256>>>(m1w, m1b);
    stats16_k<<<2, 256>>>(Zm1, 512, m1g, m1e, s6, h6);
    foldbias_k<<<1, 256>>>(512, 256, m2w, m2b, h6, ebm2);
    head2_k<<<16, 256>>>(m2w);
    stats16_k<<<1, 256>>>(Zm2, 256, m2g, m2e, s7, h7);
    foldbias_k<<<1, 32>>>(256, 2, m3w, m3b, h7, ebm3);
    head3_k<<<1, 32>>>(m3w, (float*)d_out);
}

// round 11
// speedup vs baseline: 1.3161x; 1.1016x over previous
#include <cuda_runtime.h>
#include <cuda_bf16.h>
#include <mma.h>
#include <cstddef>

using namespace nvcuda;

#define EPSB 1e-5f
constexpr int Pk = 2048;
constexpr int KN = 5;
constexpr int NPTS = 16 * Pk;
constexpr int NEDG = NPTS * KN;
using u64 = unsigned long long;

__device__ float g_Z1[(size_t)NEDG * 64];
__device__ float g_Z2[(size_t)NEDG * 64];
__device__ float g_Z4[(size_t)NEDG * 128];
__device__ float g_X12[(size_t)NPTS * 192];
__device__ float g_sq[NPTS];
__device__ int   g_idx1[NEDG];
__device__ int   g_idx2[NEDG];
__device__ float g_part[(size_t)2560 * 2 * 128];
__device__ float g_partL[(size_t)256 * 2 * 1024];
__device__ float g_s1[64], g_h1[64], g_s2[64], g_h2[64], g_s3[64], g_h3[64];
__device__ float g_s4[128], g_h4[128], g_s5[1024], g_h5[1024];
__device__ float g_s6[512], g_h6[512], g_s7[256], g_h7[256];
__device__ float g_eb2[64], g_eb3[64], g_ebm2[256], g_ebm3[2];
__device__ int   g_P1raw[16 * 1024];
__device__ float g_Zm1[16 * 512];
__device__ float g_Zm2[16 * 256];
__device__ __align__(256) __nv_bfloat16 g_Xhi[(size_t)NPTS * 192];
__device__ __align__(256) __nv_bfloat16 g_Xlo[(size_t)NPTS * 192];
__device__ __align__(256) __nv_bfloat16 g_Whi[1024 * 192];
__device__ __align__(256) __nv_bfloat16 g_Wlo[1024 * 192];
__device__ __align__(256) __nv_bfloat16 g_W2hi[128 * 128];
__device__ __align__(256) __nv_bfloat16 g_W2lo[128 * 128];

__device__ __forceinline__ u64 pack2(float lo, float hi) {
    u64 r;
    asm("mov.b64 %0, {%1, %2};" : "=l"(r) : "f"(lo), "f"(hi));
    return r;
}
__device__ __forceinline__ float2 unpack2(u64 v) {
    float2 r;
    asm("mov.b64 {%0, %1}, %2;" : "=f"(r.x), "=f"(r.y) : "l"(v));
    return r;
}
__device__ __forceinline__ void fma2(u64& d, u64 a, u64 b) {
    asm("fma.rn.f32x2 %0, %1, %2, %0;" : "+l"(d) : "l"(a), "l"(b));
}

__device__ __forceinline__ void knn_insert(float d, int j, float bd[KN], int bi[KN]) {
#pragma unroll
    for (int k = 0; k < KN; k++) {
        if (d < bd[k]) {
            float td = bd[k]; int ti = bi[k];
            bd[k] = d; bi[k] = j;
            d = td; j = ti;
        }
    }
}

__global__ void knn3_k(const float* __restrict__ pos, int* __restrict__ idx) {
    __shared__ float sx[Pk], sy[Pk], sz[Pk], sn[Pk];
    int b = blockIdx.x >> 3;
    int p0 = (blockIdx.x & 7) << 8;
    const float* base = pos + (size_t)b * Pk * 3;
    for (int j = threadIdx.x; j < Pk; j += 256) {
        float x = base[3 * j], y = base[3 * j + 1], z = base[3 * j + 2];
        sx[j] = x; sy[j] = y; sz[j] = z;
        sn[j] = x * x + y * y + z * z;
    }
    __syncthreads();
    int p = p0 + threadIdx.x;
    float x = sx[p], y = sy[p], z = sz[p], sq = sn[p];
    float bd[KN]; int bi[KN];
#pragma unroll
    for (int k = 0; k < KN; k++) { bd[k] = 1e30f; bi[k] = 0; }
    for (int j = 0; j < Pk; j++) {
        float d = sq + sn[j] - 2.f * (x * sx[j] + y * sy[j] + z * sz[j]);
        if (d < bd[KN - 1]) knn_insert(d, j, bd, bi);
    }
    int o = (b * Pk + p) * KN;
#pragma unroll
    for (int k = 0; k < KN; k++) idx[o + k] = bi[k];
}

// edges(6)->64, ReLU, fused per-block stats partials (64 edges/block)
__global__ void ec1_l0_k(const float* __restrict__ pos, const int* __restrict__ idx,
                         const float* __restrict__ w, const float* __restrict__ bias,
                         float* __restrict__ Z) {
    __shared__ float sw[384], sb[64];
    __shared__ float red[64 * 64];
    if (threadIdx.x < 64) sb[threadIdx.x] = bias[threadIdx.x];
    for (int i = threadIdx.x; i < 384; i += 256) sw[i] = w[i];
    __syncthreads();
    int g = blockIdx.x * 256 + threadIdx.x;
    int e = g >> 2, q = g & 3;
    int lr = threadIdx.x >> 2;
    int pt = e / KN, b = pt >> 11, j = idx[e];
    const float* pi = pos + (size_t)pt * 3;
    const float* pj = pos + ((size_t)(b << 11) + j) * 3;
    float e0 = pi[0], e1 = pi[1], e2 = pi[2];
    float e3 = pj[0] - e0, e4 = pj[1] - e1, e5 = pj[2] - e2;
    int c0 = q * 16;
    float out[16];
#pragma unroll
    for (int c = 0; c < 16; c++) {
        int cc = c0 + c;
        float a = sb[cc];
        a = fmaf(e0, sw[cc], a);
        a = fmaf(e1, sw[64 + cc], a);
        a = fmaf(e2, sw[128 + cc], a);
        a = fmaf(e3, sw[192 + cc], a);
        a = fmaf(e4, sw[256 + cc], a);
        a = fmaf(e5, sw[320 + cc], a);
        out[c] = fmaxf(a, 0.f);
        red[lr * 64 + cc] = out[c];
    }
    float4* dst = reinterpret_cast<float4*>(Z + (size_t)e * 64 + c0);
#pragma unroll
    for (int v = 0; v < 4; v++)
        dst[v] = make_float4(out[v * 4], out[v * 4 + 1], out[v * 4 + 2], out[v * 4 + 3]);
    __syncthreads();
    if (threadIdx.x < 64) {
        float s = 0.f, qq = 0.f;
        for (int r = 0; r < 64; r++) {
            float v = red[r * 64 + threadIdx.x];
            s += v; qq += v * v;
        }
        g_part[((size_t)blockIdx.x * 2 + 0) * 64 + threadIdx.x] = s;
        g_part[((size_t)blockIdx.x * 2 + 1) * 64 + threadIdx.x] = qq;
    }
}

__global__ void finalize_k(int C, float n, int nblk, const float* __restrict__ g,
                           const float* __restrict__ be, const float* __restrict__ part,
                           float* __restrict__ scale, float* __restrict__ shift) {
    int warp = (blockIdx.x * blockDim.x + threadIdx.x) >> 5;
    int lane = threadIdx.x & 31;
    if (warp >= C) return;
    float s = 0.f, q = 0.f;
    for (int b = lane; b < nblk; b += 32) {
        s += part[((size_t)b * 2 + 0) * C + warp];
        q += part[((size_t)b * 2 + 1) * C + warp];
    }
#pragma unroll
    for (int o = 16; o; o >>= 1) {
        s += __shfl_xor_sync(0xffffffffu, s, o);
        q += __shfl_xor_sync(0xffffffffu, q, o);
    }
    if (lane == 0) {
        float mean = s / n;
        float var = q / n - mean * mean;
        float sc = g[warp] * rsqrtf(var + EPSB);
        scale[warp] = sc;
        shift[warp] = be[warp] - mean * sc;
    }
}

__global__ void foldbias_k(int Cin, int Cout, const float* __restrict__ w,
                           const float* __restrict__ bias, const float* __restrict__ shift,
                           float* __restrict__ eb) {
    int c = blockIdx.x * blockDim.x + threadIdx.x;
    if (c >= Cout) return;
    float a = bias[c];
    for (int r = 0; r < Cin; r++) a = fmaf(shift[r], w[(size_t)r * Cout + c], a);
    eb[c] = a;
}

// 64->64 GEMM, ReLU, fused stats partials (64 edges/block)
__global__ void __launch_bounds__(256) ec_mid_k(const float* __restrict__ Zin,
                                                const float* __restrict__ w,
                                                const float* __restrict__ scaleIn,
                                                const float* __restrict__ eb,
                                                float* __restrict__ Zout) {
    __shared__ __align__(16) float At[64 * 68];
    __shared__ __align__(16) float Bs[64 * 68];
    int row0 = blockIdx.x * 64;
    for (int i = threadIdx.x; i < 4096; i += 256) {
        int r = i >> 6, k = i & 63;
        At[k * 68 + r] = Zin[(size_t)(row0 + r) * 64 + k];
    }
    for (int i = threadIdx.x; i < 4096; i += 256) {
        int k = i >> 6, c = i & 63;
        Bs[k * 68 + c] = scaleIn[k] * w[i];
    }
    __syncthreads();
    int wrp = threadIdx.x >> 5, lane = threadIdx.x & 31;
    int r0 = (wrp >> 1) * 16 + (lane >> 3) * 4;
    int c0 = (wrp & 1) * 32 + (lane & 7) * 4;
    u64 acc2[4][2] = {};
#pragma unroll 4
    for (int k = 0; k < 64; k++) {
        float4 a = *reinterpret_cast<const float4*>(&At[k * 68 + r0]);
        ulonglong2 bv = *reinterpret_cast<const ulonglong2*>(&Bs[k * 68 + c0]);
        float aa[4] = {a.x, a.y, a.z, a.w};
#pragma unroll
        for (int ii = 0; ii < 4; ii++) {
            u64 ad = pack2(aa[ii], aa[ii]);
            fma2(acc2[ii][0], ad, bv.x);
            fma2(acc2[ii][1], ad, bv.y);
        }
    }
    float e0 = eb[c0], e1 = eb[c0 + 1], e2 = eb[c0 + 2], e3 = eb[c0 + 3];
    __syncthreads();
#pragma unroll
    for (int ii = 0; ii < 4; ii++) {
        float2 p0 = unpack2(acc2[ii][0]);
        float2 p1 = unpack2(acc2[ii][1]);
        float4 o;
        o.x = fmaxf(p0.x + e0, 0.f);
        o.y = fmaxf(p0.y + e1, 0.f);
        o.z = fmaxf(p1.x + e2, 0.f);
        o.w = fmaxf(p1.y + e3, 0.f);
        *reinterpret_cast<float4*>(&Zout[(size_t)(row0 + r0 + ii) * 64 + c0]) = o;
        *reinterpret_cast<float4*>(&At[(r0 + ii) * 68 + c0]) = o;
    }
    __syncthreads();
    if (threadIdx.x < 64) {
        float s = 0.f, qq = 0.f;
        for (int r = 0; r < 64; r++) {
            float v = At[r * 68 + threadIdx.x];
            s += v; qq += v * v;
        }
        g_part[((size_t)blockIdx.x * 2 + 0) * 64 + threadIdx.x] = s;
        g_part[((size_t)blockIdx.x * 2 + 1) * 64 + threadIdx.x] = qq;
    }
}

__global__ void maxE_k(const float* __restrict__ Z, int C,
                       const float* __restrict__ scale, const float* __restrict__ shift,
                       float* __restrict__ X, int colOff, int doSq) {
    int g = blockIdx.x * 256 + threadIdx.x;
    int per = C >> 2;
    int pt = g / per;
    int c4 = (g % per) * 4;
    float4 m = make_float4(-1e30f, -1e30f, -1e30f, -1e30f);
#pragma unroll
    for (int k = 0; k < KN; k++) {
        float4 v = *reinterpret_cast<const float4*>(&Z[(size_t)(pt * KN + k) * C + c4]);
        m.x = fmaxf(m.x, v.x); m.y = fmaxf(m.y, v.y);
        m.z = fmaxf(m.z, v.z); m.w = fmaxf(m.w, v.w);
    }
    float4 o;
    o.x = fmaf(scale[c4 + 0], m.x, shift[c4 + 0]);
    o.y = fmaf(scale[c4 + 1], m.y, shift[c4 + 1]);
    o.z = fmaf(scale[c4 + 2], m.z, shift[c4 + 2]);
    o.w = fmaf(scale[c4 + 3], m.w, shift[c4 + 3]);
    *reinterpret_cast<float4*>(&X[(size_t)pt * 192 + colOff + c4]) = o;
    __nv_bfloat16 h0 = __float2bfloat16(o.x), h1 = __float2bfloat16(o.y);
    __nv_bfloat16 h2 = __float2bfloat16(o.z), h3 = __float2bfloat16(o.w);
    size_t bo = (size_t)pt * 192 + colOff + c4;
    __nv_bfloat162* dh = reinterpret_cast<__nv_bfloat162*>(&g_Xhi[bo]);
    __nv_bfloat162* dl = reinterpret_cast<__nv_bfloat162*>(&g_Xlo[bo]);
    dh[0] = __halves2bfloat162(h0, h1);
    dh[1] = __halves2bfloat162(h2, h3);
    dl[0] = __halves2bfloat162(__float2bfloat16(o.x - __bfloat162float(h0)),
                               __float2bfloat16(o.y - __bfloat162float(h1)));
    dl[1] = __halves2bfloat162(__float2bfloat16(o.z - __bfloat162float(h2)),
                               __float2bfloat16(o.w - __bfloat162float(h3)));
    if (doSq) {
        float s = o.x * o.x + o.y * o.y + o.z * o.z + o.w * o.w;
#pragma unroll
        for (int off = 8; off; off >>= 1)
            s += __shfl_down_sync(0xffffffffu, s, off, 16);
        if ((threadIdx.x & 15) == 0) g_sq[pt] = s;
    }
}

__global__ void __launch_bounds__(256) knn64_k(int* __restrict__ idx) {
    __shared__ __align__(16) float4 sq4[128 * 16];
    __shared__ float ssn[128];
    int b = blockIdx.x >> 3;
    int p = ((blockIdx.x & 7) << 8) + threadIdx.x;
    int pt = (b << 11) + p;
    ulonglong2 xpv[16];
#pragma unroll
    for (int i = 0; i < 16; i++)
        xpv[i] = *reinterpret_cast<const ulonglong2*>(&g_X12[(size_t)pt * 192 + i * 4]);
    float sqp = g_sq[pt];
    float bd[KN]; int bi[KN];
#pragma unroll
    for (int k = 0; k < KN; k++) { bd[k] = 1e30f; bi[k] = 0; }
    for (int q0 = 0; q0 < Pk; q0 += 128) {
        __syncthreads();
        for (int t = threadIdx.x; t < 2048; t += 256) {
            int qr = t >> 4, d4 = t & 15;
            sq4[qr * 16 + d4] = *reinterpret_cast<const float4*>(
                &g_X12[(size_t)((b << 11) + q0 + qr) * 192 + d4 * 4]);
        }
        if (threadIdx.x < 128) ssn[threadIdx.x] = g_sq[(b << 11) + q0 + threadIdx.x];
        __syncthreads();
        for (int qr = 0; qr < 128; qr++) {
            const ulonglong2* qv = reinterpret_cast<const ulonglong2*>(&sq4[qr * 16]);
            u64 dc[4] = {};
#pragma unroll
            for (int i = 0; i < 16; i += 2) {
                ulonglong2 qa = qv[i], qb = qv[i + 1];
                fma2(dc[0], xpv[i].x, qa.x);
                fma2(dc[1], xpv[i].y, qa.y);
                fma2(dc[2], xpv[i + 1].x, qb.x);
                fma2(dc[3], xpv[i + 1].y, qb.y);
            }
            float2 f0 = unpack2(dc[0]), f1 = unpack2(dc[1]);
            float2 f2 = unpack2(dc[2]), f3 = unpack2(dc[3]);
            float dot = ((f0.x + f0.y) + (f1.x + f1.y)) + ((f2.x + f2.y) + (f3.x + f3.y));
            float d = sqp + ssn[qr] - 2.f * dot;
            if (d < bd[KN - 1]) knn_insert(d, q0 + qr, bd, bi);
        }
    }
    int o = pt * KN;
#pragma unroll
    for (int k = 0; k < KN; k++) idx[o + k] = bi[k];
}

__global__ void wsplit2_k(const float* __restrict__ w) {
    int i = blockIdx.x * 256 + threadIdx.x;
    if (i >= 128 * 128) return;
    int r = i >> 7, c = i & 127;
    float v = w[i];
    __nv_bfloat16 h = __float2bfloat16(v);
    g_W2hi[c * 128 + r] = h;
    g_W2lo[c * 128 + r] = __float2bfloat16(v - __bfloat162float(h));
}

// WMMA EdgeConv2: gather(128) + GEMM 128x128, ReLU, stats (128 edges/block)
constexpr int EST = 40;
__global__ void __launch_bounds__(256) mma_ec2_k(const float* __restrict__ X,
                                                 const int* __restrict__ idx,
                                                 const float* __restrict__ bias,
                                                 float* __restrict__ Z) {
    extern __shared__ char dynbuf[];
    __nv_bfloat16* Ah = reinterpret_cast<__nv_bfloat16*>(dynbuf);
    __nv_bfloat16* Al = Ah + 128 * EST;
    __nv_bfloat16* Wh = Al + 128 * EST;
    __nv_bfloat16* Wl = Wh + 128 * EST;
    float* out = reinterpret_cast<float*>(dynbuf);
    int tid = threadIdx.x, wrp = tid >> 5;
    int e0 = blockIdx.x * 128;
    int wm = wrp >> 1, wn = wrp & 1;
    wmma::fragment<wmma::accumulator, 16, 16, 16, float> acc[2][4];
#pragma unroll
    for (int mm = 0; mm < 2; mm++)
#pragma unroll
        for (int nn = 0; nn < 4; nn++)
            wmma::fill_fragment(acc[mm][nn], 0.f);

    for (int kc = 0; kc < 4; kc++) {
        __syncthreads();
        for (int i = tid; i < 4096; i += 256) {
            int r = i >> 5, cq = i & 31;
            int col = kc * 32 + cq;
            int e = e0 + r;
            int pt = e / KN, bb = pt >> 11, j = idx[e];
            const float* xi = X + (size_t)pt * 192;
            const float* xj = X + ((size_t)(bb << 11) + j) * 192;
            float v = (col < 64) ? xi[col] : (xj[col - 64] - xi[col - 64]);
            __nv_bfloat16 h = __float2bfloat16(v);
            Ah[r * EST + cq] = h;
            Al[r * EST + cq] = __float2bfloat16(v - __bfloat162float(h));
        }
        if (tid < 256) {
            for (int i = tid; i < 512; i += 256) {
                int r = i >> 2, cq = (i & 3) * 8;
                size_t gg = (size_t)r * 128 + kc * 32 + cq;
                *reinterpret_cast<uint4*>(&Wh[r * EST + cq]) =
                    *reinterpret_cast<const uint4*>(&g_W2hi[gg]);
                *reinterpret_cast<uint4*>(&Wl[r * EST + cq]) =
                    *reinterpret_cast<const uint4*>(&g_W2lo[gg]);
            }
        }
        __syncthreads();
#pragma unroll
        for (int kk = 0; kk < 32; kk += 16) {
            wmma::fragment<wmma::matrix_a, 16, 16, 16, __nv_bfloat16, wmma::row_major> ah[2], al[2];
            wmma::fragment<wmma::matrix_b, 16, 16, 16, __nv_bfloat16, wmma::col_major> bh[4], bl[4];
#pragma unroll
            for (int mm = 0; mm < 2; mm++) {
                int rb = wm * 32 + mm * 16;
                wmma::load_matrix_sync(ah[mm], &Ah[rb * EST + kk], EST);
                wmma::load_matrix_sync(al[mm], &Al[rb * EST + kk], EST);
            }
#pragma unroll
            for (int nn = 0; nn < 4; nn++) {
                int nb = wn * 64 + nn * 16;
                wmma::load_matrix_sync(bh[nn], &Wh[nb * EST + kk], EST);
                wmma::load_matrix_sync(bl[nn], &Wl[nb * EST + kk], EST);
            }
#pragma unroll
            for (int mm = 0; mm < 2; mm++)
#pragma unroll
                for (int nn = 0; nn < 4; nn++) {
                    wmma::mma_sync(acc[mm][nn], ah[mm], bh[nn], acc[mm][nn]);
                    wmma::mma_sync(acc[mm][nn], ah[mm], bl[nn], acc[mm][nn]);
                    wmma::mma_sync(acc[mm][nn], al[mm], bh[nn], acc[mm][nn]);
                }
        }
    }
    __syncthreads();
#pragma unroll
    for (int mm = 0; mm < 2; mm++)
#pragma unroll
        for (int nn = 0; nn < 4; nn++) {
            int r = wm * 32 + mm * 16;
            int c = wn * 64 + nn * 16;
            wmma::store_matrix_sync(&out[r * 132 + c], acc[mm][nn], 132, wmma::mem_row_major);
        }
    __syncthreads();
    for (int i = tid; i < 4096; i += 256) {
        int r = i >> 5, c4 = (i & 31) * 4;
        float4 v = *reinterpret_cast<float4*>(&out[r * 132 + c4]);
        v.x = fmaxf(v.x + bias[c4 + 0], 0.f);
        v.y = fmaxf(v.y + bias[c4 + 1], 0.f);
        v.z = fmaxf(v.z + bias[c4 + 2], 0.f);
        v.w = fmaxf(v.w + bias[c4 + 3], 0.f);
        *reinterpret_cast<float4*>(&out[r * 132 + c4]) = v;
        *reinterpret_cast<float4*>(&Z[(size_t)(e0 + r) * 128 + c4]) = v;
    }
    __syncthreads();
    if (tid < 128) {
        float s = 0.f, qq = 0.f;
        for (int r = 0; r < 128; r++) {
            float v = out[r * 132 + tid];
            s += v; qq += v * v;
        }
        g_part[((size_t)blockIdx.x * 2 + 0) * 128 + tid] = s;
        g_part[((size_t)blockIdx.x * 2 + 1) * 128 + tid] = qq;
    }
}

__global__ void initP1_k() {
    int g = blockIdx.x * 256 + threadIdx.x;
    if (g < 16 * 1024) g_P1raw[g] = 0;
}

__global__ void wsplit_k(const float* __restrict__ w) {
    int i = blockIdx.x * 256 + threadIdx.x;
    int r = i >> 10, c = i & 1023;
    float v = w[i];
    __nv_bfloat16 h = __float2bfloat16(v);
    g_Whi[c * 192 + r] = h;
    g_Wlo[c * 192 + r] = __float2bfloat16(v - __bfloat162float(h));
}

constexpr int LSTR = 40;
__global__ void __launch_bounds__(256) mma_l1_k(const float* __restrict__ bias) {
    __shared__ __align__(16) char smbuf[128 * 68 * 4];
    __nv_bfloat16* Ah = reinterpret_cast<__nv_bfloat16*>(smbuf);
    __nv_bfloat16* Al = Ah + 128 * LSTR;
    __nv_bfloat16* Wh = Al + 128 * LSTR;
    __nv_bfloat16* Wl = Wh + 64 * LSTR;
    float* out = reinterpret_cast<float*>(smbuf);
    int tid = threadIdx.x, wrp = tid >> 5;
    int mt = blockIdx.x >> 4, nt = blockIdx.x & 15;
    int row0 = mt << 7, col0 = nt << 6;
    int wm = wrp >> 1, wn = wrp & 1;
    wmma::fragment<wmma::accumulator, 16, 16, 16, float> acc[2][2];
#pragma unroll
    for (int mm = 0; mm < 2; mm++)
#pragma unroll
        for (int nn = 0; nn < 2; nn++)
            wmma::fill_fragment(acc[mm][nn], 0.f);

    for (int kc = 0; kc < 6; kc++) {
        __syncthreads();
        for (int i = tid; i < 512; i += 256) {
            int r = i >> 2, cq = (i & 3) * 8;
            size_t g = (size_t)(row0 + r) * 192 + kc * 32 + cq;
            *reinterpret_cast<uint4*>(&Ah[r * LSTR + cq]) =
                *reinterpret_cast<const uint4*>(&g_Xhi[g]);
            *reinterpret_cast<uint4*>(&Al[r * LSTR + cq]) =
                *reinterpret_cast<const uint4*>(&g_Xlo[g]);
        }
        if (tid < 256) {
            int r = tid >> 2, cq = (tid & 3) * 8;
            size_t g = (size_t)(col0 + r) * 192 + kc * 32 + cq;
            *reinterpret_cast<uint4*>(&Wh[r * LSTR + cq]) =
                *reinterpret_cast<const uint4*>(&g_Whi[g]);
            *reinterpret_cast<uint4*>(&Wl[r * LSTR + cq]) =
                *reinterpret_cast<const uint4*>(&g_Wlo[g]);
        }
        __syncthreads();
#pragma unroll
        for (int kk = 0; kk < 32; kk += 16) {
            wmma::fragment<wmma::matrix_a, 16, 16, 16, __nv_bfloat16, wmma::row_major> ah[2], al[2];
            wmma::fragment<wmma::matrix_b, 16, 16, 16, __nv_bfloat16, wmma::col_major> bh[2], bl[2];
#pragma unroll
            for (int mm = 0; mm < 2; mm++) {
                int rb = wm * 32 + mm * 16;
                wmma::load_matrix_sync(ah[mm], &Ah[rb * LSTR + kk], LSTR);
                wmma::load_matrix_sync(al[mm], &Al[rb * LSTR + kk], LSTR);
            }
#pragma unroll
            for (int nn = 0; nn < 2; nn++) {
                int nb = wn * 32 + nn * 16;
                wmma::load_matrix_sync(bh[nn], &Wh[nb * LSTR + kk], LSTR);
                wmma::load_matrix_sync(bl[nn], &Wl[nb * LSTR + kk], LSTR);
            }
#pragma unroll
            for (int mm = 0; mm < 2; mm++)
#pragma unroll
                for (int nn = 0; nn < 2; nn++) {
                    wmma::mma_sync(acc[mm][nn], ah[mm], bh[nn], acc[mm][nn]);
                    wmma::mma_sync(acc[mm][nn], ah[mm], bl[nn], acc[mm][nn]);
                    wmma::mma_sync(acc[mm][nn], al[mm], bh[nn], acc[mm][nn]);
                }
        }
    }
    __syncthreads();
#pragma unroll
    for (int mm = 0; mm < 2; mm++)
#pragma unroll
        for (int nn = 0; nn < 2; nn++) {
            int r = wm * 32 + mm * 16;
            int c = wn * 32 + nn * 16;
            wmma::store_matrix_sync(&out[r * 68 + c], acc[mm][nn], 68, wmma::mem_row_major);
        }
    __syncthreads();
    for (int i = tid; i < 8192; i += 256) {
        int r = i >> 6, c = i & 63;
        out[r * 68 + c] = fmaxf(out[r * 68 + c] + bias[col0 + c], 0.f);
    }
    __syncthreads();
    if (tid < 64) {
        float s = 0.f, q = 0.f, m = 0.f;
        for (int r = 0; r < 128; r++) {
            float v = out[r * 68 + tid];
            s += v; q += v * v; m = fmaxf(m, v);
        }
        g_partL[((size_t)mt * 2 + 0) * 1024 + col0 + tid] = s;
        g_partL[((size_t)mt * 2 + 1) * 1024 + col0 + tid] = q;
        atomicMax(&g_P1raw[(row0 >> 11) * 1024 + col0 + tid], __float_as_int(m));
    }
}

__global__ void head1_k(const float* __restrict__ w, const float* __restrict__ bias) {
    __shared__ float sp[1024];
    int g = blockIdx.x * 256 + threadIdx.x;
    int b = g >> 9, c = g & 511;
    for (int i = threadIdx.x; i < 1024; i += 256)
        sp[i] = fmaf(g_s5[i], __int_as_float(g_P1raw[(b << 10) + i]), g_h5[i]);
    __syncthreads();
    float a = bias[c];
#pragma unroll 8
    for (int r = 0; r < 1024; r++) a = fmaf(sp[r], w[(size_t)r * 512 + c], a);
    g_Zm1[g] = fmaxf(a, 0.f);
}

__global__ void stats16_k(const float* __restrict__ Z, int C,
                          const float* __restrict__ g, const float* __restrict__ be,
                          float* __restrict__ scale, float* __restrict__ shift) {
    int c = blockIdx.x * blockDim.x + threadIdx.x;
    if (c >= C) return;
    float s = 0.f, q = 0.f;
    for (int b = 0; b < 16; b++) { float v = Z[b * C + c]; s += v; q += v * v; }
    float mean = s * 0.0625f;
    float var = q * 0.0625f - mean * mean;
    float sc = g[c] * rsqrtf(var + EPSB);
    scale[c] = sc;
    shift[c] = be[c] - mean * sc;
}

__global__ void head2_k(const float* __restrict__ w) {
    int g = blockIdx.x * 256 + threadIdx.x;
    int b = g >> 8, c = g & 255;
    float a = g_ebm2[c];
    const float* z = g_Zm1 + b * 512;
#pragma unroll 8
    for (int r = 0; r < 512; r++) a = fmaf(z[r] * g_s6[r], w[(size_t)r * 256 + c], a);
    g_Zm2[g] = fmaxf(a, 0.f);
}

__global__ void head3_k(const float* __restrict__ w, float* __restrict__ out) {
    int t = threadIdx.x;
    if (t >= 32) return;
    int b = t >> 1, n = t & 1;
    float a = g_ebm3[n];
    const float* z = g_Zm2 + b * 256;
#pragma unroll 8
    for (int r = 0; r < 256; r++) a = fmaf(z[r] * g_s7[r], w[r * 2 + n], a);
    out[b * 2 + n] = a;
}

static void* symaddr(const void* s) {
    void* p = nullptr;
    cudaGetSymbolAddress(&p, s);
    return p;
}

extern "C" void kernel_launch(void* const* d_in, const int* in_sizes, int n_in,
                              void* d_out, int out_size) {
    const float* pos = (const float*)d_in[0];
    const float* c1w0 = (const float*)d_in[1];
    const float* c1b0 = (const float*)d_in[2];
    const float* c1g0 = (const float*)d_in[3];
    const float* c1e0 = (const float*)d_in[4];
    const float* c1w1 = (const float*)d_in[5];
    const float* c1b1 = (const float*)d_in[6];
    const float* c1g1 = (const float*)d_in[7];
    const float* c1e1 = (const float*)d_in[8];
    const float* c1w2 = (const float*)d_in[9];
    const float* c1b2 = (const float*)d_in[10];
    const float* c1g2 = (const float*)d_in[11];
    const float* c1e2 = (const float*)d_in[12];
    const float* c2w = (const float*)d_in[13];
    const float* c2b = (const float*)d_in[14];
    const float* c2g = (const float*)d_in[15];
    const float* c2e = (const float*)d_in[16];
    const float* l1w = (const float*)d_in[17];
    const float* l1b = (const float*)d_in[18];
    const float* l1g = (const float*)d_in[19];
    const float* l1e = (const float*)d_in[20];
    const float* m1w = (const float*)d_in[21];
    const float* m1b = (const float*)d_in[22];
    const float* m1g = (const float*)d_in[23];
    const float* m1e = (const float*)d_in[24];
    const float* m2w = (const float*)d_in[25];
    const float* m2b = (const float*)d_in[26];
    const float* m2g = (const float*)d_in[27];
    const float* m2e = (const float*)d_in[28];
    const float* m3w = (const float*)d_in[29];
    const float* m3b = (const float*)d_in[30];

    float* Z1 = (float*)symaddr(g_Z1);
    float* Z2 = (float*)symaddr(g_Z2);
    float* Z4 = (float*)symaddr(g_Z4);
    float* X = (float*)symaddr(g_X12);
    int* I1 = (int*)symaddr(g_idx1);
    int* I2 = (int*)symaddr(g_idx2);
    float* part = (float*)symaddr(g_part);
    float* partL = (float*)symaddr(g_partL);
    float* s1 = (float*)symaddr(g_s1);
    float* h1 = (float*)symaddr(g_h1);
    float* s2 = (float*)symaddr(g_s2);
    float* h2 = (float*)symaddr(g_h2);
    float* s3 = (float*)symaddr(g_s3);
    float* h3 = (float*)symaddr(g_h3);
    float* s4 = (float*)symaddr(g_s4);
    float* h4 = (float*)symaddr(g_h4);
    float* s5 = (float*)symaddr(g_s5);
    float* h5 = (float*)symaddr(g_h5);
    float* s6 = (float*)symaddr(g_s6);
    float* h6 = (float*)symaddr(g_h6);
    float* s7 = (float*)symaddr(g_s7);
    float* h7 = (float*)symaddr(g_h7);
    float* eb2 = (float*)symaddr(g_eb2);
    float* eb3 = (float*)symaddr(g_eb3);
    float* ebm2 = (float*)symaddr(g_ebm2);
    float* ebm3 = (float*)symaddr(g_ebm3);
    float* Zm1 = (float*)symaddr(g_Zm1);
    float* Zm2 = (float*)symaddr(g_Zm2);

    cudaFuncSetAttribute(mma_ec2_k, cudaFuncAttributeMaxDynamicSharedMemorySize, 70656);

    wsplit_k<<<768, 256>>>(l1w);
    wsplit2_k<<<64, 256>>>(c2w);
    knn3_k<<<128, 256>>>(pos, I1);
    ec1_l0_k<<<NEDG * 4 / 256, 256>>>(pos, I1, c1w0, c1b0, Z1);
    finalize_k<<<8, 256>>>(64, (float)NEDG, 2560, c1g0, c1e0, part, s1, h1);
    foldbias_k<<<1, 64>>>(64, 64, c1w1, c1b1, h1, eb2);
    ec_mid_k<<<NEDG / 64, 256>>>(Z1, c1w1, s1, eb2, Z2);
    finalize_k<<<8, 256>>>(64, (float)NEDG, 2560, c1g1, c1e1, part, s2, h2);
    foldbias_k<<<1, 64>>>(64, 64, c1w2, c1b2, h2, eb3);
    ec_mid_k<<<NEDG / 64, 256>>>(Z2, c1w2, s2, eb3, Z1);
    finalize_k<<<8, 256>>>(64, (float)NEDG, 2560, c1g2, c1e2, part, s3, h3);
    maxE_k<<<NPTS * 16 / 256, 256>>>(Z1, 64, s3, h3, X, 0, 1);

    knn64_k<<<128, 256>>>(I2);
    mma_ec2_k<<<NEDG / 128, 256, 70656>>>(X, I2, c2b, Z4);
    finalize_k<<<16, 256>>>(128, (float)NEDG, 1280, c2g, c2e, part, s4, h4);
    maxE_k<<<NPTS * 32 / 256, 256>>>(Z4, 128, s4, h4, X, 64, 0);

    initP1_k<<<64, 256>>>();
    mma_l1_k<<<4096, 256>>>(l1b);
    finalize_k<<<128, 256>>>(1024, (float)NPTS, 256, l1g, l1e, partL, s5, h5);

    head1_k<<<32, 256>>>(m1w, m1b);
    stats16_k<<<2, 256>>>(Zm1, 512, m1g, m1e, s6, h6);
    foldbias_k<<<1, 256>>>(512, 256, m2w, m2b, h6, ebm2);
    head2_k<<<16, 256>>>(m2w);
    stats16_k<<<1, 256>>>(Zm2, 256, m2g, m2e, s7, h7);
    foldbias_k<<<1, 32>>>(256, 2, m3w, m3b, h7, ebm3);
    head3_k<<<1, 32>>>(m3w, (float*)d_out);
}

// round 12
// speedup vs baseline: 1.3999x; 1.0636x over previous
#include <cuda_runtime.h>
#include <cuda_bf16.h>
#include <mma.h>
#include <cstddef>

using namespace nvcuda;

#define EPSB 1e-5f
constexpr int Pk = 2048;
constexpr int KN = 5;
constexpr int NPTS = 16 * Pk;
constexpr int NEDG = NPTS * KN;
using u64 = unsigned long long;

__device__ float g_Z1[(size_t)NEDG * 64];
__device__ float g_Z2[(size_t)NEDG * 64];
__device__ float g_Z4[(size_t)NEDG * 128];
__device__ float g_X12[(size_t)NPTS * 192];
__device__ float g_sq[NPTS];
__device__ int   g_idx1[NEDG];
__device__ int   g_idx2[NEDG];
__device__ float g_part[(size_t)2560 * 2 * 128];
__device__ float g_partL[(size_t)256 * 2 * 1024];
__device__ float g_s1[64], g_h1[64], g_s2[64], g_h2[64], g_s3[64], g_h3[64];
__device__ float g_s4[128], g_h4[128], g_s5[1024], g_h5[1024];
__device__ float g_s6[512], g_h6[512], g_s7[256], g_h7[256];
__device__ float g_eb2[64], g_eb3[64], g_ebm2[256], g_ebm3[2];
__device__ int   g_P1raw[16 * 1024];
__device__ float g_Zm1[16 * 512];
__device__ float g_Zm2[16 * 256];
__device__ __align__(256) __nv_bfloat16 g_Xhi[(size_t)NPTS * 192];
__device__ __align__(256) __nv_bfloat16 g_Xlo[(size_t)NPTS * 192];
__device__ __align__(256) __nv_bfloat16 g_Whi[1024 * 192];
__device__ __align__(256) __nv_bfloat16 g_Wlo[1024 * 192];
__device__ __align__(256) __nv_bfloat16 g_W2hi[128 * 128];
__device__ __align__(256) __nv_bfloat16 g_W2lo[128 * 128];

__device__ __forceinline__ u64 pack2(float lo, float hi) {
    u64 r;
    asm("mov.b64 %0, {%1, %2};" : "=l"(r) : "f"(lo), "f"(hi));
    return r;
}
__device__ __forceinline__ float2 unpack2(u64 v) {
    float2 r;
    asm("mov.b64 {%0, %1}, %2;" : "=f"(r.x), "=f"(r.y) : "l"(v));
    return r;
}
__device__ __forceinline__ void fma2(u64& d, u64 a, u64 b) {
    asm("fma.rn.f32x2 %0, %1, %2, %0;" : "+l"(d) : "l"(a), "l"(b));
}

__device__ __forceinline__ void knn_insert(float d, int j, float bd[KN], int bi[KN]) {
#pragma unroll
    for (int k = 0; k < KN; k++) {
        if (d < bd[k]) {
            float td = bd[k]; int ti = bi[k];
            bd[k] = d; bi[k] = j;
            d = td; j = ti;
        }
    }
}

__global__ void knn3_k(const float* __restrict__ pos, int* __restrict__ idx) {
    __shared__ float sx[Pk], sy[Pk], sz[Pk], sn[Pk];
    int b = blockIdx.x >> 3;
    int p0 = (blockIdx.x & 7) << 8;
    const float* base = pos + (size_t)b * Pk * 3;
    for (int j = threadIdx.x; j < Pk; j += 256) {
        float x = base[3 * j], y = base[3 * j + 1], z = base[3 * j + 2];
        sx[j] = x; sy[j] = y; sz[j] = z;
        sn[j] = x * x + y * y + z * z;
    }
    __syncthreads();
    int p = p0 + threadIdx.x;
    float x = sx[p], y = sy[p], z = sz[p], sq = sn[p];
    float bd[KN]; int bi[KN];
#pragma unroll
    for (int k = 0; k < KN; k++) { bd[k] = 1e30f; bi[k] = 0; }
    for (int j = 0; j < Pk; j++) {
        float d = sq + sn[j] - 2.f * (x * sx[j] + y * sy[j] + z * sz[j]);
        if (d < bd[KN - 1]) knn_insert(d, j, bd, bi);
    }
    int o = (b * Pk + p) * KN;
#pragma unroll
    for (int k = 0; k < KN; k++) idx[o + k] = bi[k];
}

// edges(6)->64, ReLU, fused stats partials (64 edges/block), padded staging
__global__ void ec1_l0_k(const float* __restrict__ pos, const int* __restrict__ idx,
                         const float* __restrict__ w, const float* __restrict__ bias,
                         float* __restrict__ Z) {
    __shared__ float sw[384], sb[64];
    __shared__ float red[64 * 68];
    if (threadIdx.x < 64) sb[threadIdx.x] = bias[threadIdx.x];
    for (int i = threadIdx.x; i < 384; i += 256) sw[i] = w[i];
    __syncthreads();
    int g = blockIdx.x * 256 + threadIdx.x;
    int e = g >> 2, q = g & 3;
    int lr = threadIdx.x >> 2;
    int pt = e / KN, b = pt >> 11, j = idx[e];
    const float* pi = pos + (size_t)pt * 3;
    const float* pj = pos + ((size_t)(b << 11) + j) * 3;
    float e0 = pi[0], e1 = pi[1], e2 = pi[2];
    float e3 = pj[0] - e0, e4 = pj[1] - e1, e5 = pj[2] - e2;
    int c0 = q * 16;
    float out[16];
#pragma unroll
    for (int c = 0; c < 16; c++) {
        int cc = c0 + c;
        float a = sb[cc];
        a = fmaf(e0, sw[cc], a);
        a = fmaf(e1, sw[64 + cc], a);
        a = fmaf(e2, sw[128 + cc], a);
        a = fmaf(e3, sw[192 + cc], a);
        a = fmaf(e4, sw[256 + cc], a);
        a = fmaf(e5, sw[320 + cc], a);
        out[c] = fmaxf(a, 0.f);
        red[lr * 68 + cc] = out[c];
    }
    float4* dst = reinterpret_cast<float4*>(Z + (size_t)e * 64 + c0);
#pragma unroll
    for (int v = 0; v < 4; v++)
        dst[v] = make_float4(out[v * 4], out[v * 4 + 1], out[v * 4 + 2], out[v * 4 + 3]);
    __syncthreads();
    if (threadIdx.x < 64) {
        float s = 0.f, qq = 0.f;
        for (int r = 0; r < 64; r++) {
            float v = red[r * 68 + threadIdx.x];
            s += v; qq += v * v;
        }
        g_part[((size_t)blockIdx.x * 2 + 0) * 64 + threadIdx.x] = s;
        g_part[((size_t)blockIdx.x * 2 + 1) * 64 + threadIdx.x] = qq;
    }
}

__global__ void finalize_k(int C, float n, int nblk, const float* __restrict__ g,
                           const float* __restrict__ be, const float* __restrict__ part,
                           float* __restrict__ scale, float* __restrict__ shift) {
    int warp = (blockIdx.x * blockDim.x + threadIdx.x) >> 5;
    int lane = threadIdx.x & 31;
    if (warp >= C) return;
    float s = 0.f, q = 0.f;
    for (int b = lane; b < nblk; b += 32) {
        s += part[((size_t)b * 2 + 0) * C + warp];
        q += part[((size_t)b * 2 + 1) * C + warp];
    }
#pragma unroll
    for (int o = 16; o; o >>= 1) {
        s += __shfl_xor_sync(0xffffffffu, s, o);
        q += __shfl_xor_sync(0xffffffffu, q, o);
    }
    if (lane == 0) {
        float mean = s / n;
        float var = q / n - mean * mean;
        float sc = g[warp] * rsqrtf(var + EPSB);
        scale[warp] = sc;
        shift[warp] = be[warp] - mean * sc;
    }
}

__global__ void foldbias_k(int Cin, int Cout, const float* __restrict__ w,
                           const float* __restrict__ bias, const float* __restrict__ shift,
                           float* __restrict__ eb) {
    int c = blockIdx.x * blockDim.x + threadIdx.x;
    if (c >= Cout) return;
    float a = bias[c];
    for (int r = 0; r < Cin; r++) a = fmaf(shift[r], w[(size_t)r * Cout + c], a);
    eb[c] = a;
}

// WMMA 64->64 GEMM (BN fold via W scaling), ReLU, fused stats (128 edges/block)
constexpr int MST = 40;
__global__ void __launch_bounds__(256) mma_mid_k(const float* __restrict__ Zin,
                                                 const float* __restrict__ w,
                                                 const float* __restrict__ scaleIn,
                                                 const float* __restrict__ eb,
                                                 float* __restrict__ Zout) {
    extern __shared__ char dynb[];
    __nv_bfloat16* Ah = reinterpret_cast<__nv_bfloat16*>(dynb);
    __nv_bfloat16* Al = Ah + 128 * MST;
    __nv_bfloat16* Wh = Al + 128 * MST;
    __nv_bfloat16* Wl = Wh + 64 * MST;
    float* out = reinterpret_cast<float*>(dynb);
    int tid = threadIdx.x, wrp = tid >> 5;
    int row0 = blockIdx.x * 128;
    int wm = wrp >> 1, wn = wrp & 1;
    wmma::fragment<wmma::accumulator, 16, 16, 16, float> acc[2][2];
#pragma unroll
    for (int mm = 0; mm < 2; mm++)
#pragma unroll
        for (int nn = 0; nn < 2; nn++)
            wmma::fill_fragment(acc[mm][nn], 0.f);

    for (int kc = 0; kc < 2; kc++) {
        __syncthreads();
        for (int i = tid; i < 1024; i += 256) {
            int r = i >> 3, c4 = (i & 7) * 4;
            float4 v = *reinterpret_cast<const float4*>(
                &Zin[(size_t)(row0 + r) * 64 + kc * 32 + c4]);
            __nv_bfloat16 h0 = __float2bfloat16(v.x), h1 = __float2bfloat16(v.y);
            __nv_bfloat16 h2 = __float2bfloat16(v.z), h3 = __float2bfloat16(v.w);
            Ah[r * MST + c4 + 0] = h0;
            Ah[r * MST + c4 + 1] = h1;
            Ah[r * MST + c4 + 2] = h2;
            Ah[r * MST + c4 + 3] = h3;
            Al[r * MST + c4 + 0] = __float2bfloat16(v.x - __bfloat162float(h0));
            Al[r * MST + c4 + 1] = __float2bfloat16(v.y - __bfloat162float(h1));
            Al[r * MST + c4 + 2] = __float2bfloat16(v.z - __bfloat162float(h2));
            Al[r * MST + c4 + 3] = __float2bfloat16(v.w - __bfloat162float(h3));
        }
        for (int i = tid; i < 2048; i += 256) {
            int k = i >> 6, c = i & 63;
            int kk = kc * 32 + k;
            float v = scaleIn[kk] * w[(size_t)kk * 64 + c];
            __nv_bfloat16 h = __float2bfloat16(v);
            Wh[c * MST + k] = h;
            Wl[c * MST + k] = __float2bfloat16(v - __bfloat162float(h));
        }
        __syncthreads();
#pragma unroll
        for (int kk = 0; kk < 32; kk += 16) {
            wmma::fragment<wmma::matrix_a, 16, 16, 16, __nv_bfloat16, wmma::row_major> ah[2], al[2];
            wmma::fragment<wmma::matrix_b, 16, 16, 16, __nv_bfloat16, wmma::col_major> bh[2], bl[2];
#pragma unroll
            for (int mm = 0; mm < 2; mm++) {
                int rb = wm * 32 + mm * 16;
                wmma::load_matrix_sync(ah[mm], &Ah[rb * MST + kk], MST);
                wmma::load_matrix_sync(al[mm], &Al[rb * MST + kk], MST);
            }
#pragma unroll
            for (int nn = 0; nn < 2; nn++) {
                int nb = wn * 32 + nn * 16;
                wmma::load_matrix_sync(bh[nn], &Wh[nb * MST + kk], MST);
                wmma::load_matrix_sync(bl[nn], &Wl[nb * MST + kk], MST);
            }
#pragma unroll
            for (int mm = 0; mm < 2; mm++)
#pragma unroll
                for (int nn = 0; nn < 2; nn++) {
                    wmma::mma_sync(acc[mm][nn], ah[mm], bh[nn], acc[mm][nn]);
                    wmma::mma_sync(acc[mm][nn], ah[mm], bl[nn], acc[mm][nn]);
                    wmma::mma_sync(acc[mm][nn], al[mm], bh[nn], acc[mm][nn]);
                }
        }
    }
    __syncthreads();
#pragma unroll
    for (int mm = 0; mm < 2; mm++)
#pragma unroll
        for (int nn = 0; nn < 2; nn++) {
            int r = wm * 32 + mm * 16;
            int c = wn * 32 + nn * 16;
            wmma::store_matrix_sync(&out[r * 68 + c], acc[mm][nn], 68, wmma::mem_row_major);
        }
    __syncthreads();
    for (int i = tid; i < 2048; i += 256) {
        int r = i >> 4, c4 = (i & 15) * 4;
        float4 v = *reinterpret_cast<float4*>(&out[r * 68 + c4]);
        v.x = fmaxf(v.x + eb[c4 + 0], 0.f);
        v.y = fmaxf(v.y + eb[c4 + 1], 0.f);
        v.z = fmaxf(v.z + eb[c4 + 2], 0.f);
        v.w = fmaxf(v.w + eb[c4 + 3], 0.f);
        *reinterpret_cast<float4*>(&out[r * 68 + c4]) = v;
        *reinterpret_cast<float4*>(&Zout[(size_t)(row0 + r) * 64 + c4]) = v;
    }
    __syncthreads();
    if (tid < 64) {
        float s = 0.f, qq = 0.f;
        for (int r = 0; r < 128; r++) {
            float v = out[r * 68 + tid];
            s += v; qq += v * v;
        }
        g_part[((size_t)blockIdx.x * 2 + 0) * 64 + tid] = s;
        g_part[((size_t)blockIdx.x * 2 + 1) * 64 + tid] = qq;
    }
}

__global__ void maxE_k(const float* __restrict__ Z, int C,
                       const float* __restrict__ scale, const float* __restrict__ shift,
                       float* __restrict__ X, int colOff, int doSq) {
    int g = blockIdx.x * 256 + threadIdx.x;
    int per = C >> 2;
    int pt = g / per;
    int c4 = (g % per) * 4;
    float4 m = make_float4(-1e30f, -1e30f, -1e30f, -1e30f);
#pragma unroll
    for (int k = 0; k < KN; k++) {
        float4 v = *reinterpret_cast<const float4*>(&Z[(size_t)(pt * KN + k) * C + c4]);
        m.x = fmaxf(m.x, v.x); m.y = fmaxf(m.y, v.y);
        m.z = fmaxf(m.z, v.z); m.w = fmaxf(m.w, v.w);
    }
    float4 o;
    o.x = fmaf(scale[c4 + 0], m.x, shift[c4 + 0]);
    o.y = fmaf(scale[c4 + 1], m.y, shift[c4 + 1]);
    o.z = fmaf(scale[c4 + 2], m.z, shift[c4 + 2]);
    o.w = fmaf(scale[c4 + 3], m.w, shift[c4 + 3]);
    *reinterpret_cast<float4*>(&X[(size_t)pt * 192 + colOff + c4]) = o;
    __nv_bfloat16 h0 = __float2bfloat16(o.x), h1 = __float2bfloat16(o.y);
    __nv_bfloat16 h2 = __float2bfloat16(o.z), h3 = __float2bfloat16(o.w);
    size_t bo = (size_t)pt * 192 + colOff + c4;
    __nv_bfloat162* dh = reinterpret_cast<__nv_bfloat162*>(&g_Xhi[bo]);
    __nv_bfloat162* dl = reinterpret_cast<__nv_bfloat162*>(&g_Xlo[bo]);
    dh[0] = __halves2bfloat162(h0, h1);
    dh[1] = __halves2bfloat162(h2, h3);
    dl[0] = __halves2bfloat162(__float2bfloat16(o.x - __bfloat162float(h0)),
                               __float2bfloat16(o.y - __bfloat162float(h1)));
    dl[1] = __halves2bfloat162(__float2bfloat16(o.z - __bfloat162float(h2)),
                               __float2bfloat16(o.w - __bfloat162float(h3)));
    if (doSq) {
        float s = o.x * o.x + o.y * o.y + o.z * o.z + o.w * o.w;
#pragma unroll
        for (int off = 8; off; off >>= 1)
            s += __shfl_down_sync(0xffffffffu, s, off, 16);
        if ((threadIdx.x & 15) == 0) g_sq[pt] = s;
    }
}

__global__ void __launch_bounds__(256) knn64_k(int* __restrict__ idx) {
    __shared__ __align__(16) float4 sq4[128 * 16];
    __shared__ float ssn[128];
    int b = blockIdx.x >> 3;
    int p = ((blockIdx.x & 7) << 8) + threadIdx.x;
    int pt = (b << 11) + p;
    ulonglong2 xpv[16];
#pragma unroll
    for (int i = 0; i < 16; i++)
        xpv[i] = *reinterpret_cast<const ulonglong2*>(&g_X12[(size_t)pt * 192 + i * 4]);
    float sqp = g_sq[pt];
    float bd[KN]; int bi[KN];
#pragma unroll
    for (int k = 0; k < KN; k++) { bd[k] = 1e30f; bi[k] = 0; }
    for (int q0 = 0; q0 < Pk; q0 += 128) {
        __syncthreads();
        for (int t = threadIdx.x; t < 2048; t += 256) {
            int qr = t >> 4, d4 = t & 15;
            sq4[qr * 16 + d4] = *reinterpret_cast<const float4*>(
                &g_X12[(size_t)((b << 11) + q0 + qr) * 192 + d4 * 4]);
        }
        if (threadIdx.x < 128) ssn[threadIdx.x] = g_sq[(b << 11) + q0 + threadIdx.x];
        __syncthreads();
        for (int qr = 0; qr < 128; qr++) {
            const ulonglong2* qv = reinterpret_cast<const ulonglong2*>(&sq4[qr * 16]);
            u64 dc[4] = {};
#pragma unroll
            for (int i = 0; i < 16; i += 2) {
                ulonglong2 qa = qv[i], qb = qv[i + 1];
                fma2(dc[0], xpv[i].x, qa.x);
                fma2(dc[1], xpv[i].y, qa.y);
                fma2(dc[2], xpv[i + 1].x, qb.x);
                fma2(dc[3], xpv[i + 1].y, qb.y);
            }
            float2 f0 = unpack2(dc[0]), f1 = unpack2(dc[1]);
            float2 f2 = unpack2(dc[2]), f3 = unpack2(dc[3]);
            float dot = ((f0.x + f0.y) + (f1.x + f1.y)) + ((f2.x + f2.y) + (f3.x + f3.y));
            float d = sqp + ssn[qr] - 2.f * dot;
            if (d < bd[KN - 1]) knn_insert(d, q0 + qr, bd, bi);
        }
    }
    int o = pt * KN;
#pragma unroll
    for (int k = 0; k < KN; k++) idx[o + k] = bi[k];
}

__global__ void wsplit2_k(const float* __restrict__ w) {
    int i = blockIdx.x * 256 + threadIdx.x;
    if (i >= 128 * 128) return;
    int r = i >> 7, c = i & 127;
    float v = w[i];
    __nv_bfloat16 h = __float2bfloat16(v);
    g_W2hi[c * 128 + r] = h;
    g_W2lo[c * 128 + r] = __float2bfloat16(v - __bfloat162float(h));
}

// WMMA EdgeConv2: gather(128) + GEMM 128x128, ReLU, stats (128 edges/block)
constexpr int EST = 40;
__global__ void __launch_bounds__(256) mma_ec2_k(const float* __restrict__ X,
                                                 const int* __restrict__ idx,
                                                 const float* __restrict__ bias,
                                                 float* __restrict__ Z) {
    extern __shared__ char dynbuf[];
    __nv_bfloat16* Ah = reinterpret_cast<__nv_bfloat16*>(dynbuf);
    __nv_bfloat16* Al = Ah + 128 * EST;
    __nv_bfloat16* Wh = Al + 128 * EST;
    __nv_bfloat16* Wl = Wh + 128 * EST;
    float* out = reinterpret_cast<float*>(dynbuf);
    int tid = threadIdx.x, wrp = tid >> 5;
    int e0 = blockIdx.x * 128;
    int wm = wrp >> 1, wn = wrp & 1;
    wmma::fragment<wmma::accumulator, 16, 16, 16, float> acc[2][4];
#pragma unroll
    for (int mm = 0; mm < 2; mm++)
#pragma unroll
        for (int nn = 0; nn < 4; nn++)
            wmma::fill_fragment(acc[mm][nn], 0.f);

    for (int kc = 0; kc < 4; kc++) {
        __syncthreads();
        for (int i = tid; i < 4096; i += 256) {
            int r = i >> 5, cq = i & 31;
            int col = kc * 32 + cq;
            int e = e0 + r;
            int pt = e / KN, bb = pt >> 11, j = idx[e];
            const float* xi = X + (size_t)pt * 192;
            const float* xj = X + ((size_t)(bb << 11) + j) * 192;
            float v = (col < 64) ? xi[col] : (xj[col - 64] - xi[col - 64]);
            __nv_bfloat16 h = __float2bfloat16(v);
            Ah[r * EST + cq] = h;
            Al[r * EST + cq] = __float2bfloat16(v - __bfloat162float(h));
        }
        if (tid < 256) {
            for (int i = tid; i < 512; i += 256) {
                int r = i >> 2, cq = (i & 3) * 8;
                size_t gg = (size_t)r * 128 + kc * 32 + cq;
                *reinterpret_cast<uint4*>(&Wh[r * EST + cq]) =
                    *reinterpret_cast<const uint4*>(&g_W2hi[gg]);
                *reinterpret_cast<uint4*>(&Wl[r * EST + cq]) =
                    *reinterpret_cast<const uint4*>(&g_W2lo[gg]);
            }
        }
        __syncthreads();
#pragma unroll
        for (int kk = 0; kk < 32; kk += 16) {
            wmma::fragment<wmma::matrix_a, 16, 16, 16, __nv_bfloat16, wmma::row_major> ah[2], al[2];
            wmma::fragment<wmma::matrix_b, 16, 16, 16, __nv_bfloat16, wmma::col_major> bh[4], bl[4];
#pragma unroll
            for (int mm = 0; mm < 2; mm++) {
                int rb = wm * 32 + mm * 16;
                wmma::load_matrix_sync(ah[mm], &Ah[rb * EST + kk], EST);
                wmma::load_matrix_sync(al[mm], &Al[rb * EST + kk], EST);
            }
#pragma unroll
            for (int nn = 0; nn < 4; nn++) {
                int nb = wn * 64 + nn * 16;
                wmma::load_matrix_sync(bh[nn], &Wh[nb * EST + kk], EST);
                wmma::load_matrix_sync(bl[nn], &Wl[nb * EST + kk], EST);
            }
#pragma unroll
            for (int mm = 0; mm < 2; mm++)
#pragma unroll
                for (int nn = 0; nn < 4; nn++) {
                    wmma::mma_sync(acc[mm][nn], ah[mm], bh[nn], acc[mm][nn]);
                    wmma::mma_sync(acc[mm][nn], ah[mm], bl[nn], acc[mm][nn]);
                    wmma::mma_sync(acc[mm][nn], al[mm], bh[nn], acc[mm][nn]);
                }
        }
    }
    __syncthreads();
#pragma unroll
    for (int mm = 0; mm < 2; mm++)
#pragma unroll
        for (int nn = 0; nn < 4; nn++) {
            int r = wm * 32 + mm * 16;
            int c = wn * 64 + nn * 16;
            wmma::store_matrix_sync(&out[r * 132 + c], acc[mm][nn], 132, wmma::mem_row_major);
        }
    __syncthreads();
    for (int i = tid; i < 4096; i += 256) {
        int r = i >> 5, c4 = (i & 31) * 4;
        float4 v = *reinterpret_cast<float4*>(&out[r * 132 + c4]);
        v.x = fmaxf(v.x + bias[c4 + 0], 0.f);
        v.y = fmaxf(v.y + bias[c4 + 1], 0.f);
        v.z = fmaxf(v.z + bias[c4 + 2], 0.f);
        v.w = fmaxf(v.w + bias[c4 + 3], 0.f);
        *reinterpret_cast<float4*>(&out[r * 132 + c4]) = v;
        *reinterpret_cast<float4*>(&Z[(size_t)(e0 + r) * 128 + c4]) = v;
    }
    __syncthreads();
    if (tid < 128) {
        float s = 0.f, qq = 0.f;
        for (int r = 0; r < 128; r++) {
            float v = out[r * 132 + tid];
            s += v; qq += v * v;
        }
        g_part[((size_t)blockIdx.x * 2 + 0) * 128 + tid] = s;
        g_part[((size_t)blockIdx.x * 2 + 1) * 128 + tid] = qq;
    }
}

__global__ void initP1_k() {
    int g = blockIdx.x * 256 + threadIdx.x;
    if (g < 16 * 1024) g_P1raw[g] = 0;
}

__global__ void wsplit_k(const float* __restrict__ w) {
    int i = blockIdx.x * 256 + threadIdx.x;
    int r = i >> 10, c = i & 1023;
    float v = w[i];
    __nv_bfloat16 h = __float2bfloat16(v);
    g_Whi[c * 192 + r] = h;
    g_Wlo[c * 192 + r] = __float2bfloat16(v - __bfloat162float(h));
}

constexpr int LSTR = 40;
__global__ void __launch_bounds__(256) mma_l1_k(const float* __restrict__ bias) {
    __shared__ __align__(16) char smbuf[128 * 68 * 4];
    __nv_bfloat16* Ah = reinterpret_cast<__nv_bfloat16*>(smbuf);
    __nv_bfloat16* Al = Ah + 128 * LSTR;
    __nv_bfloat16* Wh = Al + 128 * LSTR;
    __nv_bfloat16* Wl = Wh + 64 * LSTR;
    float* out = reinterpret_cast<float*>(smbuf);
    int tid = threadIdx.x, wrp = tid >> 5;
    int mt = blockIdx.x >> 4, nt = blockIdx.x & 15;
    int row0 = mt << 7, col0 = nt << 6;
    int wm = wrp >> 1, wn = wrp & 1;
    wmma::fragment<wmma::accumulator, 16, 16, 16, float> acc[2][2];
#pragma unroll
    for (int mm = 0; mm < 2; mm++)
#pragma unroll
        for (int nn = 0; nn < 2; nn++)
            wmma::fill_fragment(acc[mm][nn], 0.f);

    for (int kc = 0; kc < 6; kc++) {
        __syncthreads();
        for (int i = tid; i < 512; i += 256) {
            int r = i >> 2, cq = (i & 3) * 8;
            size_t g = (size_t)(row0 + r) * 192 + kc * 32 + cq;
            *reinterpret_cast<uint4*>(&Ah[r * LSTR + cq]) =
                *reinterpret_cast<const uint4*>(&g_Xhi[g]);
            *reinterpret_cast<uint4*>(&Al[r * LSTR + cq]) =
                *reinterpret_cast<const uint4*>(&g_Xlo[g]);
        }
        if (tid < 256) {
            int r = tid >> 2, cq = (tid & 3) * 8;
            size_t g = (size_t)(col0 + r) * 192 + kc * 32 + cq;
            *reinterpret_cast<uint4*>(&Wh[r * LSTR + cq]) =
                *reinterpret_cast<const uint4*>(&g_Whi[g]);
            *reinterpret_cast<uint4*>(&Wl[r * LSTR + cq]) =
                *reinterpret_cast<const uint4*>(&g_Wlo[g]);
        }
        __syncthreads();
#pragma unroll
        for (int kk = 0; kk < 32; kk += 16) {
            wmma::fragment<wmma::matrix_a, 16, 16, 16, __nv_bfloat16, wmma::row_major> ah[2], al[2];
            wmma::fragment<wmma::matrix_b, 16, 16, 16, __nv_bfloat16, wmma::col_major> bh[2], bl[2];
#pragma unroll
            for (int mm = 0; mm < 2; mm++) {
                int rb = wm * 32 + mm * 16;
                wmma::load_matrix_sync(ah[mm], &Ah[rb * LSTR + kk], LSTR);
                wmma::load_matrix_sync(al[mm], &Al[rb * LSTR + kk], LSTR);
            }
#pragma unroll
            for (int nn = 0; nn < 2; nn++) {
                int nb = wn * 32 + nn * 16;
                wmma::load_matrix_sync(bh[nn], &Wh[nb * LSTR + kk], LSTR);
                wmma::load_matrix_sync(bl[nn], &Wl[nb * LSTR + kk], LSTR);
            }
#pragma unroll
            for (int mm = 0; mm < 2; mm++)
#pragma unroll
                for (int nn = 0; nn < 2; nn++) {
                    wmma::mma_sync(acc[mm][nn], ah[mm], bh[nn], acc[mm][nn]);
                    wmma::mma_sync(acc[mm][nn], ah[mm], bl[nn], acc[mm][nn]);
                    wmma::mma_sync(acc[mm][nn], al[mm], bh[nn], acc[mm][nn]);
                }
        }
    }
    __syncthreads();
#pragma unroll
    for (int mm = 0; mm < 2; mm++)
#pragma unroll
        for (int nn = 0; nn < 2; nn++) {
            int r = wm * 32 + mm * 16;
            int c = wn * 32 + nn * 16;
            wmma::store_matrix_sync(&out[r * 68 + c], acc[mm][nn], 68, wmma::mem_row_major);
        }
    __syncthreads();
    for (int i = tid; i < 8192; i += 256) {
        int r = i >> 6, c = i & 63;
        out[r * 68 + c] = fmaxf(out[r * 68 + c] + bias[col0 + c], 0.f);
    }
    __syncthreads();
    if (tid < 64) {
        float s = 0.f, q = 0.f, m = 0.f;
        for (int r = 0; r < 128; r++) {
            float v = out[r * 68 + tid];
            s += v; q += v * v; m = fmaxf(m, v);
        }
        g_partL[((size_t)mt * 2 + 0) * 1024 + col0 + tid] = s;
        g_partL[((size_t)mt * 2 + 1) * 1024 + col0 + tid] = q;
        atomicMax(&g_P1raw[(row0 >> 11) * 1024 + col0 + tid], __float_as_int(m));
    }
}

__global__ void head1_k(const float* __restrict__ w, const float* __restrict__ bias) {
    __shared__ float sp[1024];
    int g = blockIdx.x * 256 + threadIdx.x;
    int b = g >> 9, c = g & 511;
    for (int i = threadIdx.x; i < 1024; i += 256)
        sp[i] = fmaf(g_s5[i], __int_as_float(g_P1raw[(b << 10) + i]), g_h5[i]);
    __syncthreads();
    float a = bias[c];
#pragma unroll 8
    for (int r = 0; r < 1024; r++) a = fmaf(sp[r], w[(size_t)r * 512 + c], a);
    g_Zm1[g] = fmaxf(a, 0.f);
}

__global__ void stats16_k(const float* __restrict__ Z, int C,
                          const float* __restrict__ g, const float* __restrict__ be,
                          float* __restrict__ scale, float* __restrict__ shift) {
    int c = blockIdx.x * blockDim.x + threadIdx.x;
    if (c >= C) return;
    float s = 0.f, q = 0.f;
    for (int b = 0; b < 16; b++) { float v = Z[b * C + c]; s += v; q += v * v; }
    float mean = s * 0.0625f;
    float var = q * 0.0625f - mean * mean;
    float sc = g[c] * rsqrtf(var + EPSB);
    scale[c] = sc;
    shift[c] = be[c] - mean * sc;
}

__global__ void head2_k(const float* __restrict__ w) {
    int g = blockIdx.x * 256 + threadIdx.x;
    int b = g >> 8, c = g & 255;
    float a = g_ebm2[c];
    const float* z = g_Zm1 + b * 512;
#pragma unroll 8
    for (int r = 0; r < 512; r++) a = fmaf(z[r] * g_s6[r], w[(size_t)r * 256 + c], a);
    g_Zm2[g] = fmaxf(a, 0.f);
}

__global__ void head3_k(const float* __restrict__ w, float* __restrict__ out) {
    int t = threadIdx.x;
    if (t >= 32) return;
    int b = t >> 1, n = t & 1;
    float a = g_ebm3[n];
    const float* z = g_Zm2 + b * 256;
#pragma unroll 8
    for (int r = 0; r < 256; r++) a = fmaf(z[r] * g_s7[r], w[r * 2 + n], a);
    out[b * 2 + n] = a;
}

static void* symaddr(const void* s) {
    void* p = nullptr;
    cudaGetSymbolAddress(&p, s);
    return p;
}

extern "C" void kernel_launch(void* const* d_in, const int* in_sizes, int n_in,
                              void* d_out, int out_size) {
    const float* pos = (const float*)d_in[0];
    const float* c1w0 = (const float*)d_in[1];
    const float* c1b0 = (const float*)d_in[2];
    const float* c1g0 = (const float*)d_in[3];
    const float* c1e0 = (const float*)d_in[4];
    const float* c1w1 = (const float*)d_in[5];
    const float* c1b1 = (const float*)d_in[6];
    const float* c1g1 = (const float*)d_in[7];
    const float* c1e1 = (const float*)d_in[8];
    const float* c1w2 = (const float*)d_in[9];
    const float* c1b2 = (const float*)d_in[10];
    const float* c1g2 = (const float*)d_in[11];
    const float* c1e2 = (const float*)d_in[12];
    const float* c2w = (const float*)d_in[13];
    const float* c2b = (const float*)d_in[14];
    const float* c2g = (const float*)d_in[15];
    const float* c2e = (const float*)d_in[16];
    const float* l1w = (const float*)d_in[17];
    const float* l1b = (const float*)d_in[18];
    const float* l1g = (const float*)d_in[19];
    const float* l1e = (const float*)d_in[20];
    const float* m1w = (const float*)d_in[21];
    const float* m1b = (const float*)d_in[22];
    const float* m1g = (const float*)d_in[23];
    const float* m1e = (const float*)d_in[24];
    const float* m2w = (const float*)d_in[25];
    const float* m2b = (const float*)d_in[26];
    const float* m2g = (const float*)d_in[27];
    const float* m2e = (const float*)d_in[28];
    const float* m3w = (const float*)d_in[29];
    const float* m3b = (const float*)d_in[30];

    float* Z1 = (float*)symaddr(g_Z1);
    float* Z2 = (float*)symaddr(g_Z2);
    float* Z4 = (float*)symaddr(g_Z4);
    float* X = (float*)symaddr(g_X12);
    int* I1 = (int*)symaddr(g_idx1);
    int* I2 = (int*)symaddr(g_idx2);
    float* part = (float*)symaddr(g_part);
    float* partL = (float*)symaddr(g_partL);
    float* s1 = (float*)symaddr(g_s1);
    float* h1 = (float*)symaddr(g_h1);
    float* s2 = (float*)symaddr(g_s2);
    float* h2 = (float*)symaddr(g_h2);
    float* s3 = (float*)symaddr(g_s3);
    float* h3 = (float*)symaddr(g_h3);
    float* s4 = (float*)symaddr(g_s4);
    float* h4 = (float*)symaddr(g_h4);
    float* s5 = (float*)symaddr(g_s5);
    float* h5 = (float*)symaddr(g_h5);
    float* s6 = (float*)symaddr(g_s6);
    float* h6 = (float*)symaddr(g_h6);
    float* s7 = (float*)symaddr(g_s7);
    float* h7 = (float*)symaddr(g_h7);
    float* eb2 = (float*)symaddr(g_eb2);
    float* eb3 = (float*)symaddr(g_eb3);
    float* ebm2 = (float*)symaddr(g_ebm2);
    float* ebm3 = (float*)symaddr(g_ebm3);
    float* Zm1 = (float*)symaddr(g_Zm1);
    float* Zm2 = (float*)symaddr(g_Zm2);

    cudaFuncSetAttribute(mma_ec2_k, cudaFuncAttributeMaxDynamicSharedMemorySize, 70656);
    cudaFuncSetAttribute(mma_mid_k, cudaFuncAttributeMaxDynamicSharedMemorySize, 35840);

    wsplit_k<<<768, 256>>>(l1w);
    wsplit2_k<<<64, 256>>>(c2w);
    knn3_k<<<128, 256>>>(pos, I1);
    ec1_l0_k<<<NEDG * 4 / 256, 256>>>(pos, I1, c1w0, c1b0, Z1);
    finalize_k<<<8, 256>>>(64, (float)NEDG, 2560, c1g0, c1e0, part, s1, h1);
    foldbias_k<<<1, 64>>>(64, 64, c1w1, c1b1, h1, eb2);
    mma_mid_k<<<NEDG / 128, 256, 35840>>>(Z1, c1w1, s1, eb2, Z2);
    finalize_k<<<8, 256>>>(64, (float)NEDG, 1280, c1g1, c1e1, part, s2, h2);
    foldbias_k<<<1, 64>>>(64, 64, c1w2, c1b2, h2, eb3);
    mma_mid_k<<<NEDG / 128, 256, 35840>>>(Z2, c1w2, s2, eb3, Z1);
    finalize_k<<<8, 256>>>(64, (float)NEDG, 1280, c1g2, c1e2, part, s3, h3);
    maxE_k<<<NPTS * 16 / 256, 256>>>(Z1, 64, s3, h3, X, 0, 1);

    knn64_k<<<128, 256>>>(I2);
    mma_ec2_k<<<NEDG / 128, 256, 70656>>>(X, I2, c2b, Z4);
    finalize_k<<<16, 256>>>(128, (float)NEDG, 1280, c2g, c2e, part, s4, h4);
    maxE_k<<<NPTS * 32 / 256, 256>>>(Z4, 128, s4, h4, X, 64, 0);

    initP1_k<<<64, 256>>>();
    mma_l1_k<<<4096, 256>>>(l1b);
    finalize_k<<<128, 256>>>(1024, (float)NPTS, 256, l1g, l1e, partL, s5, h5);

    head1_k<<<32, 256>>>(m1w, m1b);
    stats16_k<<<2, 256>>>(Zm1, 512, m1g, m1e, s6, h6);
    foldbias_k<<<1, 256>>>(512, 256, m2w, m2b, h6, ebm2);
    head2_k<<<16, 256>>>(m2w);
    stats16_k<<<1, 256>>>(Zm2, 256, m2g, m2e, s7, h7);
    foldbias_k<<<1, 32>>>(256, 2, m3w, m3b, h7, ebm3);
    head3_k<<<1, 32>>>(m3w, (float*)d_out);
}

// round 14
// speedup vs baseline: 1.4175x; 1.0126x over previous
#include <cuda_runtime.h>
#include <cuda_bf16.h>
#include <mma.h>
#include <cstddef>

using namespace nvcuda;

#define EPSB 1e-5f
constexpr int Pk = 2048;
constexpr int KN = 5;
constexpr int NPTS = 16 * Pk;
constexpr int NEDG = NPTS * KN;

__device__ float g_Z1[(size_t)NEDG * 64];
__device__ float g_Z2[(size_t)NEDG * 64];
__device__ float g_Z4[(size_t)NEDG * 128];
__device__ float g_X12[(size_t)NPTS * 192];
__device__ float g_sq[NPTS];
__device__ int   g_idx1[NEDG];
__device__ int   g_idx2[NEDG];
__device__ float g_part[(size_t)2560 * 2 * 128];
__device__ float g_partL[(size_t)256 * 2 * 1024];
__device__ float g_s1[64], g_h1[64], g_s2[64], g_h2[64], g_s3[64], g_h3[64];
__device__ float g_s4[128], g_h4[128], g_s5[1024], g_h5[1024];
__device__ float g_s6[512], g_h6[512], g_s7[256], g_h7[256];
__device__ float g_eb2[64], g_eb3[64], g_ebm2[256], g_ebm3[2];
__device__ int   g_P1raw[16 * 1024];
__device__ float g_Zm1[16 * 512];
__device__ float g_Zm2[16 * 256];
__device__ __align__(256) __nv_bfloat16 g_Xhi[(size_t)NPTS * 192];
__device__ __align__(256) __nv_bfloat16 g_Xlo[(size_t)NPTS * 192];
__device__ __align__(256) __nv_bfloat16 g_Whi[1024 * 192];
__device__ __align__(256) __nv_bfloat16 g_Wlo[1024 * 192];
__device__ __align__(256) __nv_bfloat16 g_W2hi[128 * 128];
__device__ __align__(256) __nv_bfloat16 g_W2lo[128 * 128];

__device__ __forceinline__ void knn_insert(float d, int j, float bd[KN], int bi[KN]) {
#pragma unroll
    for (int k = 0; k < KN; k++) {
        if (d < bd[k]) {
            float td = bd[k]; int ti = bi[k];
            bd[k] = d; bi[k] = j;
            d = td; j = ti;
        }
    }
}

__global__ void knn3_k(const float* __restrict__ pos, int* __restrict__ idx) {
    __shared__ float sx[Pk], sy[Pk], sz[Pk], sn[Pk];
    int b = blockIdx.x >> 3;
    int p0 = (blockIdx.x & 7) << 8;
    const float* base = pos + (size_t)b * Pk * 3;
    for (int j = threadIdx.x; j < Pk; j += 256) {
        float x = base[3 * j], y = base[3 * j + 1], z = base[3 * j + 2];
        sx[j] = x; sy[j] = y; sz[j] = z;
        sn[j] = x * x + y * y + z * z;
    }
    __syncthreads();
    int p = p0 + threadIdx.x;
    float x = sx[p], y = sy[p], z = sz[p], sq = sn[p];
    float bd[KN]; int bi[KN];
#pragma unroll
    for (int k = 0; k < KN; k++) { bd[k] = 1e30f; bi[k] = 0; }
    for (int j = 0; j < Pk; j++) {
        float d = sq + sn[j] - 2.f * (x * sx[j] + y * sy[j] + z * sz[j]);
        if (d < bd[KN - 1]) knn_insert(d, j, bd, bi);
    }
    int o = (b * Pk + p) * KN;
#pragma unroll
    for (int k = 0; k < KN; k++) idx[o + k] = bi[k];
}

// edges(6)->64, ReLU, fused stats partials (64 edges/block)
__global__ void ec1_l0_k(const float* __restrict__ pos, const int* __restrict__ idx,
                         const float* __restrict__ w, const float* __restrict__ bias,
                         float* __restrict__ Z) {
    __shared__ float sw[384], sb[64];
    __shared__ float red[64 * 68];
    if (threadIdx.x < 64) sb[threadIdx.x] = bias[threadIdx.x];
    for (int i = threadIdx.x; i < 384; i += 256) sw[i] = w[i];
    __syncthreads();
    int g = blockIdx.x * 256 + threadIdx.x;
    int e = g >> 2, q = g & 3;
    int lr = threadIdx.x >> 2;
    int pt = e / KN, b = pt >> 11, j = idx[e];
    const float* pi = pos + (size_t)pt * 3;
    const float* pj = pos + ((size_t)(b << 11) + j) * 3;
    float e0 = pi[0], e1 = pi[1], e2 = pi[2];
    float e3 = pj[0] - e0, e4 = pj[1] - e1, e5 = pj[2] - e2;
    int c0 = q * 16;
    float out[16];
#pragma unroll
    for (int c = 0; c < 16; c++) {
        int cc = c0 + c;
        float a = sb[cc];
        a = fmaf(e0, sw[cc], a);
        a = fmaf(e1, sw[64 + cc], a);
        a = fmaf(e2, sw[128 + cc], a);
        a = fmaf(e3, sw[192 + cc], a);
        a = fmaf(e4, sw[256 + cc], a);
        a = fmaf(e5, sw[320 + cc], a);
        out[c] = fmaxf(a, 0.f);
        red[lr * 68 + cc] = out[c];
    }
    float4* dst = reinterpret_cast<float4*>(Z + (size_t)e * 64 + c0);
#pragma unroll
    for (int v = 0; v < 4; v++)
        dst[v] = make_float4(out[v * 4], out[v * 4 + 1], out[v * 4 + 2], out[v * 4 + 3]);
    __syncthreads();
    if (threadIdx.x < 64) {
        float s = 0.f, qq = 0.f;
        for (int r = 0; r < 64; r++) {
            float v = red[r * 68 + threadIdx.x];
            s += v; qq += v * v;
        }
        g_part[((size_t)blockIdx.x * 2 + 0) * 64 + threadIdx.x] = s;
        g_part[((size_t)blockIdx.x * 2 + 1) * 64 + threadIdx.x] = qq;
    }
}

__global__ void finalize_k(int C, float n, int nblk, const float* __restrict__ g,
                           const float* __restrict__ be, const float* __restrict__ part,
                           float* __restrict__ scale, float* __restrict__ shift) {
    int warp = (blockIdx.x * blockDim.x + threadIdx.x) >> 5;
    int lane = threadIdx.x & 31;
    if (warp >= C) return;
    float s = 0.f, q = 0.f;
    for (int b = lane; b < nblk; b += 32) {
        s += part[((size_t)b * 2 + 0) * C + warp];
        q += part[((size_t)b * 2 + 1) * C + warp];
    }
#pragma unroll
    for (int o = 16; o; o >>= 1) {
        s += __shfl_xor_sync(0xffffffffu, s, o);
        q += __shfl_xor_sync(0xffffffffu, q, o);
    }
    if (lane == 0) {
        float mean = s / n;
        float var = q / n - mean * mean;
        float sc = g[warp] * rsqrtf(var + EPSB);
        scale[warp] = sc;
        shift[warp] = be[warp] - mean * sc;
    }
}

__global__ void foldbias_k(int Cin, int Cout, const float* __restrict__ w,
                           const float* __restrict__ bias, const float* __restrict__ shift,
                           float* __restrict__ eb) {
    int c = blockIdx.x * blockDim.x + threadIdx.x;
    if (c >= Cout) return;
    float a = bias[c];
    for (int r = 0; r < Cin; r++) a = fmaf(shift[r], w[(size_t)r * Cout + c], a);
    eb[c] = a;
}

// WMMA 64->64 GEMM (BN fold via W scaling), ReLU, fused stats (128 edges/block)
constexpr int MST = 40;
__global__ void __launch_bounds__(256) mma_mid_k(const float* __restrict__ Zin,
                                                 const float* __restrict__ w,
                                                 const float* __restrict__ scaleIn,
                                                 const float* __restrict__ eb,
                                                 float* __restrict__ Zout) {
    extern __shared__ char dynb[];
    __nv_bfloat16* Ah = reinterpret_cast<__nv_bfloat16*>(dynb);
    __nv_bfloat16* Al = Ah + 128 * MST;
    __nv_bfloat16* Wh = Al + 128 * MST;
    __nv_bfloat16* Wl = Wh + 64 * MST;
    float* out = reinterpret_cast<float*>(dynb);
    int tid = threadIdx.x, wrp = tid >> 5;
    int row0 = blockIdx.x * 128;
    int wm = wrp >> 1, wn = wrp & 1;
    wmma::fragment<wmma::accumulator, 16, 16, 16, float> acc[2][2];
#pragma unroll
    for (int mm = 0; mm < 2; mm++)
#pragma unroll
        for (int nn = 0; nn < 2; nn++)
            wmma::fill_fragment(acc[mm][nn], 0.f);

    for (int kc = 0; kc < 2; kc++) {
        __syncthreads();
        for (int i = tid; i < 1024; i += 256) {
            int r = i >> 3, c4 = (i & 7) * 4;
            float4 v = *reinterpret_cast<const float4*>(
                &Zin[(size_t)(row0 + r) * 64 + kc * 32 + c4]);
            __nv_bfloat16 h0 = __float2bfloat16(v.x), h1 = __float2bfloat16(v.y);
            __nv_bfloat16 h2 = __float2bfloat16(v.z), h3 = __float2bfloat16(v.w);
            Ah[r * MST + c4 + 0] = h0;
            Ah[r * MST + c4 + 1] = h1;
            Ah[r * MST + c4 + 2] = h2;
            Ah[r * MST + c4 + 3] = h3;
            Al[r * MST + c4 + 0] = __float2bfloat16(v.x - __bfloat162float(h0));
            Al[r * MST + c4 + 1] = __float2bfloat16(v.y - __bfloat162float(h1));
            Al[r * MST + c4 + 2] = __float2bfloat16(v.z - __bfloat162float(h2));
            Al[r * MST + c4 + 3] = __float2bfloat16(v.w - __bfloat162float(h3));
        }
        for (int i = tid; i < 2048; i += 256) {
            int k = i >> 6, c = i & 63;
            int kk = kc * 32 + k;
            float v = scaleIn[kk] * w[(size_t)kk * 64 + c];
            __nv_bfloat16 h = __float2bfloat16(v);
            Wh[c * MST + k] = h;
            Wl[c * MST + k] = __float2bfloat16(v - __bfloat162float(h));
        }
        __syncthreads();
#pragma unroll
        for (int kk = 0; kk < 32; kk += 16) {
            wmma::fragment<wmma::matrix_a, 16, 16, 16, __nv_bfloat16, wmma::row_major> ah[2], al[2];
            wmma::fragment<wmma::matrix_b, 16, 16, 16, __nv_bfloat16, wmma::col_major> bh[2], bl[2];
#pragma unroll
            for (int mm = 0; mm < 2; mm++) {
                int rb = wm * 32 + mm * 16;
                wmma::load_matrix_sync(ah[mm], &Ah[rb * MST + kk], MST);
                wmma::load_matrix_sync(al[mm], &Al[rb * MST + kk], MST);
            }
#pragma unroll
            for (int nn = 0; nn < 2; nn++) {
                int nb = wn * 32 + nn * 16;
                wmma::load_matrix_sync(bh[nn], &Wh[nb * MST + kk], MST);
                wmma::load_matrix_sync(bl[nn], &Wl[nb * MST + kk], MST);
            }
#pragma unroll
            for (int mm = 0; mm < 2; mm++)
#pragma unroll
                for (int nn = 0; nn < 2; nn++) {
                    wmma::mma_sync(acc[mm][nn], ah[mm], bh[nn], acc[mm][nn]);
                    wmma::mma_sync(acc[mm][nn], ah[mm], bl[nn], acc[mm][nn]);
                    wmma::mma_sync(acc[mm][nn], al[mm], bh[nn], acc[mm][nn]);
                }
        }
    }
    __syncthreads();
#pragma unroll
    for (int mm = 0; mm < 2; mm++)
#pragma unroll
        for (int nn = 0; nn < 2; nn++) {
            int r = wm * 32 + mm * 16;
            int c = wn * 32 + nn * 16;
            wmma::store_matrix_sync(&out[r * 68 + c], acc[mm][nn], 68, wmma::mem_row_major);
        }
    __syncthreads();
    for (int i = tid; i < 2048; i += 256) {
        int r = i >> 4, c4 = (i & 15) * 4;
        float4 v = *reinterpret_cast<float4*>(&out[r * 68 + c4]);
        v.x = fmaxf(v.x + eb[c4 + 0], 0.f);
        v.y = fmaxf(v.y + eb[c4 + 1], 0.f);
        v.z = fmaxf(v.z + eb[c4 + 2], 0.f);
        v.w = fmaxf(v.w + eb[c4 + 3], 0.f);
        *reinterpret_cast<float4*>(&out[r * 68 + c4]) = v;
        *reinterpret_cast<float4*>(&Zout[(size_t)(row0 + r) * 64 + c4]) = v;
    }
    __syncthreads();
    if (tid < 64) {
        float s = 0.f, qq = 0.f;
        for (int r = 0; r < 128; r++) {
            float v = out[r * 68 + tid];
            s += v; qq += v * v;
        }
        g_part[((size_t)blockIdx.x * 2 + 0) * 64 + tid] = s;
        g_part[((size_t)blockIdx.x * 2 + 1) * 64 + tid] = qq;
    }
}

__global__ void maxE_k(const float* __restrict__ Z, int C,
                       const float* __restrict__ scale, const float* __restrict__ shift,
                       float* __restrict__ X, int colOff, int doSq) {
    int g = blockIdx.x * 256 + threadIdx.x;
    int per = C >> 2;
    int pt = g / per;
    int c4 = (g % per) * 4;
    float4 m = make_float4(-1e30f, -1e30f, -1e30f, -1e30f);
#pragma unroll
    for (int k = 0; k < KN; k++) {
        float4 v = *reinterpret_cast<const float4*>(&Z[(size_t)(pt * KN + k) * C + c4]);
        m.x = fmaxf(m.x, v.x); m.y = fmaxf(m.y, v.y);
        m.z = fmaxf(m.z, v.z); m.w = fmaxf(m.w, v.w);
    }
    float4 o;
    o.x = fmaf(scale[c4 + 0], m.x, shift[c4 + 0]);
    o.y = fmaf(scale[c4 + 1], m.y, shift[c4 + 1]);
    o.z = fmaf(scale[c4 + 2], m.z, shift[c4 + 2]);
    o.w = fmaf(scale[c4 + 3], m.w, shift[c4 + 3]);
    *reinterpret_cast<float4*>(&X[(size_t)pt * 192 + colOff + c4]) = o;
    __nv_bfloat16 h0 = __float2bfloat16(o.x), h1 = __float2bfloat16(o.y);
    __nv_bfloat16 h2 = __float2bfloat16(o.z), h3 = __float2bfloat16(o.w);
    size_t bo = (size_t)pt * 192 + colOff + c4;
    __nv_bfloat162* dh = reinterpret_cast<__nv_bfloat162*>(&g_Xhi[bo]);
    __nv_bfloat162* dl = reinterpret_cast<__nv_bfloat162*>(&g_Xlo[bo]);
    dh[0] = __halves2bfloat162(h0, h1);
    dh[1] = __halves2bfloat162(h2, h3);
    dl[0] = __halves2bfloat162(__float2bfloat16(o.x - __bfloat162float(h0)),
                               __float2bfloat16(o.y - __bfloat162float(h1)));
    dl[1] = __halves2bfloat162(__float2bfloat16(o.z - __bfloat162float(h2)),
                               __float2bfloat16(o.w - __bfloat162float(h3)));
    if (doSq) {
        float s = o.x * o.x + o.y * o.y + o.z * o.z + o.w * o.w;
#pragma unroll
        for (int off = 8; off; off >>= 1)
            s += __shfl_down_sync(0xffffffffu, s, off, 16);
        if ((threadIdx.x & 15) == 0) g_sq[pt] = s;
    }
}

// WMMA kNN on 64-dim features: dot tiles via tensor cores, scalar top-5 scan
constexpr int KST = 72;
__global__ void __launch_bounds__(256) knn64tc_k(int* __restrict__ idx) {
    extern __shared__ char kbuf[];
    __nv_bfloat16* Qh = reinterpret_cast<__nv_bfloat16*>(kbuf);
    __nv_bfloat16* Ql = Qh + 128 * KST;
    __nv_bfloat16* Ch = Ql + 128 * KST;
    __nv_bfloat16* Cl = Ch + 128 * KST;
    float* out = reinterpret_cast<float*>(kbuf + 4 * 128 * KST * 2);
    __shared__ float ssn[128];
    int tid = threadIdx.x, wrp = tid >> 5;
    int b = blockIdx.x >> 4, qt = blockIdx.x & 15;
    int q0 = (b << 11) + qt * 128;
    int wm = wrp >> 1, wn = wrp & 1;
    for (int i = tid; i < 1024; i += 256) {
        int r = i >> 3, cq = (i & 7) * 8;
        size_t g = (size_t)(q0 + r) * 192 + cq;
        *reinterpret_cast<uint4*>(&Qh[r * KST + cq]) =
            *reinterpret_cast<const uint4*>(&g_Xhi[g]);
        *reinterpret_cast<uint4*>(&Ql[r * KST + cq]) =
            *reinterpret_cast<const uint4*>(&g_Xlo[g]);
    }
    float sqp = 0.f, bd[KN]; int bi[KN];
    if (tid < 128) sqp = g_sq[q0 + tid];
#pragma unroll
    for (int k = 0; k < KN; k++) { bd[k] = 1e30f; bi[k] = 0; }

    for (int ct = 0; ct < 16; ct++) {
        __syncthreads();
        int c0 = (b << 11) + ct * 128;
        for (int i = tid; i < 1024; i += 256) {
            int r = i >> 3, cq = (i & 7) * 8;
            size_t g = (size_t)(c0 + r) * 192 + cq;
            *reinterpret_cast<uint4*>(&Ch[r * KST + cq]) =
                *reinterpret_cast<const uint4*>(&g_Xhi[g]);
            *reinterpret_cast<uint4*>(&Cl[r * KST + cq]) =
                *reinterpret_cast<const uint4*>(&g_Xlo[g]);
        }
        if (tid < 128) ssn[tid] = g_sq[c0 + tid];
        __syncthreads();
        wmma::fragment<wmma::accumulator, 16, 16, 16, float> acc[2][4];
#pragma unroll
        for (int mm = 0; mm < 2; mm++)
#pragma unroll
            for (int nn = 0; nn < 4; nn++)
                wmma::fill_fragment(acc[mm][nn], 0.f);
#pragma unroll
        for (int kk = 0; kk < 64; kk += 16) {
            wmma::fragment<wmma::matrix_a, 16, 16, 16, __nv_bfloat16, wmma::row_major> ah[2], al[2];
            wmma::fragment<wmma::matrix_b, 16, 16, 16, __nv_bfloat16, wmma::col_major> bh[4], bl[4];
#pragma unroll
            for (int mm = 0; mm < 2; mm++) {
                int rb = wm * 32 + mm * 16;
                wmma::load_matrix_sync(ah[mm], &Qh[rb * KST + kk], KST);
                wmma::load_matrix_sync(al[mm], &Ql[rb * KST + kk], KST);
            }
#pragma unroll
            for (int nn = 0; nn < 4; nn++) {
                int nb = wn * 64 + nn * 16;
                wmma::load_matrix_sync(bh[nn], &Ch[nb * KST + kk], KST);
                wmma::load_matrix_sync(bl[nn], &Cl[nb * KST + kk], KST);
            }
#pragma unroll
            for (int mm = 0; mm < 2; mm++)
#pragma unroll
                for (int nn = 0; nn < 4; nn++) {
                    wmma::mma_sync(acc[mm][nn], ah[mm], bh[nn], acc[mm][nn]);
                    wmma::mma_sync(acc[mm][nn], ah[mm], bl[nn], acc[mm][nn]);
                    wmma::mma_sync(acc[mm][nn], al[mm], bh[nn], acc[mm][nn]);
                }
        }
#pragma unroll
        for (int mm = 0; mm < 2; mm++)
#pragma unroll
            for (int nn = 0; nn < 4; nn++) {
                int r = wm * 32 + mm * 16;
                int c = wn * 64 + nn * 16;
                wmma::store_matrix_sync(&out[r * 132 + c], acc[mm][nn], 132, wmma::mem_row_major);
            }
        __syncthreads();
        if (tid < 128) {
            int jb = ct * 128;
            for (int c = 0; c < 128; c++) {
                float d = sqp + ssn[c] - 2.f * out[tid * 132 + c];
                if (d < bd[KN - 1]) knn_insert(d, jb + c, bd, bi);
            }
        }
    }
    if (tid < 128) {
        int o = (q0 + tid) * KN;
#pragma unroll
        for (int k = 0; k < KN; k++) idx[o + k] = bi[k];
    }
}

__global__ void wsplit2_k(const float* __restrict__ w) {
    int i = blockIdx.x * 256 + threadIdx.x;
    if (i >= 128 * 128) return;
    int r = i >> 7, c = i & 127;
    float v = w[i];
    __nv_bfloat16 h = __float2bfloat16(v);
    g_W2hi[c * 128 + r] = h;
    g_W2lo[c * 128 + r] = __float2bfloat16(v - __bfloat162float(h));
}

// WMMA EdgeConv2: gather(128) + GEMM 128x128, ReLU, stats (128 edges/block)
constexpr int EST = 40;
__global__ void __launch_bounds__(256) mma_ec2_k(const float* __restrict__ X,
                                                 const int* __restrict__ idx,
                                                 const float* __restrict__ bias,
                                                 float* __restrict__ Z) {
    extern __shared__ char dynbuf[];
    __nv_bfloat16* Ah = reinterpret_cast<__nv_bfloat16*>(dynbuf);
    __nv_bfloat16* Al = Ah + 128 * EST;
    __nv_bfloat16* Wh = Al + 128 * EST;
    __nv_bfloat16* Wl = Wh + 128 * EST;
    float* out = reinterpret_cast<float*>(dynbuf);
    int tid = threadIdx.x, wrp = tid >> 5;
    int e0 = blockIdx.x * 128;
    int wm = wrp >> 1, wn = wrp & 1;
    wmma::fragment<wmma::accumulator, 16, 16, 16, float> acc[2][4];
#pragma unroll
    for (int mm = 0; mm < 2; mm++)
#pragma unroll
        for (int nn = 0; nn < 4; nn++)
            wmma::fill_fragment(acc[mm][nn], 0.f);

    for (int kc = 0; kc < 4; kc++) {
        __syncthreads();
        for (int i = tid; i < 4096; i += 256) {
            int r = i >> 5, cq = i & 31;
            int col = kc * 32 + cq;
            int e = e0 + r;
            int pt = e / KN, bb = pt >> 11, j = idx[e];
            const float* xi = X + (size_t)pt * 192;
            const float* xj = X + ((size_t)(bb << 11) + j) * 192;
            float v = (col < 64) ? xi[col] : (xj[col - 64] - xi[col - 64]);
            __nv_bfloat16 h = __float2bfloat16(v);
            Ah[r * EST + cq] = h;
            Al[r * EST + cq] = __float2bfloat16(v - __bfloat162float(h));
        }
        if (tid < 256) {
            for (int i = tid; i < 512; i += 256) {
                int r = i >> 2, cq = (i & 3) * 8;
                size_t gg = (size_t)r * 128 + kc * 32 + cq;
                *reinterpret_cast<uint4*>(&Wh[r * EST + cq]) =
                    *reinterpret_cast<const uint4*>(&g_W2hi[gg]);
                *reinterpret_cast<uint4*>(&Wl[r * EST + cq]) =
                    *reinterpret_cast<const uint4*>(&g_W2lo[gg]);
            }
        }
        __syncthreads();
#pragma unroll
        for (int kk = 0; kk < 32; kk += 16) {
            wmma::fragment<wmma::matrix_a, 16, 16, 16, __nv_bfloat16, wmma::row_major> ah[2], al[2];
            wmma::fragment<wmma::matrix_b, 16, 16, 16, __nv_bfloat16, wmma::col_major> bh[4], bl[4];
#pragma unroll
            for (int mm = 0; mm < 2; mm++) {
                int rb = wm * 32 + mm * 16;
                wmma::load_matrix_sync(ah[mm], &Ah[rb * EST + kk], EST);
                wmma::load_matrix_sync(al[mm], &Al[rb * EST + kk], EST);
            }
#pragma unroll
            for (int nn = 0; nn < 4; nn++) {
                int nb = wn * 64 + nn * 16;
                wmma::load_matrix_sync(bh[nn], &Wh[nb * EST + kk], EST);
                wmma::load_matrix_sync(bl[nn], &Wl[nb * EST + kk], EST);
            }
#pragma unroll
            for (int mm = 0; mm < 2; mm++)
#pragma unroll
                for (int nn = 0; nn < 4; nn++) {
                    wmma::mma_sync(acc[mm][nn], ah[mm], bh[nn], acc[mm][nn]);
                    wmma::mma_sync(acc[mm][nn], ah[mm], bl[nn], acc[mm][nn]);
                    wmma::mma_sync(acc[mm][nn], al[mm], bh[nn], acc[mm][nn]);
                }
        }
    }
    __syncthreads();
#pragma unroll
    for (int mm = 0; mm < 2; mm++)
#pragma unroll
        for (int nn = 0; nn < 4; nn++) {
            int r = wm * 32 + mm * 16;
            int c = wn * 64 + nn * 16;
            wmma::store_matrix_sync(&out[r * 132 + c], acc[mm][nn], 132, wmma::mem_row_major);
        }
    __syncthreads();
    for (int i = tid; i < 4096; i += 256) {
        int r = i >> 5, c4 = (i & 31) * 4;
        float4 v = *reinterpret_cast<float4*>(&out[r * 132 + c4]);
        v.x = fmaxf(v.x + bias[c4 + 0], 0.f);
        v.y = fmaxf(v.y + bias[c4 + 1], 0.f);
        v.z = fmaxf(v.z + bias[c4 + 2], 0.f);
        v.w = fmaxf(v.w + bias[c4 + 3], 0.f);
        *reinterpret_cast<float4*>(&out[r * 132 + c4]) = v;
        *reinterpret_cast<float4*>(&Z[(size_t)(e0 + r) * 128 + c4]) = v;
    }
    __syncthreads();
    if (tid < 128) {
        float s = 0.f, qq = 0.f;
        for (int r = 0; r < 128; r++) {
            float v = out[r * 132 + tid];
            s += v; qq += v * v;
        }
        g_part[((size_t)blockIdx.x * 2 + 0) * 128 + tid] = s;
        g_part[((size_t)blockIdx.x * 2 + 1) * 128 + tid] = qq;
    }
}

__global__ void initP1_k() {
    int g = blockIdx.x * 256 + threadIdx.x;
    if (g < 16 * 1024) g_P1raw[g] = 0;
}

__global__ void wsplit_k(const float* __restrict__ w) {
    int i = blockIdx.x * 256 + threadIdx.x;
    int r = i >> 10, c = i & 1023;
    float v = w[i];
    __nv_bfloat16 h = __float2bfloat16(v);
    g_Whi[c * 192 + r] = h;
    g_Wlo[c * 192 + r] = __float2bfloat16(v - __bfloat162float(h));
}

constexpr int LSTR = 40;
__global__ void __launch_bounds__(256) mma_l1_k(const float* __restrict__ bias) {
    __shared__ __align__(16) char smbuf[128 * 68 * 4];
    __nv_bfloat16* Ah = reinterpret_cast<__nv_bfloat16*>(smbuf);
    __nv_bfloat16* Al = Ah + 128 * LSTR;
    __nv_bfloat16* Wh = Al + 128 * LSTR;
    __nv_bfloat16* Wl = Wh + 64 * LSTR;
    float* out = reinterpret_cast<float*>(smbuf);
    int tid = threadIdx.x, wrp = tid >> 5;
    int mt = blockIdx.x >> 4, nt = blockIdx.x & 15;
    int row0 = mt << 7, col0 = nt << 6;
    int wm = wrp >> 1, wn = wrp & 1;
    wmma::fragment<wmma::accumulator, 16, 16, 16, float> acc[2][2];
#pragma unroll
    for (int mm = 0; mm < 2; mm++)
#pragma unroll
        for (int nn = 0; nn < 2; nn++)
            wmma::fill_fragment(acc[mm][nn], 0.f);

    for (int kc = 0; kc < 6; kc++) {
        __syncthreads();
        for (int i = tid; i < 512; i += 256) {
            int r = i >> 2, cq = (i & 3) * 8;
            size_t g = (size_t)(row0 + r) * 192 + kc * 32 + cq;
            *reinterpret_cast<uint4*>(&Ah[r * LSTR + cq]) =
                *reinterpret_cast<const uint4*>(&g_Xhi[g]);
            *reinterpret_cast<uint4*>(&Al[r * LSTR + cq]) =
                *reinterpret_cast<const uint4*>(&g_Xlo[g]);
        }
        if (tid < 256) {
            int r = tid >> 2, cq = (tid & 3) * 8;
            size_t g = (size_t)(col0 + r) * 192 + kc * 32 + cq;
            *reinterpret_cast<uint4*>(&Wh[r * LSTR + cq]) =
                *reinterpret_cast<const uint4*>(&g_Whi[g]);
            *reinterpret_cast<uint4*>(&Wl[r * LSTR + cq]) =
                *reinterpret_cast<const uint4*>(&g_Wlo[g]);
        }
        __syncthreads();
#pragma unroll
        for (int kk = 0; kk < 32; kk += 16) {
            wmma::fragment<wmma::matrix_a, 16, 16, 16, __nv_bfloat16, wmma::row_major> ah[2], al[2];
            wmma::fragment<wmma::matrix_b, 16, 16, 16, __nv_bfloat16, wmma::col_major> bh[2], bl[2];
#pragma unroll
            for (int mm = 0; mm < 2; mm++) {
                int rb = wm * 32 + mm * 16;
                wmma::load_matrix_sync(ah[mm], &Ah[rb * LSTR + kk], LSTR);
                wmma::load_matrix_sync(al[mm], &Al[rb * LSTR + kk], LSTR);
            }
#pragma unroll
            for (int nn = 0; nn < 2; nn++) {
                int nb = wn * 32 + nn * 16;
                wmma::load_matrix_sync(bh[nn], &Wh[nb * LSTR + kk], LSTR);
                wmma::load_matrix_sync(bl[nn], &Wl[nb * LSTR + kk], LSTR);
            }
#pragma unroll
            for (int mm = 0; mm < 2; mm++)
#pragma unroll
                for (int nn = 0; nn < 2; nn++) {
                    wmma::mma_sync(acc[mm][nn], ah[mm], bh[nn], acc[mm][nn]);
                    wmma::mma_sync(acc[mm][nn], ah[mm], bl[nn], acc[mm][nn]);
                    wmma::mma_sync(acc[mm][nn], al[mm], bh[nn], acc[mm][nn]);
                }
        }
    }
    __syncthreads();
#pragma unroll
    for (int mm = 0; mm < 2; mm++)
#pragma unroll
        for (int nn = 0; nn < 2; nn++) {
            int r = wm * 32 + mm * 16;
            int c = wn * 32 + nn * 16;
            wmma::store_matrix_sync(&out[r * 68 + c], acc[mm][nn], 68, wmma::mem_row_major);
        }
    __syncthreads();
    for (int i = tid; i < 8192; i += 256) {
        int r = i >> 6, c = i & 63;
        out[r * 68 + c] = fmaxf(out[r * 68 + c] + bias[col0 + c], 0.f);
    }
    __syncthreads();
    if (tid < 64) {
        float s = 0.f, q = 0.f, m = 0.f;
        for (int r = 0; r < 128; r++) {
            float v = out[r * 68 + tid];
            s += v; q += v * v; m = fmaxf(m, v);
        }
        g_partL[((size_t)mt * 2 + 0) * 1024 + col0 + tid] = s;
        g_partL[((size_t)mt * 2 + 1) * 1024 + col0 + tid] = q;
        atomicMax(&g_P1raw[(row0 >> 11) * 1024 + col0 + tid], __float_as_int(m));
    }
}

__global__ void head1_k(const float* __restrict__ w, const float* __restrict__ bias) {
    __shared__ float sp[1024];
    int g = blockIdx.x * 256 + threadIdx.x;
    int b = g >> 9, c = g & 511;
    for (int i = threadIdx.x; i < 1024; i += 256)
        sp[i] = fmaf(g_s5[i], __int_as_float(g_P1raw[(b << 10) + i]), g_h5[i]);
    __syncthreads();
    float a = bias[c];
#pragma unroll 8
    for (int r = 0; r < 1024; r++) a = fmaf(sp[r], w[(size_t)r * 512 + c], a);
    g_Zm1[g] = fmaxf(a, 0.f);
}

__global__ void stats16_k(const float* __restrict__ Z, int C,
                          const float* __restrict__ g, const float* __restrict__ be,
                          float* __restrict__ scale, float* __restrict__ shift) {
    int c = blockIdx.x * blockDim.x + threadIdx.x;
    if (c >= C) return;
    float s = 0.f, q = 0.f;
    for (int b = 0; b < 16; b++) { float v = Z[b * C + c]; s += v; q += v * v; }
    float mean = s * 0.0625f;
    float var = q * 0.0625f - mean * mean;
    float sc = g[c] * rsqrtf(var + EPSB);
    scale[c] = sc;
    shift[c] = be[c] - mean * sc;
}

__global__ void head2_k(const float* __restrict__ w) {
    int g = blockIdx.x * 256 + threadIdx.x;
    int b = g >> 8, c = g & 255;
    float a = g_ebm2[c];
    const float* z = g_Zm1 + b * 512;
#pragma unroll 8
    for (int r = 0; r < 512; r++) a = fmaf(z[r] * g_s6[r], w[(size_t)r * 256 + c], a);
    g_Zm2[g] = fmaxf(a, 0.f);
}

__global__ void head3_k(const float* __restrict__ w, float* __restrict__ out) {
    int t = threadIdx.x;
    if (t >= 32) return;
    int b = t >> 1, n = t & 1;
    float a = g_ebm3[n];
    const float* z = g_Zm2 + b * 256;
#pragma unroll 8
    for (int r = 0; r < 256; r++) a = fmaf(z[r] * g_s7[r], w[r * 2 + n], a);
    out[b * 2 + n] = a;
}

static void* symaddr(const void* s) {
    void* p = nullptr;
    cudaGetSymbolAddress(&p, s);
    return p;
}

extern "C" void kernel_launch(void* const* d_in, const int* in_sizes, int n_in,
                              void* d_out, int out_size) {
    const float* pos = (const float*)d_in[0];
    const float* c1w0 = (const float*)d_in[1];
    const float* c1b0 = (const float*)d_in[2];
    const float* c1g0 = (const float*)d_in[3];
    const float* c1e0 = (const float*)d_in[4];
    const float* c1w1 = (const float*)d_in[5];
    const float* c1b1 = (const float*)d_in[6];
    const float* c1g1 = (const float*)d_in[7];
    const float* c1e1 = (const float*)d_in[8];
    const float* c1w2 = (const float*)d_in[9];
    const float* c1b2 = (const float*)d_in[10];
    const float* c1g2 = (const float*)d_in[11];
    const float* c1e2 = (const float*)d_in[12];
    const float* c2w = (const float*)d_in[13];
    const float* c2b = (const float*)d_in[14];
    const float* c2g = (const float*)d_in[15];
    const float* c2e = (const float*)d_in[16];
    const float* l1w = (const float*)d_in[17];
    const float* l1b = (const float*)d_in[18];
    const float* l1g = (const float*)d_in[19];
    const float* l1e = (const float*)d_in[20];
    const float* m1w = (const float*)d_in[21];
    const float* m1b = (const float*)d_in[22];
    const float* m1g = (const float*)d_in[23];
    const float* m1e = (const float*)d_in[24];
    const float* m2w = (const float*)d_in[25];
    const float* m2b = (const float*)d_in[26];
    const float* m2g = (const float*)d_in[27];
    const float* m2e = (const float*)d_in[28];
    const float* m3w = (const float*)d_in[29];
    const float* m3b = (const float*)d_in[30];

    float* Z1 = (float*)symaddr(g_Z1);
    float* Z2 = (float*)symaddr(g_Z2);
    float* Z4 = (float*)symaddr(g_Z4);
    float* X = (float*)symaddr(g_X12);
    int* I1 = (int*)symaddr(g_idx1);
    int* I2 = (int*)symaddr(g_idx2);
    float* part = (float*)symaddr(g_part);
    float* partL = (float*)symaddr(g_partL);
    float* s1 = (float*)symaddr(g_s1);
    float* h1 = (float*)symaddr(g_h1);
    float* s2 = (float*)symaddr(g_s2);
    float* h2 = (float*)symaddr(g_h2);
    float* s3 = (float*)symaddr(g_s3);
    float* h3 = (float*)symaddr(g_h3);
    float* s4 = (float*)symaddr(g_s4);
    float* h4 = (float*)symaddr(g_h4);
    float* s5 = (float*)symaddr(g_s5);
    float* h5 = (float*)symaddr(g_h5);
    float* s6 = (float*)symaddr(g_s6);
    float* h6 = (float*)symaddr(g_h6);
    float* s7 = (float*)symaddr(g_s7);
    float* h7 = (float*)symaddr(g_h7);
    float* eb2 = (float*)symaddr(g_eb2);
    float* eb3 = (float*)symaddr(g_eb3);
    float* ebm2 = (float*)symaddr(g_ebm2);
    float* ebm3 = (float*)symaddr(g_ebm3);
    float* Zm1 = (float*)symaddr(g_Zm1);
    float* Zm2 = (float*)symaddr(g_Zm2);

    cudaFuncSetAttribute(mma_ec2_k, cudaFuncAttributeMaxDynamicSharedMemorySize, 70656);
    cudaFuncSetAttribute(mma_mid_k, cudaFuncAttributeMaxDynamicSharedMemorySize, 35840);
    cudaFuncSetAttribute(knn64tc_k, cudaFuncAttributeMaxDynamicSharedMemorySize, 141312);

    wsplit_k<<<768, 256>>>(l1w);
    wsplit2_k<<<64, 256>>>(c2w);
    knn3_k<<<128, 256>>>(pos, I1);
    ec1_l0_k<<<NEDG * 4 / 256, 256>>>(pos, I1, c1w0, c1b0, Z1);
    finalize_k<<<8, 256>>>(64, (float)NEDG, 2560, c1g0, c1e0, part, s1, h1);
    foldbias_k<<<1, 64>>>(64, 64, c1w1, c1b1, h1, eb2);
    mma_mid_k<<<NEDG / 128, 256, 35840>>>(Z1, c1w1, s1, eb2, Z2);
    finalize_k<<<8, 256>>>(64, (float)NEDG, 1280, c1g1, c1e1, part, s2, h2);
    foldbias_k<<<1, 64>>>(64, 64, c1w2, c1b2, h2, eb3);
    mma_mid_k<<<NEDG / 128, 256, 35840>>>(Z2, c1w2, s2, eb3, Z1);
    finalize_k<<<8, 256>>>(64, (float)NEDG, 1280, c1g2, c1e2, part, s3, h3);
    maxE_k<<<NPTS * 16 / 256, 256>>>(Z1, 64, s3, h3, X, 0, 1);

    knn64tc_k<<<256, 256, 141312>>>(I2);
    mma_ec2_k<<<NEDG / 128, 256, 70656>>>(X, I2, c2b, Z4);
    finalize_k<<<16, 256>>>(128, (float)NEDG, 1280, c2g, c2e, part, s4, h4);
    maxE_k<<<NPTS * 32 / 256, 256>>>(Z4, 128, s4, h4, X, 64, 0);

    initP1_k<<<64, 256>>>();
    mma_l1_k<<<4096, 256>>>(l1b);
    finalize_k<<<128, 256>>>(1024, (float)NPTS, 256, l1g, l1e, partL, s5, h5);

    head1_k<<<32, 256>>>(m1w, m1b);
    stats16_k<<<2, 256>>>(Zm1, 512, m1g, m1e, s6, h6);
    foldbias_k<<<1, 256>>>(512, 256, m2w, m2b, h6, ebm2);
    head2_k<<<16, 256>>>(m2w);
    stats16_k<<<1, 256>>>(Zm2, 256, m2g, m2e, s7, h7);
    foldbias_k<<<1, 32>>>(256, 2, m3w, m3b, h7, ebm3);
    head3_k<<<1, 32>>>(m3w, (float*)d_out);
}

// round 15
// speedup vs baseline: 1.5775x; 1.1129x over previous
#include <cuda_runtime.h>
#include <cuda_bf16.h>
#include <mma.h>
#include <cstddef>

using namespace nvcuda;

#define EPSB 1e-5f
constexpr int Pk = 2048;
constexpr int KN = 5;
constexpr int NPTS = 16 * Pk;
constexpr int NEDG = NPTS * KN;

__device__ float g_Z1[(size_t)NEDG * 64];
__device__ float g_Z2[(size_t)NEDG * 64];
__device__ float g_Z4[(size_t)NEDG * 128];
__device__ float g_X12[(size_t)NPTS * 192];
__device__ float g_sq[NPTS];
__device__ int   g_idx1[NEDG];
__device__ int   g_idx2[NEDG];
__device__ float g_part[(size_t)2560 * 2 * 128];
__device__ float g_partL[(size_t)256 * 2 * 1024];
__device__ float g_s1[64], g_h1[64], g_s2[64], g_h2[64], g_s3[64], g_h3[64];
__device__ float g_s4[128], g_h4[128], g_s5[1024], g_h5[1024];
__device__ float g_s6[512], g_h6[512], g_s7[256], g_h7[256];
__device__ float g_eb2[64], g_eb3[64], g_ebm2[256], g_ebm3[2];
__device__ int   g_P1raw[16 * 1024];
__device__ float g_Zm1[16 * 512];
__device__ float g_Zm2[16 * 256];
__device__ __align__(256) __nv_bfloat16 g_Xhi[(size_t)NPTS * 192];
__device__ __align__(256) __nv_bfloat16 g_Xlo[(size_t)NPTS * 192];
__device__ __align__(256) __nv_bfloat16 g_Whi[1024 * 192];
__device__ __align__(256) __nv_bfloat16 g_Wlo[1024 * 192];
__device__ __align__(256) __nv_bfloat16 g_W2hi[128 * 128];
__device__ __align__(256) __nv_bfloat16 g_W2lo[128 * 128];

__device__ __forceinline__ void knn_insert(float d, int j, float bd[KN], int bi[KN]) {
#pragma unroll
    for (int k = 0; k < KN; k++) {
        if (d < bd[k]) {
            float td = bd[k]; int ti = bi[k];
            bd[k] = d; bi[k] = j;
            d = td; j = ti;
        }
    }
}

__global__ void knn3_k(const float* __restrict__ pos, int* __restrict__ idx) {
    __shared__ float sx[Pk], sy[Pk], sz[Pk], sn[Pk];
    int b = blockIdx.x >> 3;
    int p0 = (blockIdx.x & 7) << 8;
    const float* base = pos + (size_t)b * Pk * 3;
    for (int j = threadIdx.x; j < Pk; j += 256) {
        float x = base[3 * j], y = base[3 * j + 1], z = base[3 * j + 2];
        sx[j] = x; sy[j] = y; sz[j] = z;
        sn[j] = x * x + y * y + z * z;
    }
    __syncthreads();
    int p = p0 + threadIdx.x;
    float x = sx[p], y = sy[p], z = sz[p], sq = sn[p];
    float bd[KN]; int bi[KN];
#pragma unroll
    for (int k = 0; k < KN; k++) { bd[k] = 1e30f; bi[k] = 0; }
    for (int j = 0; j < Pk; j++) {
        float d = sq + sn[j] - 2.f * (x * sx[j] + y * sy[j] + z * sz[j]);
        if (d < bd[KN - 1]) knn_insert(d, j, bd, bi);
    }
    int o = (b * Pk + p) * KN;
#pragma unroll
    for (int k = 0; k < KN; k++) idx[o + k] = bi[k];
}

// edges(6)->64, ReLU, fused stats partials (64 edges/block)
__global__ void ec1_l0_k(const float* __restrict__ pos, const int* __restrict__ idx,
                         const float* __restrict__ w, const float* __restrict__ bias,
                         float* __restrict__ Z) {
    __shared__ float sw[384], sb[64];
    __shared__ float red[64 * 68];
    if (threadIdx.x < 64) sb[threadIdx.x] = bias[threadIdx.x];
    for (int i = threadIdx.x; i < 384; i += 256) sw[i] = w[i];
    __syncthreads();
    int g = blockIdx.x * 256 + threadIdx.x;
    int e = g >> 2, q = g & 3;
    int lr = threadIdx.x >> 2;
    int pt = e / KN, b = pt >> 11, j = idx[e];
    const float* pi = pos + (size_t)pt * 3;
    const float* pj = pos + ((size_t)(b << 11) + j) * 3;
    float e0 = pi[0], e1 = pi[1], e2 = pi[2];
    float e3 = pj[0] - e0, e4 = pj[1] - e1, e5 = pj[2] - e2;
    int c0 = q * 16;
    float out[16];
#pragma unroll
    for (int c = 0; c < 16; c++) {
        int cc = c0 + c;
        float a = sb[cc];
        a = fmaf(e0, sw[cc], a);
        a = fmaf(e1, sw[64 + cc], a);
        a = fmaf(e2, sw[128 + cc], a);
        a = fmaf(e3, sw[192 + cc], a);
        a = fmaf(e4, sw[256 + cc], a);
        a = fmaf(e5, sw[320 + cc], a);
        out[c] = fmaxf(a, 0.f);
        red[lr * 68 + cc] = out[c];
    }
    float4* dst = reinterpret_cast<float4*>(Z + (size_t)e * 64 + c0);
#pragma unroll
    for (int v = 0; v < 4; v++)
        dst[v] = make_float4(out[v * 4], out[v * 4 + 1], out[v * 4 + 2], out[v * 4 + 3]);
    __syncthreads();
    if (threadIdx.x < 64) {
        float s = 0.f, qq = 0.f;
        for (int r = 0; r < 64; r++) {
            float v = red[r * 68 + threadIdx.x];
            s += v; qq += v * v;
        }
        g_part[((size_t)blockIdx.x * 2 + 0) * 64 + threadIdx.x] = s;
        g_part[((size_t)blockIdx.x * 2 + 1) * 64 + threadIdx.x] = qq;
    }
}

__global__ void finalize_k(int C, float n, int nblk, const float* __restrict__ g,
                           const float* __restrict__ be, const float* __restrict__ part,
                           float* __restrict__ scale, float* __restrict__ shift) {
    int warp = (blockIdx.x * blockDim.x + threadIdx.x) >> 5;
    int lane = threadIdx.x & 31;
    if (warp >= C) return;
    float s = 0.f, q = 0.f;
    for (int b = lane; b < nblk; b += 32) {
        s += part[((size_t)b * 2 + 0) * C + warp];
        q += part[((size_t)b * 2 + 1) * C + warp];
    }
#pragma unroll
    for (int o = 16; o; o >>= 1) {
        s += __shfl_xor_sync(0xffffffffu, s, o);
        q += __shfl_xor_sync(0xffffffffu, q, o);
    }
    if (lane == 0) {
        float mean = s / n;
        float var = q / n - mean * mean;
        float sc = g[warp] * rsqrtf(var + EPSB);
        scale[warp] = sc;
        shift[warp] = be[warp] - mean * sc;
    }
}

__global__ void foldbias_k(int Cin, int Cout, const float* __restrict__ w,
                           const float* __restrict__ bias, const float* __restrict__ shift,
                           float* __restrict__ eb) {
    int c = blockIdx.x * blockDim.x + threadIdx.x;
    if (c >= Cout) return;
    float a = bias[c];
    for (int r = 0; r < Cin; r++) a = fmaf(shift[r], w[(size_t)r * Cout + c], a);
    eb[c] = a;
}

// WMMA 64->64 GEMM (BN fold via W scaling), ReLU, fused stats (128 edges/block)
constexpr int MST = 40;
__global__ void __launch_bounds__(256) mma_mid_k(const float* __restrict__ Zin,
                                                 const float* __restrict__ w,
                                                 const float* __restrict__ scaleIn,
                                                 const float* __restrict__ eb,
                                                 float* __restrict__ Zout) {
    extern __shared__ char dynb[];
    __nv_bfloat16* Ah = reinterpret_cast<__nv_bfloat16*>(dynb);
    __nv_bfloat16* Al = Ah + 128 * MST;
    __nv_bfloat16* Wh = Al + 128 * MST;
    __nv_bfloat16* Wl = Wh + 64 * MST;
    float* out = reinterpret_cast<float*>(dynb);
    int tid = threadIdx.x, wrp = tid >> 5;
    int row0 = blockIdx.x * 128;
    int wm = wrp >> 1, wn = wrp & 1;
    wmma::fragment<wmma::accumulator, 16, 16, 16, float> acc[2][2];
#pragma unroll
    for (int mm = 0; mm < 2; mm++)
#pragma unroll
        for (int nn = 0; nn < 2; nn++)
            wmma::fill_fragment(acc[mm][nn], 0.f);

    for (int kc = 0; kc < 2; kc++) {
        __syncthreads();
        for (int i = tid; i < 1024; i += 256) {
            int r = i >> 3, c4 = (i & 7) * 4;
            float4 v = *reinterpret_cast<const float4*>(
                &Zin[(size_t)(row0 + r) * 64 + kc * 32 + c4]);
            __nv_bfloat16 h0 = __float2bfloat16(v.x), h1 = __float2bfloat16(v.y);
            __nv_bfloat16 h2 = __float2bfloat16(v.z), h3 = __float2bfloat16(v.w);
            Ah[r * MST + c4 + 0] = h0;
            Ah[r * MST + c4 + 1] = h1;
            Ah[r * MST + c4 + 2] = h2;
            Ah[r * MST + c4 + 3] = h3;
            Al[r * MST + c4 + 0] = __float2bfloat16(v.x - __bfloat162float(h0));
            Al[r * MST + c4 + 1] = __float2bfloat16(v.y - __bfloat162float(h1));
            Al[r * MST + c4 + 2] = __float2bfloat16(v.z - __bfloat162float(h2));
            Al[r * MST + c4 + 3] = __float2bfloat16(v.w - __bfloat162float(h3));
        }
        for (int i = tid; i < 2048; i += 256) {
            int k = i >> 6, c = i & 63;
            int kk = kc * 32 + k;
            float v = scaleIn[kk] * w[(size_t)kk * 64 + c];
            __nv_bfloat16 h = __float2bfloat16(v);
            Wh[c * MST + k] = h;
            Wl[c * MST + k] = __float2bfloat16(v - __bfloat162float(h));
        }
        __syncthreads();
#pragma unroll
        for (int kk = 0; kk < 32; kk += 16) {
            wmma::fragment<wmma::matrix_a, 16, 16, 16, __nv_bfloat16, wmma::row_major> ah[2], al[2];
            wmma::fragment<wmma::matrix_b, 16, 16, 16, __nv_bfloat16, wmma::col_major> bh[2], bl[2];
#pragma unroll
            for (int mm = 0; mm < 2; mm++) {
                int rb = wm * 32 + mm * 16;
                wmma::load_matrix_sync(ah[mm], &Ah[rb * MST + kk], MST);
                wmma::load_matrix_sync(al[mm], &Al[rb * MST + kk], MST);
            }
#pragma unroll
            for (int nn = 0; nn < 2; nn++) {
                int nb = wn * 32 + nn * 16;
                wmma::load_matrix_sync(bh[nn], &Wh[nb * MST + kk], MST);
                wmma::load_matrix_sync(bl[nn], &Wl[nb * MST + kk], MST);
            }
#pragma unroll
            for (int mm = 0; mm < 2; mm++)
#pragma unroll
                for (int nn = 0; nn < 2; nn++) {
                    wmma::mma_sync(acc[mm][nn], ah[mm], bh[nn], acc[mm][nn]);
                    wmma::mma_sync(acc[mm][nn], ah[mm], bl[nn], acc[mm][nn]);
                    wmma::mma_sync(acc[mm][nn], al[mm], bh[nn], acc[mm][nn]);
                }
        }
    }
    __syncthreads();
#pragma unroll
    for (int mm = 0; mm < 2; mm++)
#pragma unroll
        for (int nn = 0; nn < 2; nn++) {
            int r = wm * 32 + mm * 16;
            int c = wn * 32 + nn * 16;
            wmma::store_matrix_sync(&out[r * 68 + c], acc[mm][nn], 68, wmma::mem_row_major);
        }
    __syncthreads();
    for (int i = tid; i < 2048; i += 256) {
        int r = i >> 4, c4 = (i & 15) * 4;
        float4 v = *reinterpret_cast<float4*>(&out[r * 68 + c4]);
        v.x = fmaxf(v.x + eb[c4 + 0], 0.f);
        v.y = fmaxf(v.y + eb[c4 + 1], 0.f);
        v.z = fmaxf(v.z + eb[c4 + 2], 0.f);
        v.w = fmaxf(v.w + eb[c4 + 3], 0.f);
        *reinterpret_cast<float4*>(&out[r * 68 + c4]) = v;
        *reinterpret_cast<float4*>(&Zout[(size_t)(row0 + r) * 64 + c4]) = v;
    }
    __syncthreads();
    if (tid < 64) {
        float s = 0.f, qq = 0.f;
        for (int r = 0; r < 128; r++) {
            float v = out[r * 68 + tid];
            s += v; qq += v * v;
        }
        g_part[((size_t)blockIdx.x * 2 + 0) * 64 + tid] = s;
        g_part[((size_t)blockIdx.x * 2 + 1) * 64 + tid] = qq;
    }
}

__global__ void maxE_k(const float* __restrict__ Z, int C,
                       const float* __restrict__ scale, const float* __restrict__ shift,
                       float* __restrict__ X, int colOff, int doSq) {
    int g = blockIdx.x * 256 + threadIdx.x;
    int per = C >> 2;
    int pt = g / per;
    int c4 = (g % per) * 4;
    float4 m = make_float4(-1e30f, -1e30f, -1e30f, -1e30f);
#pragma unroll
    for (int k = 0; k < KN; k++) {
        float4 v = *reinterpret_cast<const float4*>(&Z[(size_t)(pt * KN + k) * C + c4]);
        m.x = fmaxf(m.x, v.x); m.y = fmaxf(m.y, v.y);
        m.z = fmaxf(m.z, v.z); m.w = fmaxf(m.w, v.w);
    }
    float4 o;
    o.x = fmaf(scale[c4 + 0], m.x, shift[c4 + 0]);
    o.y = fmaf(scale[c4 + 1], m.y, shift[c4 + 1]);
    o.z = fmaf(scale[c4 + 2], m.z, shift[c4 + 2]);
    o.w = fmaf(scale[c4 + 3], m.w, shift[c4 + 3]);
    *reinterpret_cast<float4*>(&X[(size_t)pt * 192 + colOff + c4]) = o;
    __nv_bfloat16 h0 = __float2bfloat16(o.x), h1 = __float2bfloat16(o.y);
    __nv_bfloat16 h2 = __float2bfloat16(o.z), h3 = __float2bfloat16(o.w);
    size_t bo = (size_t)pt * 192 + colOff + c4;
    __nv_bfloat162* dh = reinterpret_cast<__nv_bfloat162*>(&g_Xhi[bo]);
    __nv_bfloat162* dl = reinterpret_cast<__nv_bfloat162*>(&g_Xlo[bo]);
    dh[0] = __halves2bfloat162(h0, h1);
    dh[1] = __halves2bfloat162(h2, h3);
    dl[0] = __halves2bfloat162(__float2bfloat16(o.x - __bfloat162float(h0)),
                               __float2bfloat16(o.y - __bfloat162float(h1)));
    dl[1] = __halves2bfloat162(__float2bfloat16(o.z - __bfloat162float(h2)),
                               __float2bfloat16(o.w - __bfloat162float(h3)));
    if (doSq) {
        float s = o.x * o.x + o.y * o.y + o.z * o.z + o.w * o.w;
#pragma unroll
        for (int off = 8; off; off >>= 1)
            s += __shfl_down_sync(0xffffffffu, s, off, 16);
        if ((threadIdx.x & 15) == 0) g_sq[pt] = s;
    }
}

// WMMA kNN: dot tiles via tensor cores; 256-thread split scan + final merge
constexpr int KST = 72;
__global__ void __launch_bounds__(256) knn64tc_k(int* __restrict__ idx) {
    extern __shared__ char kbuf[];
    __nv_bfloat16* Qh = reinterpret_cast<__nv_bfloat16*>(kbuf);
    __nv_bfloat16* Ql = Qh + 128 * KST;
    __nv_bfloat16* Ch = Ql + 128 * KST;
    __nv_bfloat16* Cl = Ch + 128 * KST;
    float* out = reinterpret_cast<float*>(kbuf + 4 * 128 * KST * 2);
    __shared__ float ssn[128];
    int tid = threadIdx.x, wrp = tid >> 5;
    int b = blockIdx.x >> 4, qt = blockIdx.x & 15;
    int q0 = (b << 11) + qt * 128;
    int wm = wrp >> 1, wn = wrp & 1;
    int qr = tid & 127;          // query row
    int half = tid >> 7;         // candidate half
    for (int i = tid; i < 1024; i += 256) {
        int r = i >> 3, cq = (i & 7) * 8;
        size_t g = (size_t)(q0 + r) * 192 + cq;
        *reinterpret_cast<uint4*>(&Qh[r * KST + cq]) =
            *reinterpret_cast<const uint4*>(&g_Xhi[g]);
        *reinterpret_cast<uint4*>(&Ql[r * KST + cq]) =
            *reinterpret_cast<const uint4*>(&g_Xlo[g]);
    }
    float sqp = g_sq[q0 + qr];
    float bd[KN]; int bi[KN];
#pragma unroll
    for (int k = 0; k < KN; k++) { bd[k] = 1e30f; bi[k] = 0; }

    for (int ct = 0; ct < 16; ct++) {
        __syncthreads();
        int c0 = (b << 11) + ct * 128;
        for (int i = tid; i < 1024; i += 256) {
            int r = i >> 3, cq = (i & 7) * 8;
            size_t g = (size_t)(c0 + r) * 192 + cq;
            *reinterpret_cast<uint4*>(&Ch[r * KST + cq]) =
                *reinterpret_cast<const uint4*>(&g_Xhi[g]);
            *reinterpret_cast<uint4*>(&Cl[r * KST + cq]) =
                *reinterpret_cast<const uint4*>(&g_Xlo[g]);
        }
        if (tid < 128) ssn[tid] = g_sq[c0 + tid];
        __syncthreads();
        wmma::fragment<wmma::accumulator, 16, 16, 16, float> acc[2][4];
#pragma unroll
        for (int mm = 0; mm < 2; mm++)
#pragma unroll
            for (int nn = 0; nn < 4; nn++)
                wmma::fill_fragment(acc[mm][nn], 0.f);
#pragma unroll
        for (int kk = 0; kk < 64; kk += 16) {
            wmma::fragment<wmma::matrix_a, 16, 16, 16, __nv_bfloat16, wmma::row_major> ah[2], al[2];
            wmma::fragment<wmma::matrix_b, 16, 16, 16, __nv_bfloat16, wmma::col_major> bh[4], bl[4];
#pragma unroll
            for (int mm = 0; mm < 2; mm++) {
                int rb = wm * 32 + mm * 16;
                wmma::load_matrix_sync(ah[mm], &Qh[rb * KST + kk], KST);
                wmma::load_matrix_sync(al[mm], &Ql[rb * KST + kk], KST);
            }
#pragma unroll
            for (int nn = 0; nn < 4; nn++) {
                int nb = wn * 64 + nn * 16;
                wmma::load_matrix_sync(bh[nn], &Ch[nb * KST + kk], KST);
                wmma::load_matrix_sync(bl[nn], &Cl[nb * KST + kk], KST);
            }
#pragma unroll
            for (int mm = 0; mm < 2; mm++)
#pragma unroll
                for (int nn = 0; nn < 4; nn++) {
                    wmma::mma_sync(acc[mm][nn], ah[mm], bh[nn], acc[mm][nn]);
                    wmma::mma_sync(acc[mm][nn], ah[mm], bl[nn], acc[mm][nn]);
                    wmma::mma_sync(acc[mm][nn], al[mm], bh[nn], acc[mm][nn]);
                }
        }
#pragma unroll
        for (int mm = 0; mm < 2; mm++)
#pragma unroll
            for (int nn = 0; nn < 4; nn++) {
                int r = wm * 32 + mm * 16;
                int c = wn * 64 + nn * 16;
                wmma::store_matrix_sync(&out[r * 132 + c], acc[mm][nn], 132, wmma::mem_row_major);
            }
        __syncthreads();
        {
            int jb = ct * 128 + half * 64;
            const float* row = &out[qr * 132 + half * 64];
            const float* nn = &ssn[half * 64];
            for (int c = 0; c < 64; c++) {
                float d = sqp + nn[c] - 2.f * row[c];
                if (d < bd[KN - 1]) knn_insert(d, jb + c, bd, bi);
            }
        }
    }
    __syncthreads();
    if (tid >= 128) {
        int r = tid - 128;
#pragma unroll
        for (int k = 0; k < KN; k++) {
            out[r * KN + k] = bd[k];
            reinterpret_cast<int*>(out + 640)[r * KN + k] = bi[k];
        }
    }
    __syncthreads();
    if (tid < 128) {
        const float* d1 = &out[tid * KN];
        const int* i1 = &reinterpret_cast<int*>(out + 640)[tid * KN];
        int mi[KN];
        int a = 0, c = 0;
#pragma unroll
        for (int k = 0; k < KN; k++) {
            bool takeA = (c >= KN) || (a < KN && (bd[a] < d1[c] ||
                         (bd[a] == d1[c] && bi[a] < i1[c])));
            if (takeA) { mi[k] = bi[a]; a++; }
            else { mi[k] = i1[c]; c++; }
        }
        int o = (q0 + tid) * KN;
#pragma unroll
        for (int k = 0; k < KN; k++) idx[o + k] = mi[k];
    }
}

__global__ void wsplit2_k(const float* __restrict__ w) {
    int i = blockIdx.x * 256 + threadIdx.x;
    if (i >= 128 * 128) return;
    int r = i >> 7, c = i & 127;
    float v = w[i];
    __nv_bfloat16 h = __float2bfloat16(v);
    g_W2hi[c * 128 + r] = h;
    g_W2lo[c * 128 + r] = __float2bfloat16(v - __bfloat162float(h));
}

// WMMA EdgeConv2: vectorized gather(128) + GEMM 128x128, ReLU, stats
constexpr int EST = 40;
__global__ void __launch_bounds__(256) mma_ec2_k(const float* __restrict__ X,
                                                 const int* __restrict__ idx,
                                                 const float* __restrict__ bias,
                                                 float* __restrict__ Z) {
    extern __shared__ char dynbuf[];
    __nv_bfloat16* Ah = reinterpret_cast<__nv_bfloat16*>(dynbuf);
    __nv_bfloat16* Al = Ah + 128 * EST;
    __nv_bfloat16* Wh = Al + 128 * EST;
    __nv_bfloat16* Wl = Wh + 128 * EST;
    float* out = reinterpret_cast<float*>(dynbuf);
    int tid = threadIdx.x, wrp = tid >> 5;
    int e0 = blockIdx.x * 128;
    int wm = wrp >> 1, wn = wrp & 1;
    wmma::fragment<wmma::accumulator, 16, 16, 16, float> acc[2][4];
#pragma unroll
    for (int mm = 0; mm < 2; mm++)
#pragma unroll
        for (int nn = 0; nn < 4; nn++)
            wmma::fill_fragment(acc[mm][nn], 0.f);

    for (int kc = 0; kc < 4; kc++) {
        __syncthreads();
        for (int i = tid; i < 1024; i += 256) {
            int r = i >> 3, c4 = (i & 7) * 4;
            int col = kc * 32 + c4;
            int e = e0 + r;
            int pt = e / KN, bb = pt >> 11, j = idx[e];
            const float* xi = X + (size_t)pt * 192;
            const float* xj = X + ((size_t)(bb << 11) + j) * 192;
            float4 v;
            if (col < 64) {
                v = *reinterpret_cast<const float4*>(&xi[col]);
            } else {
                float4 a = *reinterpret_cast<const float4*>(&xj[col - 64]);
                float4 bq = *reinterpret_cast<const float4*>(&xi[col - 64]);
                v = make_float4(a.x - bq.x, a.y - bq.y, a.z - bq.z, a.w - bq.w);
            }
            __nv_bfloat16 h0 = __float2bfloat16(v.x), h1 = __float2bfloat16(v.y);
            __nv_bfloat16 h2 = __float2bfloat16(v.z), h3 = __float2bfloat16(v.w);
            Ah[r * EST + c4 + 0] = h0;
            Ah[r * EST + c4 + 1] = h1;
            Ah[r * EST + c4 + 2] = h2;
            Ah[r * EST + c4 + 3] = h3;
            Al[r * EST + c4 + 0] = __float2bfloat16(v.x - __bfloat162float(h0));
            Al[r * EST + c4 + 1] = __float2bfloat16(v.y - __bfloat162float(h1));
            Al[r * EST + c4 + 2] = __float2bfloat16(v.z - __bfloat162float(h2));
            Al[r * EST + c4 + 3] = __float2bfloat16(v.w - __bfloat162float(h3));
        }
        if (tid < 256) {
            for (int i = tid; i < 512; i += 256) {
                int r = i >> 2, cq = (i & 3) * 8;
                size_t gg = (size_t)r * 128 + kc * 32 + cq;
                *reinterpret_cast<uint4*>(&Wh[r * EST + cq]) =
                    *reinterpret_cast<const uint4*>(&g_W2hi[gg]);
                *reinterpret_cast<uint4*>(&Wl[r * EST + cq]) =
                    *reinterpret_cast<const uint4*>(&g_W2lo[gg]);
            }
        }
        __syncthreads();
#pragma unroll
        for (int kk = 0; kk < 32; kk += 16) {
            wmma::fragment<wmma::matrix_a, 16, 16, 16, __nv_bfloat16, wmma::row_major> ah[2], al[2];
            wmma::fragment<wmma::matrix_b, 16, 16, 16, __nv_bfloat16, wmma::col_major> bh[4], bl[4];
#pragma unroll
            for (int mm = 0; mm < 2; mm++) {
                int rb = wm * 32 + mm * 16;
                wmma::load_matrix_sync(ah[mm], &Ah[rb * EST + kk], EST);
                wmma::load_matrix_sync(al[mm], &Al[rb * EST + kk], EST);
            }
#pragma unroll
            for (int nn = 0; nn < 4; nn++) {
                int nb = wn * 64 + nn * 16;
                wmma::load_matrix_sync(bh[nn], &Wh[nb * EST + kk], EST);
                wmma::load_matrix_sync(bl[nn], &Wl[nb * EST + kk], EST);
            }
#pragma unroll
            for (int mm = 0; mm < 2; mm++)
#pragma unroll
                for (int nn = 0; nn < 4; nn++) {
                    wmma::mma_sync(acc[mm][nn], ah[mm], bh[nn], acc[mm][nn]);
                    wmma::mma_sync(acc[mm][nn], ah[mm], bl[nn], acc[mm][nn]);
                    wmma::mma_sync(acc[mm][nn], al[mm], bh[nn], acc[mm][nn]);
                }
        }
    }
    __syncthreads();
#pragma unroll
    for (int mm = 0; mm < 2; mm++)
#pragma unroll
        for (int nn = 0; nn < 4; nn++) {
            int r = wm * 32 + mm * 16;
            int c = wn * 64 + nn * 16;
            wmma::store_matrix_sync(&out[r * 132 + c], acc[mm][nn], 132, wmma::mem_row_major);
        }
    __syncthreads();
    for (int i = tid; i < 4096; i += 256) {
        int r = i >> 5, c4 = (i & 31) * 4;
        float4 v = *reinterpret_cast<float4*>(&out[r * 132 + c4]);
        v.x = fmaxf(v.x + bias[c4 + 0], 0.f);
        v.y = fmaxf(v.y + bias[c4 + 1], 0.f);
        v.z = fmaxf(v.z + bias[c4 + 2], 0.f);
        v.w = fmaxf(v.w + bias[c4 + 3], 0.f);
        *reinterpret_cast<float4*>(&out[r * 132 + c4]) = v;
        *reinterpret_cast<float4*>(&Z[(size_t)(e0 + r) * 128 + c4]) = v;
    }
    __syncthreads();
    if (tid < 128) {
        float s = 0.f, qq = 0.f;
        for (int r = 0; r < 128; r++) {
            float v = out[r * 132 + tid];
            s += v; qq += v * v;
        }
        g_part[((size_t)blockIdx.x * 2 + 0) * 128 + tid] = s;
        g_part[((size_t)blockIdx.x * 2 + 1) * 128 + tid] = qq;
    }
}

__global__ void initP1_k() {
    int g = blockIdx.x * 256 + threadIdx.x;
    if (g < 16 * 1024) g_P1raw[g] = 0;
}

__global__ void wsplit_k(const float* __restrict__ w) {
    int i = blockIdx.x * 256 + threadIdx.x;
    int r = i >> 10, c = i & 1023;
    float v = w[i];
    __nv_bfloat16 h = __float2bfloat16(v);
    g_Whi[c * 192 + r] = h;
    g_Wlo[c * 192 + r] = __float2bfloat16(v - __bfloat162float(h));
}

constexpr int LSTR = 40;
__global__ void __launch_bounds__(256) mma_l1_k(const float* __restrict__ bias) {
    __shared__ __align__(16) char smbuf[128 * 68 * 4];
    __nv_bfloat16* Ah = reinterpret_cast<__nv_bfloat16*>(smbuf);
    __nv_bfloat16* Al = Ah + 128 * LSTR;
    __nv_bfloat16* Wh = Al + 128 * LSTR;
    __nv_bfloat16* Wl = Wh + 64 * LSTR;
    float* out = reinterpret_cast<float*>(smbuf);
    int tid = threadIdx.x, wrp = tid >> 5;
    int mt = blockIdx.x >> 4, nt = blockIdx.x & 15;
    int row0 = mt << 7, col0 = nt << 6;
    int wm = wrp >> 1, wn = wrp & 1;
    wmma::fragment<wmma::accumulator, 16, 16, 16, float> acc[2][2];
#pragma unroll
    for (int mm = 0; mm < 2; mm++)
#pragma unroll
        for (int nn = 0; nn < 2; nn++)
            wmma::fill_fragment(acc[mm][nn], 0.f);

    for (int kc = 0; kc < 6; kc++) {
        __syncthreads();
        for (int i = tid; i < 512; i += 256) {
            int r = i >> 2, cq = (i & 3) * 8;
            size_t g = (size_t)(row0 + r) * 192 + kc * 32 + cq;
            *reinterpret_cast<uint4*>(&Ah[r * LSTR + cq]) =
                *reinterpret_cast<const uint4*>(&g_Xhi[g]);
            *reinterpret_cast<uint4*>(&Al[r * LSTR + cq]) =
                *reinterpret_cast<const uint4*>(&g_Xlo[g]);
        }
        if (tid < 256) {
            int r = tid >> 2, cq = (tid & 3) * 8;
            size_t g = (size_t)(col0 + r) * 192 + kc * 32 + cq;
            *reinterpret_cast<uint4*>(&Wh[r * LSTR + cq]) =
                *reinterpret_cast<const uint4*>(&g_Whi[g]);
            *reinterpret_cast<uint4*>(&Wl[r * LSTR + cq]) =
                *reinterpret_cast<const uint4*>(&g_Wlo[g]);
        }
        __syncthreads();
#pragma unroll
        for (int kk = 0; kk < 32; kk += 16) {
            wmma::fragment<wmma::matrix_a, 16, 16, 16, __nv_bfloat16, wmma::row_major> ah[2], al[2];
            wmma::fragment<wmma::matrix_b, 16, 16, 16, __nv_bfloat16, wmma::col_major> bh[2], bl[2];
#pragma unroll
            for (int mm = 0; mm < 2; mm++) {
                int rb = wm * 32 + mm * 16;
                wmma::load_matrix_sync(ah[mm], &Ah[rb * LSTR + kk], LSTR);
                wmma::load_matrix_sync(al[mm], &Al[rb * LSTR + kk], LSTR);
            }
#pragma unroll
            for (int nn = 0; nn < 2; nn++) {
                int nb = wn * 32 + nn * 16;
                wmma::load_matrix_sync(bh[nn], &Wh[nb * LSTR + kk], LSTR);
                wmma::load_matrix_sync(bl[nn], &Wl[nb * LSTR + kk], LSTR);
            }
#pragma unroll
            for (int mm = 0; mm < 2; mm++)
#pragma unroll
                for (int nn = 0; nn < 2; nn++) {
                    wmma::mma_sync(acc[mm][nn], ah[mm], bh[nn], acc[mm][nn]);
                    wmma::mma_sync(acc[mm][nn], ah[mm], bl[nn], acc[mm][nn]);
                    wmma::mma_sync(acc[mm][nn], al[mm], bh[nn], acc[mm][nn]);
                }
        }
    }
    __syncthreads();
#pragma unroll
    for (int mm = 0; mm < 2; mm++)
#pragma unroll
        for (int nn = 0; nn < 2; nn++) {
            int r = wm * 32 + mm * 16;
            int c = wn * 32 + nn * 16;
            wmma::store_matrix_sync(&out[r * 68 + c], acc[mm][nn], 68, wmma::mem_row_major);
        }
    __syncthreads();
    for (int i = tid; i < 8192; i += 256) {
        int r = i >> 6, c = i & 63;
        out[r * 68 + c] = fmaxf(out[r * 68 + c] + bias[col0 + c], 0.f);
    }
    __syncthreads();
    if (tid < 64) {
        float s = 0.f, q = 0.f, m = 0.f;
        for (int r = 0; r < 128; r++) {
            float v = out[r * 68 + tid];
            s += v; q += v * v; m = fmaxf(m, v);
        }
        g_partL[((size_t)mt * 2 + 0) * 1024 + col0 + tid] = s;
        g_partL[((size_t)mt * 2 + 1) * 1024 + col0 + tid] = q;
        atomicMax(&g_P1raw[(row0 >> 11) * 1024 + col0 + tid], __float_as_int(m));
    }
}

__global__ void head1_k(const float* __restrict__ w, const float* __restrict__ bias) {
    __shared__ float sp[1024];
    int g = blockIdx.x * 256 + threadIdx.x;
    int b = g >> 9, c = g & 511;
    for (int i = threadIdx.x; i < 1024; i += 256)
        sp[i] = fmaf(g_s5[i], __int_as_float(g_P1raw[(b << 10) + i]), g_h5[i]);
    __syncthreads();
    float a = bias[c];
#pragma unroll 8
    for (int r = 0; r < 1024; r++) a = fmaf(sp[r], w[(size_t)r * 512 + c], a);
    g_Zm1[g] = fmaxf(a, 0.f);
}

__global__ void stats16_k(const float* __restrict__ Z, int C,
                          const float* __restrict__ g, const float* __restrict__ be,
                          float* __restrict__ scale, float* __restrict__ shift) {
    int c = blockIdx.x * blockDim.x + threadIdx.x;
    if (c >= C) return;
    float s = 0.f, q = 0.f;
    for (int b = 0; b < 16; b++) { float v = Z[b * C + c]; s += v; q += v * v; }
    float mean = s * 0.0625f;
    float var = q * 0.0625f - mean * mean;
    float sc = g[c] * rsqrtf(var + EPSB);
    scale[c] = sc;
    shift[c] = be[c] - mean * sc;
}

__global__ void head2_k(const float* __restrict__ w) {
    int g = blockIdx.x * 256 + threadIdx.x;
    int b = g >> 8, c = g & 255;
    float a = g_ebm2[c];
    const float* z = g_Zm1 + b * 512;
#pragma unroll 8
    for (int r = 0; r < 512; r++) a = fmaf(z[r] * g_s6[r], w[(size_t)r * 256 + c], a);
    g_Zm2[g] = fmaxf(a, 0.f);
}

__global__ void head3_k(const float* __restrict__ w, float* __restrict__ out) {
    int t = threadIdx.x;
    if (t >= 32) return;
    int b = t >> 1, n = t & 1;
    float a = g_ebm3[n];
    const float* z = g_Zm2 + b * 256;
#pragma unroll 8
    for (int r = 0; r < 256; r++) a = fmaf(z[r] * g_s7[r], w[r * 2 + n], a);
    out[b * 2 + n] = a;
}

static void* symaddr(const void* s) {
    void* p = nullptr;
    cudaGetSymbolAddress(&p, s);
    return p;
}

extern "C" void kernel_launch(void* const* d_in, const int* in_sizes, int n_in,
                              void* d_out, int out_size) {
    const float* pos = (const float*)d_in[0];
    const float* c1w0 = (const float*)d_in[1];
    const float* c1b0 = (const float*)d_in[2];
    const float* c1g0 = (const float*)d_in[3];
    const float* c1e0 = (const float*)d_in[4];
    const float* c1w1 = (const float*)d_in[5];
    const float* c1b1 = (const float*)d_in[6];
    const float* c1g1 = (const float*)d_in[7];
    const float* c1e1 = (const float*)d_in[8];
    const float* c1w2 = (const float*)d_in[9];
    const float* c1b2 = (const float*)d_in[10];
    const float* c1g2 = (const float*)d_in[11];
    const float* c1e2 = (const float*)d_in[12];
    const float* c2w = (const float*)d_in[13];
    const float* c2b = (const float*)d_in[14];
    const float* c2g = (const float*)d_in[15];
    const float* c2e = (const float*)d_in[16];
    const float* l1w = (const float*)d_in[17];
    const float* l1b = (const float*)d_in[18];
    const float* l1g = (const float*)d_in[19];
    const float* l1e = (const float*)d_in[20];
    const float* m1w = (const float*)d_in[21];
    const float* m1b = (const float*)d_in[22];
    const float* m1g = (const float*)d_in[23];
    const float* m1e = (const float*)d_in[24];
    const float* m2w = (const float*)d_in[25];
    const float* m2b = (const float*)d_in[26];
    const float* m2g = (const float*)d_in[27];
    const float* m2e = (const float*)d_in[28];
    const float* m3w = (const float*)d_in[29];
    const float* m3b = (const float*)d_in[30];

    float* Z1 = (float*)symaddr(g_Z1);
    float* Z2 = (float*)symaddr(g_Z2);
    float* Z4 = (float*)symaddr(g_Z4);
    float* X = (float*)symaddr(g_X12);
    int* I1 = (int*)symaddr(g_idx1);
    int* I2 = (int*)symaddr(g_idx2);
    float* part = (float*)symaddr(g_part);
    float* partL = (float*)symaddr(g_partL);
    float* s1 = (float*)symaddr(g_s1);
    float* h1 = (float*)symaddr(g_h1);
    float* s2 = (float*)symaddr(g_s2);
    float* h2 = (float*)symaddr(g_h2);
    float* s3 = (float*)symaddr(g_s3);
    float* h3 = (float*)symaddr(g_h3);
    float* s4 = (float*)symaddr(g_s4);
    float* h4 = (float*)symaddr(g_h4);
    float* s5 = (float*)symaddr(g_s5);
    float* h5 = (float*)symaddr(g_h5);
    float* s6 = (float*)symaddr(g_s6);
    float* h6 = (float*)symaddr(g_h6);
    float* s7 = (float*)symaddr(g_s7);
    float* h7 = (float*)symaddr(g_h7);
    float* eb2 = (float*)symaddr(g_eb2);
    float* eb3 = (float*)symaddr(g_eb3);
    float* ebm2 = (float*)symaddr(g_ebm2);
    float* ebm3 = (float*)symaddr(g_ebm3);
    float* Zm1 = (float*)symaddr(g_Zm1);
    float* Zm2 = (float*)symaddr(g_Zm2);

    cudaFuncSetAttribute(mma_ec2_k, cudaFuncAttributeMaxDynamicSharedMemorySize, 70656);
    cudaFuncSetAttribute(mma_mid_k, cudaFuncAttributeMaxDynamicSharedMemorySize, 35840);
    cudaFuncSetAttribute(knn64tc_k, cudaFuncAttributeMaxDynamicSharedMemorySize, 141312);

    wsplit_k<<<768, 256>>>(l1w);
    wsplit2_k<<<64, 256>>>(c2w);
    knn3_k<<<128, 256>>>(pos, I1);
    ec1_l0_k<<<NEDG * 4 / 256, 256>>>(pos, I1, c1w0, c1b0, Z1);
    finalize_k<<<8, 256>>>(64, (float)NEDG, 2560, c1g0, c1e0, part, s1, h1);
    foldbias_k<<<1, 64>>>(64, 64, c1w1, c1b1, h1, eb2);
    mma_mid_k<<<NEDG / 128, 256, 35840>>>(Z1, c1w1, s1, eb2, Z2);
    finalize_k<<<8, 256>>>(64, (float)NEDG, 1280, c1g1, c1e1, part, s2, h2);
    foldbias_k<<<1, 64>>>(64, 64, c1w2, c1b2, h2, eb3);
    mma_mid_k<<<NEDG / 128, 256, 35840>>>(Z2, c1w2, s2, eb3, Z1);
    finalize_k<<<8, 256>>>(64, (float)NEDG, 1280, c1g2, c1e2, part, s3, h3);
    maxE_k<<<NPTS * 16 / 256, 256>>>(Z1, 64, s3, h3, X, 0, 1);

    knn64tc_k<<<256, 256, 141312>>>(I2);
    mma_ec2_k<<<NEDG / 128, 256, 70656>>>(X, I2, c2b, Z4);
    finalize_k<<<16, 256>>>(128, (float)NEDG, 1280, c2g, c2e, part, s4, h4);
    maxE_k<<<NPTS * 32 / 256, 256>>>(Z4, 128, s4, h4, X, 64, 0);

    initP1_k<<<64, 256>>>();
    mma_l1_k<<<4096, 256>>>(l1b);
    finalize_k<<<128, 256>>>(1024, (float)NPTS, 256, l1g, l1e, partL, s5, h5);

    head1_k<<<32, 256>>>(m1w, m1b);
    stats16_k<<<2, 256>>>(Zm1, 512, m1g, m1e, s6, h6);
    foldbias_k<<<1, 256>>>(512, 256, m2w, m2b, h6, ebm2);
    head2_k<<<16, 256>>>(m2w);
    stats16_k<<<1, 256>>>(Zm2, 256, m2g, m2e, s7, h7);
    foldbias_k<<<1, 32>>>(256, 2, m3w, m3b, h7, ebm3);
    head3_k<<<1, 32>>>(m3w, (float*)d_out);
}

// round 16
// speedup vs baseline: 1.6659x; 1.0560x over previous
#include <cuda_runtime.h>
#include <cuda_bf16.h>
#include <mma.h>
#include <cstddef>

using namespace nvcuda;

#define EPSB 1e-5f
constexpr int Pk = 2048;
constexpr int KN = 5;
constexpr int NPTS = 16 * Pk;
constexpr int NEDG = NPTS * KN;

__device__ float g_Z1[(size_t)NEDG * 64];
__device__ float g_Z2[(size_t)NEDG * 64];
__device__ float g_Z4[(size_t)NEDG * 128];
__device__ float g_X12[(size_t)NPTS * 192];
__device__ float g_sq[NPTS];
__device__ int   g_idx1[NEDG];
__device__ int   g_idx2[NEDG];
__device__ float g_part[(size_t)2560 * 2 * 128];
__device__ float g_partL[(size_t)256 * 2 * 1024];
__device__ float g_s1[64], g_h1[64], g_s2[64], g_h2[64], g_s3[64], g_h3[64];
__device__ float g_s4[128], g_h4[128], g_s5[1024], g_h5[1024];
__device__ float g_s6[512], g_h6[512], g_s7[256], g_h7[256];
__device__ float g_eb2[64], g_eb3[64], g_ebm2[256], g_ebm3[2];
__device__ int   g_P1raw[16 * 1024];
__device__ float g_Zm1[16 * 512];
__device__ float g_Zm2[16 * 256];
__device__ __align__(256) __nv_bfloat16 g_Xhi[(size_t)NPTS * 192];
__device__ __align__(256) __nv_bfloat16 g_Xlo[(size_t)NPTS * 192];
__device__ __align__(256) __nv_bfloat16 g_Whi[1024 * 192];
__device__ __align__(256) __nv_bfloat16 g_Wlo[1024 * 192];
__device__ __align__(256) __nv_bfloat16 g_W2hi[128 * 128];
__device__ __align__(256) __nv_bfloat16 g_W2lo[128 * 128];

__device__ __forceinline__ void knn_insert(float d, int j, float bd[KN], int bi[KN]) {
#pragma unroll
    for (int k = 0; k < KN; k++) {
        if (d < bd[k]) {
            float td = bd[k]; int ti = bi[k];
            bd[k] = d; bi[k] = j;
            d = td; j = ti;
        }
    }
}

__global__ void knn3_k(const float* __restrict__ pos, int* __restrict__ idx) {
    __shared__ float4 s4[Pk];
    int b = blockIdx.x >> 3;
    int p0 = (blockIdx.x & 7) << 8;
    const float* base = pos + (size_t)b * Pk * 3;
    for (int j = threadIdx.x; j < Pk; j += 256) {
        float x = base[3 * j], y = base[3 * j + 1], z = base[3 * j + 2];
        s4[j] = make_float4(x, y, z, x * x + y * y + z * z);
    }
    __syncthreads();
    int p = p0 + threadIdx.x;
    float4 me = s4[p];
    float x = me.x, y = me.y, z = me.z, sq = me.w;
    float bd[KN]; int bi[KN];
#pragma unroll
    for (int k = 0; k < KN; k++) { bd[k] = 1e30f; bi[k] = 0; }
#pragma unroll 4
    for (int j = 0; j < Pk; j++) {
        float4 v = s4[j];
        float d = sq + v.w - 2.f * (x * v.x + y * v.y + z * v.z);
        if (d < bd[KN - 1]) knn_insert(d, j, bd, bi);
    }
    int o = (b * Pk + p) * KN;
#pragma unroll
    for (int k = 0; k < KN; k++) idx[o + k] = bi[k];
}

// edges(6)->64, ReLU, fused stats partials (64 edges/block)
__global__ void ec1_l0_k(const float* __restrict__ pos, const int* __restrict__ idx,
                         const float* __restrict__ w, const float* __restrict__ bias,
                         float* __restrict__ Z) {
    __shared__ float sw[384], sb[64];
    __shared__ float red[64 * 68];
    if (threadIdx.x < 64) sb[threadIdx.x] = bias[threadIdx.x];
    for (int i = threadIdx.x; i < 384; i += 256) sw[i] = w[i];
    __syncthreads();
    int g = blockIdx.x * 256 + threadIdx.x;
    int e = g >> 2, q = g & 3;
    int lr = threadIdx.x >> 2;
    int pt = e / KN, b = pt >> 11, j = idx[e];
    const float* pi = pos + (size_t)pt * 3;
    const float* pj = pos + ((size_t)(b << 11) + j) * 3;
    float e0 = pi[0], e1 = pi[1], e2 = pi[2];
    float e3 = pj[0] - e0, e4 = pj[1] - e1, e5 = pj[2] - e2;
    int c0 = q * 16;
    float out[16];
#pragma unroll
    for (int c = 0; c < 16; c++) {
        int cc = c0 + c;
        float a = sb[cc];
        a = fmaf(e0, sw[cc], a);
        a = fmaf(e1, sw[64 + cc], a);
        a = fmaf(e2, sw[128 + cc], a);
        a = fmaf(e3, sw[192 + cc], a);
        a = fmaf(e4, sw[256 + cc], a);
        a = fmaf(e5, sw[320 + cc], a);
        out[c] = fmaxf(a, 0.f);
    }
    float4* dst = reinterpret_cast<float4*>(Z + (size_t)e * 64 + c0);
#pragma unroll
    for (int v = 0; v < 4; v++) {
        float4 o4 = make_float4(out[v * 4], out[v * 4 + 1], out[v * 4 + 2], out[v * 4 + 3]);
        dst[v] = o4;
        *reinterpret_cast<float4*>(&red[lr * 68 + c0 + v * 4]) = o4;
    }
    __syncthreads();
    if (threadIdx.x < 64) {
        float s = 0.f, qq = 0.f;
        for (int r = 0; r < 64; r++) {
            float v = red[r * 68 + threadIdx.x];
            s += v; qq += v * v;
        }
        g_part[((size_t)blockIdx.x * 2 + 0) * 64 + threadIdx.x] = s;
        g_part[((size_t)blockIdx.x * 2 + 1) * 64 + threadIdx.x] = qq;
    }
}

__global__ void finalize_k(int C, float n, int nblk, const float* __restrict__ g,
                           const float* __restrict__ be, const float* __restrict__ part,
                           float* __restrict__ scale, float* __restrict__ shift) {
    int warp = (blockIdx.x * blockDim.x + threadIdx.x) >> 5;
    int lane = threadIdx.x & 31;
    if (warp >= C) return;
    float s = 0.f, q = 0.f;
    for (int b = lane; b < nblk; b += 32) {
        s += part[((size_t)b * 2 + 0) * C + warp];
        q += part[((size_t)b * 2 + 1) * C + warp];
    }
#pragma unroll
    for (int o = 16; o; o >>= 1) {
        s += __shfl_xor_sync(0xffffffffu, s, o);
        q += __shfl_xor_sync(0xffffffffu, q, o);
    }
    if (lane == 0) {
        float mean = s / n;
        float var = q / n - mean * mean;
        float sc = g[warp] * rsqrtf(var + EPSB);
        scale[warp] = sc;
        shift[warp] = be[warp] - mean * sc;
    }
}

__global__ void foldbias_k(int Cin, int Cout, const float* __restrict__ w,
                           const float* __restrict__ bias, const float* __restrict__ shift,
                           float* __restrict__ eb) {
    int c = blockIdx.x * blockDim.x + threadIdx.x;
    if (c >= Cout) return;
    float a = bias[c];
    for (int r = 0; r < Cin; r++) a = fmaf(shift[r], w[(size_t)r * Cout + c], a);
    eb[c] = a;
}

// WMMA 64->64 GEMM (BN fold via W scaling), ReLU, fused stats (128 edges/block)
constexpr int MST = 40;
__global__ void __launch_bounds__(256) mma_mid_k(const float* __restrict__ Zin,
                                                 const float* __restrict__ w,
                                                 const float* __restrict__ scaleIn,
                                                 const float* __restrict__ eb,
                                                 float* __restrict__ Zout) {
    extern __shared__ char dynb[];
    __nv_bfloat16* Ah = reinterpret_cast<__nv_bfloat16*>(dynb);
    __nv_bfloat16* Al = Ah + 128 * MST;
    __nv_bfloat16* Wh = Al + 128 * MST;
    __nv_bfloat16* Wl = Wh + 64 * MST;
    float* out = reinterpret_cast<float*>(dynb);
    int tid = threadIdx.x, wrp = tid >> 5;
    int row0 = blockIdx.x * 128;
    int wm = wrp >> 1, wn = wrp & 1;
    wmma::fragment<wmma::accumulator, 16, 16, 16, float> acc[2][2];
#pragma unroll
    for (int mm = 0; mm < 2; mm++)
#pragma unroll
        for (int nn = 0; nn < 2; nn++)
            wmma::fill_fragment(acc[mm][nn], 0.f);

    for (int kc = 0; kc < 2; kc++) {
        __syncthreads();
        for (int i = tid; i < 1024; i += 256) {
            int r = i >> 3, c4 = (i & 7) * 4;
            float4 v = *reinterpret_cast<const float4*>(
                &Zin[(size_t)(row0 + r) * 64 + kc * 32 + c4]);
            __nv_bfloat16 h0 = __float2bfloat16(v.x), h1 = __float2bfloat16(v.y);
            __nv_bfloat16 h2 = __float2bfloat16(v.z), h3 = __float2bfloat16(v.w);
            Ah[r * MST + c4 + 0] = h0;
            Ah[r * MST + c4 + 1] = h1;
            Ah[r * MST + c4 + 2] = h2;
            Ah[r * MST + c4 + 3] = h3;
            Al[r * MST + c4 + 0] = __float2bfloat16(v.x - __bfloat162float(h0));
            Al[r * MST + c4 + 1] = __float2bfloat16(v.y - __bfloat162float(h1));
            Al[r * MST + c4 + 2] = __float2bfloat16(v.z - __bfloat162float(h2));
            Al[r * MST + c4 + 3] = __float2bfloat16(v.w - __bfloat162float(h3));
        }
        for (int i = tid; i < 2048; i += 256) {
            int k = i >> 6, c = i & 63;
            int kk = kc * 32 + k;
            float v = scaleIn[kk] * w[(size_t)kk * 64 + c];
            __nv_bfloat16 h = __float2bfloat16(v);
            Wh[c * MST + k] = h;
            Wl[c * MST + k] = __float2bfloat16(v - __bfloat162float(h));
        }
        __syncthreads();
#pragma unroll
        for (int kk = 0; kk < 32; kk += 16) {
            wmma::fragment<wmma::matrix_a, 16, 16, 16, __nv_bfloat16, wmma::row_major> ah[2], al[2];
            wmma::fragment<wmma::matrix_b, 16, 16, 16, __nv_bfloat16, wmma::col_major> bh[2], bl[2];
#pragma unroll
            for (int mm = 0; mm < 2; mm++) {
                int rb = wm * 32 + mm * 16;
                wmma::load_matrix_sync(ah[mm], &Ah[rb * MST + kk], MST);
                wmma::load_matrix_sync(al[mm], &Al[rb * MST + kk], MST);
            }
#pragma unroll
            for (int nn = 0; nn < 2; nn++) {
                int nb = wn * 32 + nn * 16;
                wmma::load_matrix_sync(bh[nn], &Wh[nb * MST + kk], MST);
                wmma::load_matrix_sync(bl[nn], &Wl[nb * MST + kk], MST);
            }
#pragma unroll
            for (int mm = 0; mm < 2; mm++)
#pragma unroll
                for (int nn = 0; nn < 2; nn++) {
                    wmma::mma_sync(acc[mm][nn], ah[mm], bh[nn], acc[mm][nn]);
                    wmma::mma_sync(acc[mm][nn], ah[mm], bl[nn], acc[mm][nn]);
                    wmma::mma_sync(acc[mm][nn], al[mm], bh[nn], acc[mm][nn]);
                }
        }
    }
    __syncthreads();
#pragma unroll
    for (int mm = 0; mm < 2; mm++)
#pragma unroll
        for (int nn = 0; nn < 2; nn++) {
            int r = wm * 32 + mm * 16;
            int c = wn * 32 + nn * 16;
            wmma::store_matrix_sync(&out[r * 68 + c], acc[mm][nn], 68, wmma::mem_row_major);
        }
    __syncthreads();
    for (int i = tid; i < 2048; i += 256) {
        int r = i >> 4, c4 = (i & 15) * 4;
        float4 v = *reinterpret_cast<float4*>(&out[r * 68 + c4]);
        v.x = fmaxf(v.x + eb[c4 + 0], 0.f);
        v.y = fmaxf(v.y + eb[c4 + 1], 0.f);
        v.z = fmaxf(v.z + eb[c4 + 2], 0.f);
        v.w = fmaxf(v.w + eb[c4 + 3], 0.f);
        *reinterpret_cast<float4*>(&out[r * 68 + c4]) = v;
        *reinterpret_cast<float4*>(&Zout[(size_t)(row0 + r) * 64 + c4]) = v;
    }
    __syncthreads();
    if (tid < 64) {
        float s = 0.f, qq = 0.f;
        for (int r = 0; r < 128; r++) {
            float v = out[r * 68 + tid];
            s += v; qq += v * v;
        }
        g_part[((size_t)blockIdx.x * 2 + 0) * 64 + tid] = s;
        g_part[((size_t)blockIdx.x * 2 + 1) * 64 + tid] = qq;
    }
}

__global__ void maxE_k(const float* __restrict__ Z, int C,
                       const float* __restrict__ scale, const float* __restrict__ shift,
                       float* __restrict__ X, int colOff, int doSq) {
    int g = blockIdx.x * 256 + threadIdx.x;
    int per = C >> 2;
    int pt = g / per;
    int c4 = (g % per) * 4;
    float4 m = make_float4(-1e30f, -1e30f, -1e30f, -1e30f);
#pragma unroll
    for (int k = 0; k < KN; k++) {
        float4 v = *reinterpret_cast<const float4*>(&Z[(size_t)(pt * KN + k) * C + c4]);
        m.x = fmaxf(m.x, v.x); m.y = fmaxf(m.y, v.y);
        m.z = fmaxf(m.z, v.z); m.w = fmaxf(m.w, v.w);
    }
    float4 o;
    o.x = fmaf(scale[c4 + 0], m.x, shift[c4 + 0]);
    o.y = fmaf(scale[c4 + 1], m.y, shift[c4 + 1]);
    o.z = fmaf(scale[c4 + 2], m.z, shift[c4 + 2]);
    o.w = fmaf(scale[c4 + 3], m.w, shift[c4 + 3]);
    *reinterpret_cast<float4*>(&X[(size_t)pt * 192 + colOff + c4]) = o;
    __nv_bfloat16 h0 = __float2bfloat16(o.x), h1 = __float2bfloat16(o.y);
    __nv_bfloat16 h2 = __float2bfloat16(o.z), h3 = __float2bfloat16(o.w);
    size_t bo = (size_t)pt * 192 + colOff + c4;
    __nv_bfloat162* dh = reinterpret_cast<__nv_bfloat162*>(&g_Xhi[bo]);
    __nv_bfloat162* dl = reinterpret_cast<__nv_bfloat162*>(&g_Xlo[bo]);
    dh[0] = __halves2bfloat162(h0, h1);
    dh[1] = __halves2bfloat162(h2, h3);
    dl[0] = __halves2bfloat162(__float2bfloat16(o.x - __bfloat162float(h0)),
                               __float2bfloat16(o.y - __bfloat162float(h1)));
    dl[1] = __halves2bfloat162(__float2bfloat16(o.z - __bfloat162float(h2)),
                               __float2bfloat16(o.w - __bfloat162float(h3)));
    if (doSq) {
        float s = o.x * o.x + o.y * o.y + o.z * o.z + o.w * o.w;
#pragma unroll
        for (int off = 8; off; off >>= 1)
            s += __shfl_down_sync(0xffffffffu, s, off, 16);
        if ((threadIdx.x & 15) == 0) g_sq[pt] = s;
    }
}

// WMMA kNN: 64-query tiles (2 CTA/SM), 4-way split scan + lexicographic merge
constexpr int KST = 72;
__global__ void __launch_bounds__(256) knn64tc_k(int* __restrict__ idx) {
    extern __shared__ char kbuf[];
    __nv_bfloat16* Qh = reinterpret_cast<__nv_bfloat16*>(kbuf);
    __nv_bfloat16* Ql = Qh + 64 * KST;
    __nv_bfloat16* Ch = Ql + 64 * KST;
    __nv_bfloat16* Cl = Ch + 128 * KST;
    float* out = reinterpret_cast<float*>(kbuf + 384 * KST * 2);
    __shared__ float ssn[128];
    int tid = threadIdx.x, wrp = tid >> 5;
    int b = blockIdx.x >> 5, qt = blockIdx.x & 31;
    int q0 = (b << 11) + qt * 64;
    int wm = wrp >> 2, wn = wrp & 3;
    int qr = tid & 63, quar = tid >> 6;
    for (int i = tid; i < 512; i += 256) {
        int r = i >> 3, cq = (i & 7) * 8;
        size_t g = (size_t)(q0 + r) * 192 + cq;
        *reinterpret_cast<uint4*>(&Qh[r * KST + cq]) =
            *reinterpret_cast<const uint4*>(&g_Xhi[g]);
        *reinterpret_cast<uint4*>(&Ql[r * KST + cq]) =
            *reinterpret_cast<const uint4*>(&g_Xlo[g]);
    }
    float sqp = g_sq[q0 + qr];
    float bd[KN]; int bi[KN];
#pragma unroll
    for (int k = 0; k < KN; k++) { bd[k] = 1e30f; bi[k] = 0; }

    for (int ct = 0; ct < 16; ct++) {
        __syncthreads();
        int c0 = (b << 11) + ct * 128;
        for (int i = tid; i < 1024; i += 256) {
            int r = i >> 3, cq = (i & 7) * 8;
            size_t g = (size_t)(c0 + r) * 192 + cq;
            *reinterpret_cast<uint4*>(&Ch[r * KST + cq]) =
                *reinterpret_cast<const uint4*>(&g_Xhi[g]);
            *reinterpret_cast<uint4*>(&Cl[r * KST + cq]) =
                *reinterpret_cast<const uint4*>(&g_Xlo[g]);
        }
        if (tid < 128) ssn[tid] = g_sq[c0 + tid];
        __syncthreads();
        wmma::fragment<wmma::accumulator, 16, 16, 16, float> acc[2][2];
#pragma unroll
        for (int mm = 0; mm < 2; mm++)
#pragma unroll
            for (int nn = 0; nn < 2; nn++)
                wmma::fill_fragment(acc[mm][nn], 0.f);
#pragma unroll
        for (int kk = 0; kk < 64; kk += 16) {
            wmma::fragment<wmma::matrix_a, 16, 16, 16, __nv_bfloat16, wmma::row_major> ah[2], al[2];
            wmma::fragment<wmma::matrix_b, 16, 16, 16, __nv_bfloat16, wmma::col_major> bh[2], bl[2];
#pragma unroll
            for (int mm = 0; mm < 2; mm++) {
                int rb = wm * 32 + mm * 16;
                wmma::load_matrix_sync(ah[mm], &Qh[rb * KST + kk], KST);
                wmma::load_matrix_sync(al[mm], &Ql[rb * KST + kk], KST);
            }
#pragma unroll
            for (int nn = 0; nn < 2; nn++) {
                int nb = wn * 32 + nn * 16;
                wmma::load_matrix_sync(bh[nn], &Ch[nb * KST + kk], KST);
                wmma::load_matrix_sync(bl[nn], &Cl[nb * KST + kk], KST);
            }
#pragma unroll
            for (int mm = 0; mm < 2; mm++)
#pragma unroll
                for (int nn = 0; nn < 2; nn++) {
                    wmma::mma_sync(acc[mm][nn], ah[mm], bh[nn], acc[mm][nn]);
                    wmma::mma_sync(acc[mm][nn], ah[mm], bl[nn], acc[mm][nn]);
                    wmma::mma_sync(acc[mm][nn], al[mm], bh[nn], acc[mm][nn]);
                }
        }
#pragma unroll
        for (int mm = 0; mm < 2; mm++)
#pragma unroll
            for (int nn = 0; nn < 2; nn++) {
                int r = wm * 32 + mm * 16;
                int c = wn * 32 + nn * 16;
                wmma::store_matrix_sync(&out[r * 132 + c], acc[mm][nn], 132, wmma::mem_row_major);
            }
        __syncthreads();
        {
            int jb = ct * 128 + quar * 32;
            const float* row = &out[qr * 132 + quar * 32];
            const float* nn_ = &ssn[quar * 32];
#pragma unroll 4
            for (int c = 0; c < 32; c++) {
                float d = sqp + nn_[c] - 2.f * row[c];
                if (d < bd[KN - 1]) knn_insert(d, jb + c, bd, bi);
            }
        }
    }
    __syncthreads();
    if (tid >= 64) {
        int r = tid - 64;   // 0..191
#pragma unroll
        for (int k = 0; k < KN; k++) {
            out[r * KN + k] = bd[k];
            reinterpret_cast<int*>(out + 960)[r * KN + k] = bi[k];
        }
    }
    __syncthreads();
    if (tid < 64) {
        float D[4][KN]; int I[4][KN];
#pragma unroll
        for (int k = 0; k < KN; k++) { D[0][k] = bd[k]; I[0][k] = bi[k]; }
#pragma unroll
        for (int s = 1; s < 4; s++) {
            int r = (s - 1) * 64 + tid;
#pragma unroll
            for (int k = 0; k < KN; k++) {
                D[s][k] = out[r * KN + k];
                I[s][k] = reinterpret_cast<int*>(out + 960)[r * KN + k];
            }
        }
        int ptr[4] = {0, 0, 0, 0};
        int o = (q0 + tid) * KN;
#pragma unroll
        for (int k = 0; k < KN; k++) {
            int best = -1;
            float bdv = 1e38f; int biv = 0x7fffffff;
#pragma unroll
            for (int s = 0; s < 4; s++) {
                if (ptr[s] < KN) {
                    float dv = D[s][ptr[s]]; int iv = I[s][ptr[s]];
                    if (dv < bdv || (dv == bdv && iv < biv)) {
                        bdv = dv; biv = iv; best = s;
                    }
                }
            }
            idx[o + k] = biv;
            ptr[best]++;
        }
    }
}

__global__ void wsplit2_k(const float* __restrict__ w) {
    int i = blockIdx.x * 256 + threadIdx.x;
    if (i >= 128 * 128) return;
    int r = i >> 7, c = i & 127;
    float v = w[i];
    __nv_bfloat16 h = __float2bfloat16(v);
    g_W2hi[c * 128 + r] = h;
    g_W2lo[c * 128 + r] = __float2bfloat16(v - __bfloat162float(h));
}

// WMMA EdgeConv2: vectorized gather(128) + GEMM 128x128, ReLU, stats
constexpr int EST = 40;
__global__ void __launch_bounds__(256) mma_ec2_k(const float* __restrict__ X,
                                                 const int* __restrict__ idx,
                                                 const float* __restrict__ bias,
                                                 float* __restrict__ Z) {
    extern __shared__ char dynbuf[];
    __nv_bfloat16* Ah = reinterpret_cast<__nv_bfloat16*>(dynbuf);
    __nv_bfloat16* Al = Ah + 128 * EST;
    __nv_bfloat16* Wh = Al + 128 * EST;
    __nv_bfloat16* Wl = Wh + 128 * EST;
    float* out = reinterpret_cast<float*>(dynbuf);
    int tid = threadIdx.x, wrp = tid >> 5;
    int e0 = blockIdx.x * 128;
    int wm = wrp >> 1, wn = wrp & 1;
    wmma::fragment<wmma::accumulator, 16, 16, 16, float> acc[2][4];
#pragma unroll
    for (int mm = 0; mm < 2; mm++)
#pragma unroll
        for (int nn = 0; nn < 4; nn++)
            wmma::fill_fragment(acc[mm][nn], 0.f);

    for (int kc = 0; kc < 4; kc++) {
        __syncthreads();
        for (int i = tid; i < 1024; i += 256) {
            int r = i >> 3, c4 = (i & 7) * 4;
            int col = kc * 32 + c4;
            int e = e0 + r;
            int pt = e / KN, bb = pt >> 11, j = idx[e];
            const float* xi = X + (size_t)pt * 192;
            const float* xj = X + ((size_t)(bb << 11) + j) * 192;
            float4 v;
            if (col < 64) {
                v = *reinterpret_cast<const float4*>(&xi[col]);
            } else {
                float4 a = *reinterpret_cast<const float4*>(&xj[col - 64]);
                float4 bq = *reinterpret_cast<const float4*>(&xi[col - 64]);
                v = make_float4(a.x - bq.x, a.y - bq.y, a.z - bq.z, a.w - bq.w);
            }
            __nv_bfloat16 h0 = __float2bfloat16(v.x), h1 = __float2bfloat16(v.y);
            __nv_bfloat16 h2 = __float2bfloat16(v.z), h3 = __float2bfloat16(v.w);
            Ah[r * EST + c4 + 0] = h0;
            Ah[r * EST + c4 + 1] = h1;
            Ah[r * EST + c4 + 2] = h2;
            Ah[r * EST + c4 + 3] = h3;
            Al[r * EST + c4 + 0] = __float2bfloat16(v.x - __bfloat162float(h0));
            Al[r * EST + c4 + 1] = __float2bfloat16(v.y - __bfloat162float(h1));
            Al[r * EST + c4 + 2] = __float2bfloat16(v.z - __bfloat162float(h2));
            Al[r * EST + c4 + 3] = __float2bfloat16(v.w - __bfloat162float(h3));
        }
        if (tid < 256) {
            for (int i = tid; i < 512; i += 256) {
                int r = i >> 2, cq = (i & 3) * 8;
                size_t gg = (size_t)r * 128 + kc * 32 + cq;
                *reinterpret_cast<uint4*>(&Wh[r * EST + cq]) =
                    *reinterpret_cast<const uint4*>(&g_W2hi[gg]);
                *reinterpret_cast<uint4*>(&Wl[r * EST + cq]) =
                    *reinterpret_cast<const uint4*>(&g_W2lo[gg]);
            }
        }
        __syncthreads();
#pragma unroll
        for (int kk = 0; kk < 32; kk += 16) {
            wmma::fragment<wmma::matrix_a, 16, 16, 16, __nv_bfloat16, wmma::row_major> ah[2], al[2];
            wmma::fragment<wmma::matrix_b, 16, 16, 16, __nv_bfloat16, wmma::col_major> bh[4], bl[4];
#pragma unroll
            for (int mm = 0; mm < 2; mm++) {
                int rb = wm * 32 + mm * 16;
                wmma::load_matrix_sync(ah[mm], &Ah[rb * EST + kk], EST);
                wmma::load_matrix_sync(al[mm], &Al[rb * EST + kk], EST);
            }
#pragma unroll
            for (int nn = 0; nn < 4; nn++) {
                int nb = wn * 64 + nn * 16;
                wmma::load_matrix_sync(bh[nn], &Wh[nb * EST + kk], EST);
                wmma::load_matrix_sync(bl[nn], &Wl[nb * EST + kk], EST);
            }
#pragma unroll
            for (int mm = 0; mm < 2; mm++)
#pragma unroll
                for (int nn = 0; nn < 4; nn++) {
                    wmma::mma_sync(acc[mm][nn], ah[mm], bh[nn], acc[mm][nn]);
                    wmma::mma_sync(acc[mm][nn], ah[mm], bl[nn], acc[mm][nn]);
                    wmma::mma_sync(acc[mm][nn], al[mm], bh[nn], acc[mm][nn]);
                }
        }
    }
    __syncthreads();
#pragma unroll
    for (int mm = 0; mm < 2; mm++)
#pragma unroll
        for (int nn = 0; nn < 4; nn++) {
            int r = wm * 32 + mm * 16;
            int c = wn * 64 + nn * 16;
            wmma::store_matrix_sync(&out[r * 132 + c], acc[mm][nn], 132, wmma::mem_row_major);
        }
    __syncthreads();
    for (int i = tid; i < 4096; i += 256) {
        int r = i >> 5, c4 = (i & 31) * 4;
        float4 v = *reinterpret_cast<float4*>(&out[r * 132 + c4]);
        v.x = fmaxf(v.x + bias[c4 + 0], 0.f);
        v.y = fmaxf(v.y + bias[c4 + 1], 0.f);
        v.z = fmaxf(v.z + bias[c4 + 2], 0.f);
        v.w = fmaxf(v.w + bias[c4 + 3], 0.f);
        *reinterpret_cast<float4*>(&out[r * 132 + c4]) = v;
        *reinterpret_cast<float4*>(&Z[(size_t)(e0 + r) * 128 + c4]) = v;
    }
    __syncthreads();
    if (tid < 128) {
        float s = 0.f, qq = 0.f;
        for (int r = 0; r < 128; r++) {
            float v = out[r * 132 + tid];
            s += v; qq += v * v;
        }
        g_part[((size_t)blockIdx.x * 2 + 0) * 128 + tid] = s;
        g_part[((size_t)blockIdx.x * 2 + 1) * 128 + tid] = qq;
    }
}

__global__ void initP1_k() {
    int g = blockIdx.x * 256 + threadIdx.x;
    if (g < 16 * 1024) g_P1raw[g] = 0;
}

__global__ void wsplit_k(const float* __restrict__ w) {
    int i = blockIdx.x * 256 + threadIdx.x;
    int r = i >> 10, c = i & 1023;
    float v = w[i];
    __nv_bfloat16 h = __float2bfloat16(v);
    g_Whi[c * 192 + r] = h;
    g_Wlo[c * 192 + r] = __float2bfloat16(v - __bfloat162float(h));
}

constexpr int LSTR = 40;
__global__ void __launch_bounds__(256) mma_l1_k(const float* __restrict__ bias) {
    __shared__ __align__(16) char smbuf[128 * 68 * 4];
    __nv_bfloat16* Ah = reinterpret_cast<__nv_bfloat16*>(smbuf);
    __nv_bfloat16* Al = Ah + 128 * LSTR;
    __nv_bfloat16* Wh = Al + 128 * LSTR;
    __nv_bfloat16* Wl = Wh + 64 * LSTR;
    float* out = reinterpret_cast<float*>(smbuf);
    int tid = threadIdx.x, wrp = tid >> 5;
    int mt = blockIdx.x >> 4, nt = blockIdx.x & 15;
    int row0 = mt << 7, col0 = nt << 6;
    int wm = wrp >> 1, wn = wrp & 1;
    wmma::fragment<wmma::accumulator, 16, 16, 16, float> acc[2][2];
#pragma unroll
    for (int mm = 0; mm < 2; mm++)
#pragma unroll
        for (int nn = 0; nn < 2; nn++)
            wmma::fill_fragment(acc[mm][nn], 0.f);

    for (int kc = 0; kc < 6; kc++) {
        __syncthreads();
        for (int i = tid; i < 512; i += 256) {
            int r = i >> 2, cq = (i & 3) * 8;
            size_t g = (size_t)(row0 + r) * 192 + kc * 32 + cq;
            *reinterpret_cast<uint4*>(&Ah[r * LSTR + cq]) =
                *reinterpret_cast<const uint4*>(&g_Xhi[g]);
            *reinterpret_cast<uint4*>(&Al[r * LSTR + cq]) =
                *reinterpret_cast<const uint4*>(&g_Xlo[g]);
        }
        if (tid < 256) {
            int r = tid >> 2, cq = (tid & 3) * 8;
            size_t g = (size_t)(col0 + r) * 192 + kc * 32 + cq;
            *reinterpret_cast<uint4*>(&Wh[r * LSTR + cq]) =
                *reinterpret_cast<const uint4*>(&g_Whi[g]);
            *reinterpret_cast<uint4*>(&Wl[r * LSTR + cq]) =
                *reinterpret_cast<const uint4*>(&g_Wlo[g]);
        }
        __syncthreads();
#pragma unroll
        for (int kk = 0; kk < 32; kk += 16) {
            wmma::fragment<wmma::matrix_a, 16, 16, 16, __nv_bfloat16, wmma::row_major> ah[2], al[2];
            wmma::fragment<wmma::matrix_b, 16, 16, 16, __nv_bfloat16, wmma::col_major> bh[2], bl[2];
#pragma unroll
            for (int mm = 0; mm < 2; mm++) {
                int rb = wm * 32 + mm * 16;
                wmma::load_matrix_sync(ah[mm], &Ah[rb * LSTR + kk], LSTR);
                wmma::load_matrix_sync(al[mm], &Al[rb * LSTR + kk], LSTR);
            }
#pragma unroll
            for (int nn = 0; nn < 2; nn++) {
                int nb = wn * 32 + nn * 16;
                wmma::load_matrix_sync(bh[nn], &Wh[nb * LSTR + kk], LSTR);
                wmma::load_matrix_sync(bl[nn], &Wl[nb * LSTR + kk], LSTR);
            }
#pragma unroll
            for (int mm = 0; mm < 2; mm++)
#pragma unroll
                for (int nn = 0; nn < 2; nn++) {
                    wmma::mma_sync(acc[mm][nn], ah[mm], bh[nn], acc[mm][nn]);
                    wmma::mma_sync(acc[mm][nn], ah[mm], bl[nn], acc[mm][nn]);
                    wmma::mma_sync(acc[mm][nn], al[mm], bh[nn], acc[mm][nn]);
                }
        }
    }
    __syncthreads();
#pragma unroll
    for (int mm = 0; mm < 2; mm++)
#pragma unroll
        for (int nn = 0; nn < 2; nn++) {
            int r = wm * 32 + mm * 16;
            int c = wn * 32 + nn * 16;
            wmma::store_matrix_sync(&out[r * 68 + c], acc[mm][nn], 68, wmma::mem_row_major);
        }
    __syncthreads();
    for (int i = tid; i < 8192; i += 256) {
        int r = i >> 6, c = i & 63;
        out[r * 68 + c] = fmaxf(out[r * 68 + c] + bias[col0 + c], 0.f);
    }
    __syncthreads();
    if (tid < 64) {
        float s = 0.f, q = 0.f, m = 0.f;
        for (int r = 0; r < 128; r++) {
            float v = out[r * 68 + tid];
            s += v; q += v * v; m = fmaxf(m, v);
        }
        g_partL[((size_t)mt * 2 + 0) * 1024 + col0 + tid] = s;
        g_partL[((size_t)mt * 2 + 1) * 1024 + col0 + tid] = q;
        atomicMax(&g_P1raw[(row0 >> 11) * 1024 + col0 + tid], __float_as_int(m));
    }
}

__global__ void head1_k(const float* __restrict__ w, const float* __restrict__ bias) {
    __shared__ float sp[1024];
    int g = blockIdx.x * 256 + threadIdx.x;
    int b = g >> 9, c = g & 511;
    for (int i = threadIdx.x; i < 1024; i += 256)
        sp[i] = fmaf(g_s5[i], __int_as_float(g_P1raw[(b << 10) + i]), g_h5[i]);
    __syncthreads();
    float a = bias[c];
#pragma unroll 8
    for (int r = 0; r < 1024; r++) a = fmaf(sp[r], w[(size_t)r * 512 + c], a);
    g_Zm1[g] = fmaxf(a, 0.f);
}

__global__ void stats16_k(const float* __restrict__ Z, int C,
                          const float* __restrict__ g, const float* __restrict__ be,
                          float* __restrict__ scale, float* __restrict__ shift) {
    int c = blockIdx.x * blockDim.x + threadIdx.x;
    if (c >= C) return;
    float s = 0.f, q = 0.f;
    for (int b = 0; b < 16; b++) { float v = Z[b * C + c]; s += v; q += v * v; }
    float mean = s * 0.0625f;
    float var = q * 0.0625f - mean * mean;
    float sc = g[c] * rsqrtf(var + EPSB);
    scale[c] = sc;
    shift[c] = be[c] - mean * sc;
}

__global__ void head2_k(const float* __restrict__ w) {
    int g = blockIdx.x * 256 + threadIdx.x;
    int b = g >> 8, c = g & 255;
    float a = g_ebm2[c];
    const float* z = g_Zm1 + b * 512;
#pragma unroll 8
    for (int r = 0; r < 512; r++) a = fmaf(z[r] * g_s6[r], w[(size_t)r * 256 + c], a);
    g_Zm2[g] = fmaxf(a, 0.f);
}

__global__ void head3_k(const float* __restrict__ w, float* __restrict__ out) {
    int t = threadIdx.x;
    if (t >= 32) return;
    int b = t >> 1, n = t & 1;
    float a = g_ebm3[n];
    const float* z = g_Zm2 + b * 256;
#pragma unroll 8
    for (int r = 0; r < 256; r++) a = fmaf(z[r] * g_s7[r], w[r * 2 + n], a);
    out[b * 2 + n] = a;
}

static void* symaddr(const void* s) {
    void* p = nullptr;
    cudaGetSymbolAddress(&p, s);
    return p;
}

extern "C" void kernel_launch(void* const* d_in, const int* in_sizes, int n_in,
                              void* d_out, int out_size) {
    const float* pos = (const float*)d_in[0];
    const float* c1w0 = (const float*)d_in[1];
    const float* c1b0 = (const float*)d_in[2];
    const float* c1g0 = (const float*)d_in[3];
    const float* c1e0 = (const float*)d_in[4];
    const float* c1w1 = (const float*)d_in[5];
    const float* c1b1 = (const float*)d_in[6];
    const float* c1g1 = (const float*)d_in[7];
    const float* c1e1 = (const float*)d_in[8];
    const float* c1w2 = (const float*)d_in[9];
    const float* c1b2 = (const float*)d_in[10];
    const float* c1g2 = (const float*)d_in[11];
    const float* c1e2 = (const float*)d_in[12];
    const float* c2w = (const float*)d_in[13];
    const float* c2b = (const float*)d_in[14];
    const float* c2g = (const float*)d_in[15];
    const float* c2e = (const float*)d_in[16];
    const float* l1w = (const float*)d_in[17];
    const float* l1b = (const float*)d_in[18];
    const float* l1g = (const float*)d_in[19];
    const float* l1e = (const float*)d_in[20];
    const float* m1w = (const float*)d_in[21];
    const float* m1b = (const float*)d_in[22];
    const float* m1g = (const float*)d_in[23];
    const float* m1e = (const float*)d_in[24];
    const float* m2w = (const float*)d_in[25];
    const float* m2b = (const float*)d_in[26];
    const float* m2g = (const float*)d_in[27];
    const float* m2e = (const float*)d_in[28];
    const float* m3w = (const float*)d_in[29];
    const float* m3b = (const float*)d_in[30];

    float* Z1 = (float*)symaddr(g_Z1);
    float* Z2 = (float*)symaddr(g_Z2);
    float* Z4 = (float*)symaddr(g_Z4);
    float* X = (float*)symaddr(g_X12);
    int* I1 = (int*)symaddr(g_idx1);
    int* I2 = (int*)symaddr(g_idx2);
    float* part = (float*)symaddr(g_part);
    float* partL = (float*)symaddr(g_partL);
    float* s1 = (float*)symaddr(g_s1);
    float* h1 = (float*)symaddr(g_h1);
    float* s2 = (float*)symaddr(g_s2);
    float* h2 = (float*)symaddr(g_h2);
    float* s3 = (float*)symaddr(g_s3);
    float* h3 = (float*)symaddr(g_h3);
    float* s4 = (float*)symaddr(g_s4);
    float* h4 = (float*)symaddr(g_h4);
    float* s5 = (float*)symaddr(g_s5);
    float* h5 = (float*)symaddr(g_h5);
    float* s6 = (float*)symaddr(g_s6);
    float* h6 = (float*)symaddr(g_h6);
    float* s7 = (float*)symaddr(g_s7);
    float* h7 = (float*)symaddr(g_h7);
    float* eb2 = (float*)symaddr(g_eb2);
    float* eb3 = (float*)symaddr(g_eb3);
    float* ebm2 = (float*)symaddr(g_ebm2);
    float* ebm3 = (float*)symaddr(g_ebm3);
    float* Zm1 = (float*)symaddr(g_Zm1);
    float* Zm2 = (float*)symaddr(g_Zm2);

    cudaFuncSetAttribute(mma_ec2_k, cudaFuncAttributeMaxDynamicSharedMemorySize, 70656);
    cudaFuncSetAttribute(mma_mid_k, cudaFuncAttributeMaxDynamicSharedMemorySize, 35840);
    cudaFuncSetAttribute(knn64tc_k, cudaFuncAttributeMaxDynamicSharedMemorySize, 89088);

    wsplit_k<<<768, 256>>>(l1w);
    wsplit2_k<<<64, 256>>>(c2w);
    knn3_k<<<128, 256>>>(pos, I1);
    ec1_l0_k<<<NEDG * 4 / 256, 256>>>(pos, I1, c1w0, c1b0, Z1);
    finalize_k<<<8, 256>>>(64, (float)NEDG, 2560, c1g0, c1e0, part, s1, h1);
    foldbias_k<<<1, 64>>>(64, 64, c1w1, c1b1, h1, eb2);
    mma_mid_k<<<NEDG / 128, 256, 35840>>>(Z1, c1w1, s1, eb2, Z2);
    finalize_k<<<8, 256>>>(64, (float)NEDG, 1280, c1g1, c1e1, part, s2, h2);
    foldbias_k<<<1, 64>>>(64, 64, c1w2, c1b2, h2, eb3);
    mma_mid_k<<<NEDG / 128, 256, 35840>>>(Z2, c1w2, s2, eb3, Z1);
    finalize_k<<<8, 256>>>(64, (float)NEDG, 1280, c1g2, c1e2, part, s3, h3);
    maxE_k<<<NPTS * 16 / 256, 256>>>(Z1, 64, s3, h3, X, 0, 1);

    knn64tc_k<<<512, 256, 89088>>>(I2);
    mma_ec2_k<<<NEDG / 128, 256, 70656>>>(X, I2, c2b, Z4);
    finalize_k<<<16, 256>>>(128, (float)NEDG, 1280, c2g, c2e, part, s4, h4);
    maxE_k<<<NPTS * 32 / 256, 256>>>(Z4, 128, s4, h4, X, 64, 0);

    initP1_k<<<64, 256>>>();
    mma_l1_k<<<4096, 256>>>(l1b);
    finalize_k<<<128, 256>>>(1024, (float)NPTS, 256, l1g, l1e, partL, s5, h5);

    head1_k<<<32, 256>>>(m1w, m1b);
    stats16_k<<<2, 256>>>(Zm1, 512, m1g, m1e, s6, h6);
    foldbias_k<<<1, 256>>>(512, 256, m2w, m2b, h6, ebm2);
    head2_k<<<16, 256>>>(m2w);
    stats16_k<<<1, 256>>>(Zm2, 256, m2g, m2e, s7, h7);
    foldbias_k<<<1, 32>>>(256, 2, m3w, m3b, h7, ebm3);
    head3_k<<<1, 32>>>(m3w, (float*)d_out);
}